// round 2
// baseline (speedup 1.0000x reference)
#include <cuda_runtime.h>
#include <math.h>

#define BATCH 4
#define NPTS  40960
#define KNN   16
#define P_TOTAL (BATCH * NPTS)   // 163840

typedef unsigned long long u64;

// packed fp32x2 FMA (Blackwell): d = a*b + c per 32-bit half
__device__ __forceinline__ u64 ffma2(u64 a, u64 b, u64 c) {
    u64 d;
    asm("fma.rn.f32x2 %0, %1, %2, %3;" : "=l"(d) : "l"(a), "l"(b), "l"(c));
    return d;
}
__device__ __forceinline__ float hadd2(u64 v) {
    return __uint_as_float((unsigned)v) + __uint_as_float((unsigned)(v >> 32));
}

// Scratch (device globals: no allocation allowed in kernel_launch)
__device__ float g_f_pc [P_TOTAL * 32];                 // 21 MB
__device__ float g_f_agg[P_TOTAL * 32];                 // 21 MB
__device__ float g_f_xyz2[(size_t)P_TOTAL * KNN * 32];  // 335 MB

// ---------------------------------------------------------------------------
// Kernel 1: f_pc = ReLU((feature @ w_mlp1) * s + b)
// ---------------------------------------------------------------------------
__global__ __launch_bounds__(256) void kern_mlp1(
    const float* __restrict__ feature,
    const float* __restrict__ w, const float* __restrict__ s, const float* __restrict__ b)
{
    __shared__ float ws[1024];   // packed [16 jp][32 c] float2
    __shared__ float sv[32], bv[32];
    __shared__ float xs[8][32];

    for (int i = threadIdx.x; i < 512; i += blockDim.x) {
        int jp = i >> 5, c = i & 31;
        ((float2*)ws)[i] = make_float2(w[(2 * jp) * 32 + c], w[(2 * jp + 1) * 32 + c]);
    }
    if (threadIdx.x < 32) { sv[threadIdx.x] = s[threadIdx.x]; bv[threadIdx.x] = b[threadIdx.x]; }
    __syncthreads();

    const int lane = threadIdx.x & 31;
    const int warp = threadIdx.x >> 5;
    const int nwarps = (gridDim.x * blockDim.x) >> 5;
    int gw = (blockIdx.x * blockDim.x + threadIdx.x) >> 5;
    const u64* wp = (const u64*)ws;

    for (int p = gw; p < P_TOTAL; p += nwarps) {
        xs[warp][lane] = feature[(size_t)p * 32 + lane];
        __syncwarp();
        u64 acc = 0ull;
        #pragma unroll
        for (int i = 0; i < 8; i++) {
            ulonglong2 f = *(const ulonglong2*)(&xs[warp][i * 4]);
            acc = ffma2(f.x, wp[(2 * i) * 32 + lane], acc);
            acc = ffma2(f.y, wp[(2 * i + 1) * 32 + lane], acc);
        }
        g_f_pc[(size_t)p * 32 + lane] = fmaxf(hadd2(acc) * sv[lane] + bv[lane], 0.f);
        __syncwarp();
    }
}

// ---------------------------------------------------------------------------
// Shared helper: one attention pass over fs tile [16][64] for channel `ch`.
// logits = fs @ wfc[:,ch] (wfc packed as [32 jp][64 ch] float2), softmax over
// k, pool fs[:,ch], returns pooled value.
// ---------------------------------------------------------------------------
__device__ __forceinline__ float att_pass(const float* __restrict__ fs_s,
                                          const u64* __restrict__ wfcp, int ch)
{
    u64 acc2[KNN];
    #pragma unroll
    for (int k = 0; k < KNN; k++) acc2[k] = 0ull;

    for (int it = 0; it < 16; it++) {           // 2 j-pairs per iter
        u64 w0 = wfcp[(2 * it) * 64 + ch];
        u64 w1 = wfcp[(2 * it + 1) * 64 + ch];
        #pragma unroll
        for (int k = 0; k < KNN; k++) {
            ulonglong2 f = *(const ulonglong2*)(fs_s + k * 64 + it * 4);
            acc2[k] = ffma2(f.x, w0, acc2[k]);
            acc2[k] = ffma2(f.y, w1, acc2[k]);
        }
    }
    float lg[KNN];
    float m = -1e30f;
    #pragma unroll
    for (int k = 0; k < KNN; k++) { lg[k] = hadd2(acc2[k]); m = fmaxf(m, lg[k]); }
    float ssum = 0.f;
    #pragma unroll
    for (int k = 0; k < KNN; k++) { float e = __expf(lg[k] - m); lg[k] = e; ssum += e; }
    float a = 0.f;
    #pragma unroll
    for (int k = 0; k < KNN; k++) a += fs_s[k * 64 + ch] * lg[k];
    return __fdividef(a, ssum);
}

// ---------------------------------------------------------------------------
// Kernel 2: rel_pos + lfa1 + gather(f_pc) + att1 -> g_f_agg ; lfa2 -> g_f_xyz2
// ---------------------------------------------------------------------------
#define K2_WARP_FLOATS 1248   // fs 1024 + rp 160 + agg 64
#define K2_BASE_FLOATS 7680
#define K2_WARPS 16
#define K2_SMEM_BYTES ((K2_BASE_FLOATS + K2_WARPS * K2_WARP_FLOATS) * 4)

__global__ __launch_bounds__(512) void kern_att1(
    const float* __restrict__ xyz, const int* __restrict__ neigh,
    const float* __restrict__ wlfa1, const float* __restrict__ slfa1, const float* __restrict__ blfa1,
    const float* __restrict__ wfc1,
    const float* __restrict__ wam1, const float* __restrict__ sam1, const float* __restrict__ bam1,
    const float* __restrict__ wlfa2, const float* __restrict__ slfa2, const float* __restrict__ blfa2)
{
    extern __shared__ float sm[];
    float* s_wfc = sm;            // 4096  wfc1 packed [32 jp][64]
    float* s_wam = sm + 4096;     // 2048  wam1 packed [32 jp][32]
    float* s_wl2 = sm + 6144;     // 1024  wlfa2 packed [16 jp][32]
    float* s_wl1 = sm + 7168;     // 320   wlfa1 packed [5 jp][32]
    float* s_vec = sm + 7488;     // 192
    float* s_wrp = sm + K2_BASE_FLOATS;

    for (int i = threadIdx.x; i < 2048; i += blockDim.x) {
        int jp = i >> 6, c = i & 63;
        ((float2*)s_wfc)[i] = make_float2(wfc1[(2 * jp) * 64 + c], wfc1[(2 * jp + 1) * 64 + c]);
    }
    for (int i = threadIdx.x; i < 1024; i += blockDim.x) {
        int jp = i >> 5, c = i & 31;
        ((float2*)s_wam)[i] = make_float2(wam1[(2 * jp) * 32 + c], wam1[(2 * jp + 1) * 32 + c]);
    }
    for (int i = threadIdx.x; i < 512; i += blockDim.x) {
        int jp = i >> 5, c = i & 31;
        ((float2*)s_wl2)[i] = make_float2(wlfa2[(2 * jp) * 32 + c], wlfa2[(2 * jp + 1) * 32 + c]);
    }
    for (int i = threadIdx.x; i < 160; i += blockDim.x) {
        int jp = i >> 5, c = i & 31;
        ((float2*)s_wl1)[i] = make_float2(wlfa1[(2 * jp) * 32 + c], wlfa1[(2 * jp + 1) * 32 + c]);
    }
    if (threadIdx.x < 32) {
        int l = threadIdx.x;
        s_vec[l]       = slfa1[l];  s_vec[32 + l]  = blfa1[l];
        s_vec[64 + l]  = sam1[l];   s_vec[96 + l]  = bam1[l];
        s_vec[128 + l] = slfa2[l];  s_vec[160 + l] = blfa2[l];
    }
    __syncthreads();

    const int lane = threadIdx.x & 31;
    const int warp = threadIdx.x >> 5;
    float* fs_s  = s_wrp + warp * K2_WARP_FLOATS;
    float* rp_s  = fs_s + 1024;
    float* agg_s = fs_s + 1184;

    const u64* wfcp = (const u64*)s_wfc;
    const u64* wamp = (const u64*)s_wam;
    const u64* wl2p = (const u64*)s_wl2;
    const u64* wl1p = (const u64*)s_wl1;

    const int nwarps = (gridDim.x * blockDim.x) >> 5;
    int gw = (blockIdx.x * blockDim.x + threadIdx.x) >> 5;

    for (int p = gw; p < P_TOTAL; p += nwarps) {
        const int b = p / NPTS;
        const size_t bbase = (size_t)b * NPTS;

        int myidx = 0;
        if (lane < KNN) myidx = neigh[(size_t)p * KNN + lane];

        const float cx = xyz[(size_t)p * 3 + 0];
        const float cy = xyz[(size_t)p * 3 + 1];
        const float cz = xyz[(size_t)p * 3 + 2];

        if (lane < KNN) {
            size_t nb = bbase + (size_t)myidx;
            float nx = xyz[nb * 3 + 0], ny = xyz[nb * 3 + 1], nz = xyz[nb * 3 + 2];
            float rx = cx - nx, ry = cy - ny, rz = cz - nz;
            float d = sqrtf(rx * rx + ry * ry + rz * rz);
            float* rp = rp_s + lane * 10;
            rp[0] = d;  rp[1] = rx; rp[2] = ry; rp[3] = rz;
            rp[4] = cx; rp[5] = cy; rp[6] = cz;
            rp[7] = nx; rp[8] = ny; rp[9] = nz;
        }
        __syncwarp();

        // f_xyz = ReLU(relpos @ wlfa1) -> fs[:,32+lane]   (j packed over 5 pairs)
        {
            u64 w0 = wl1p[0 * 32 + lane], w1 = wl1p[1 * 32 + lane],
                w2 = wl1p[2 * 32 + lane], w3 = wl1p[3 * 32 + lane],
                w4 = wl1p[4 * 32 + lane];
            const float sl = s_vec[lane], bl = s_vec[32 + lane];
            #pragma unroll
            for (int k = 0; k < KNN; k++) {
                const float* rp = rp_s + k * 10;
                u64 acc = 0ull;
                acc = ffma2(*(const u64*)(rp + 0), w0, acc);
                acc = ffma2(*(const u64*)(rp + 2), w1, acc);
                acc = ffma2(*(const u64*)(rp + 4), w2, acc);
                acc = ffma2(*(const u64*)(rp + 6), w3, acc);
                acc = ffma2(*(const u64*)(rp + 8), w4, acc);
                fs_s[k * 64 + 32 + lane] = fmaxf(hadd2(acc) * sl + bl, 0.f);
            }
        }
        // f_nb = gather(f_pc) -> fs[:,lane]
        #pragma unroll
        for (int k = 0; k < KNN; k++) {
            int nb = __shfl_sync(0xffffffffu, myidx, k);
            fs_s[k * 64 + lane] = g_f_pc[(bbase + (size_t)nb) * 32 + lane];
        }
        __syncwarp();

        // attention: two passes (channel lane, channel lane+32)
        agg_s[lane]      = att_pass(fs_s, wfcp, lane);
        agg_s[32 + lane] = att_pass(fs_s, wfcp, 32 + lane);
        __syncwarp();

        // f_agg = ReLU((agg @ wam1)*s + b), channel = lane
        {
            u64 acc = 0ull;
            #pragma unroll
            for (int i = 0; i < 16; i++) {
                ulonglong2 a = *(const ulonglong2*)(agg_s + i * 4);
                acc = ffma2(a.x, wamp[(2 * i) * 32 + lane], acc);
                acc = ffma2(a.y, wamp[(2 * i + 1) * 32 + lane], acc);
            }
            g_f_agg[(size_t)p * 32 + lane] =
                fmaxf(hadd2(acc) * s_vec[64 + lane] + s_vec[96 + lane], 0.f);
        }

        // f_xyz2 = ReLU((f_xyz @ wlfa2)*s + b) -> scratch
        {
            u64 wc[16];
            #pragma unroll
            for (int i = 0; i < 16; i++) wc[i] = wl2p[i * 32 + lane];
            const float sl = s_vec[128 + lane], bl = s_vec[160 + lane];
            #pragma unroll
            for (int k = 0; k < KNN; k++) {
                u64 acc = 0ull;
                #pragma unroll
                for (int i = 0; i < 8; i++) {
                    ulonglong2 f = *(const ulonglong2*)(fs_s + k * 64 + 32 + i * 4);
                    acc = ffma2(f.x, wc[2 * i], acc);
                    acc = ffma2(f.y, wc[2 * i + 1], acc);
                }
                g_f_xyz2[((size_t)p * KNN + k) * 32 + lane] =
                    fmaxf(hadd2(acc) * sl + bl, 0.f);
            }
        }
        __syncwarp();
    }
}

// ---------------------------------------------------------------------------
// Kernel 3: gather(f_agg) + f_xyz2 + att2 + att2_mlp + mlp2 + shortcut + leaky
// ---------------------------------------------------------------------------
#define K3_WARP_FLOATS 1184   // fs 1024 + agg 64 + pc2 64 + feat 32
#define K3_BASE_FLOATS 21120
#define K3_WARPS 16
#define K3_SMEM_BYTES ((K3_BASE_FLOATS + K3_WARPS * K3_WARP_FLOATS) * 4)

__global__ __launch_bounds__(512) void kern_att2(
    const float* __restrict__ feature, const int* __restrict__ neigh,
    const float* __restrict__ wfc2,
    const float* __restrict__ wam2, const float* __restrict__ sam2, const float* __restrict__ bam2,
    const float* __restrict__ wmlp2, const float* __restrict__ smlp2, const float* __restrict__ bmlp2,
    const float* __restrict__ wsc, const float* __restrict__ ssc, const float* __restrict__ bsc,
    float* __restrict__ out)
{
    extern __shared__ float sm[];
    float* s_wfc = sm;             // 4096  packed [32 jp][64]
    float* s_wam = sm + 4096;      // 4096  packed [32 jp][64]
    float* s_wm2 = sm + 8192;      // 8192  packed [32 jp][128]
    float* s_wsc = sm + 16384;     // 4096  packed [16 jp][128]
    float* s_vec = sm + 20480;     // 640
    float* s_wrp = sm + K3_BASE_FLOATS;

    for (int i = threadIdx.x; i < 2048; i += blockDim.x) {
        int jp = i >> 6, c = i & 63;
        ((float2*)s_wfc)[i] = make_float2(wfc2[(2 * jp) * 64 + c], wfc2[(2 * jp + 1) * 64 + c]);
        ((float2*)s_wam)[i] = make_float2(wam2[(2 * jp) * 64 + c], wam2[(2 * jp + 1) * 64 + c]);
    }
    for (int i = threadIdx.x; i < 4096; i += blockDim.x) {
        int jp = i >> 7, c = i & 127;
        ((float2*)s_wm2)[i] = make_float2(wmlp2[(2 * jp) * 128 + c], wmlp2[(2 * jp + 1) * 128 + c]);
    }
    for (int i = threadIdx.x; i < 2048; i += blockDim.x) {
        int jp = i >> 7, c = i & 127;
        ((float2*)s_wsc)[i] = make_float2(wsc[(2 * jp) * 128 + c], wsc[(2 * jp + 1) * 128 + c]);
    }
    if (threadIdx.x < 64) {
        int l = threadIdx.x;
        s_vec[l] = sam2[l]; s_vec[64 + l] = bam2[l];
    }
    if (threadIdx.x < 128) {
        int l = threadIdx.x;
        s_vec[128 + l] = smlp2[l]; s_vec[256 + l] = bmlp2[l];
        s_vec[384 + l] = ssc[l];   s_vec[512 + l] = bsc[l];
    }
    __syncthreads();

    const int lane = threadIdx.x & 31;
    const int warp = threadIdx.x >> 5;
    float* fs_s   = s_wrp + warp * K3_WARP_FLOATS;
    float* agg_s  = fs_s + 1024;
    float* pc2_s  = fs_s + 1088;
    float* feat_s = fs_s + 1152;

    const u64* wfcp = (const u64*)s_wfc;
    const u64* wamp = (const u64*)s_wam;
    const u64* wm2p = (const u64*)s_wm2;
    const u64* wscp = (const u64*)s_wsc;

    const int nwarps = (gridDim.x * blockDim.x) >> 5;
    int gw = (blockIdx.x * blockDim.x + threadIdx.x) >> 5;

    for (int p = gw; p < P_TOTAL; p += nwarps) {
        const int b = p / NPTS;
        const size_t bbase = (size_t)b * NPTS;

        int myidx = 0;
        if (lane < KNN) myidx = neigh[(size_t)p * KNN + lane];

        #pragma unroll
        for (int k = 0; k < KNN; k++) {
            int nb = __shfl_sync(0xffffffffu, myidx, k);
            fs_s[k * 64 + lane] = g_f_agg[(bbase + (size_t)nb) * 32 + lane];
        }
        #pragma unroll
        for (int k = 0; k < KNN; k++) {
            fs_s[k * 64 + 32 + lane] = g_f_xyz2[((size_t)p * KNN + k) * 32 + lane];
        }
        feat_s[lane] = feature[(size_t)p * 32 + lane];
        __syncwarp();

        agg_s[lane]      = att_pass(fs_s, wfcp, lane);
        agg_s[32 + lane] = att_pass(fs_s, wfcp, 32 + lane);
        __syncwarp();

        // f_pc2 = ReLU((agg @ wam2)*s + b), channels lane and lane+32
        {
            u64 aL = 0ull, aH = 0ull;
            #pragma unroll
            for (int i = 0; i < 16; i++) {
                ulonglong2 a = *(const ulonglong2*)(agg_s + i * 4);
                aL = ffma2(a.x, wamp[(2 * i) * 64 + lane], aL);
                aH = ffma2(a.x, wamp[(2 * i) * 64 + 32 + lane], aH);
                aL = ffma2(a.y, wamp[(2 * i + 1) * 64 + lane], aL);
                aH = ffma2(a.y, wamp[(2 * i + 1) * 64 + 32 + lane], aH);
            }
            pc2_s[lane]      = fmaxf(hadd2(aL) * s_vec[lane]      + s_vec[64 + lane], 0.f);
            pc2_s[32 + lane] = fmaxf(hadd2(aH) * s_vec[32 + lane] + s_vec[96 + lane], 0.f);
        }
        __syncwarp();

        // out = leaky( (f_pc2 @ wmlp2)*s+b + (feature @ wsc)*s+b )
        {
            u64 o2[4] = {0ull, 0ull, 0ull, 0ull};
            #pragma unroll
            for (int i = 0; i < 16; i++) {
                ulonglong2 a = *(const ulonglong2*)(pc2_s + i * 4);
                #pragma unroll
                for (int ci = 0; ci < 4; ci++) {
                    o2[ci] = ffma2(a.x, wm2p[(2 * i) * 128 + ci * 32 + lane], o2[ci]);
                    o2[ci] = ffma2(a.y, wm2p[(2 * i + 1) * 128 + ci * 32 + lane], o2[ci]);
                }
            }
            u64 s2[4] = {0ull, 0ull, 0ull, 0ull};
            #pragma unroll
            for (int i = 0; i < 8; i++) {
                ulonglong2 f = *(const ulonglong2*)(feat_s + i * 4);
                #pragma unroll
                for (int ci = 0; ci < 4; ci++) {
                    s2[ci] = ffma2(f.x, wscp[(2 * i) * 128 + ci * 32 + lane], s2[ci]);
                    s2[ci] = ffma2(f.y, wscp[(2 * i + 1) * 128 + ci * 32 + lane], s2[ci]);
                }
            }
            #pragma unroll
            for (int ci = 0; ci < 4; ci++) {
                int c = ci * 32 + lane;
                float v = hadd2(o2[ci]) * s_vec[128 + c] + s_vec[256 + c]
                        + hadd2(s2[ci]) * s_vec[384 + c] + s_vec[512 + c];
                out[(size_t)p * 128 + c] = (v < 0.f) ? 0.2f * v : v;
            }
        }
        __syncwarp();
    }
}

// ---------------------------------------------------------------------------
extern "C" void kernel_launch(void* const* d_in, const int* in_sizes, int n_in,
                              void* d_out, int out_size)
{
    const float* feature = (const float*)d_in[0];
    const float* xyz     = (const float*)d_in[1];
    const int*   neigh   = (const int*)  d_in[2];
    const float* w_mlp1  = (const float*)d_in[3];
    const float* s_mlp1  = (const float*)d_in[4];
    const float* b_mlp1  = (const float*)d_in[5];
    const float* w_lfa1  = (const float*)d_in[6];
    const float* s_lfa1  = (const float*)d_in[7];
    const float* b_lfa1  = (const float*)d_in[8];
    const float* w_fc1   = (const float*)d_in[9];
    const float* w_am1   = (const float*)d_in[10];
    const float* s_am1   = (const float*)d_in[11];
    const float* b_am1   = (const float*)d_in[12];
    const float* w_lfa2  = (const float*)d_in[13];
    const float* s_lfa2  = (const float*)d_in[14];
    const float* b_lfa2  = (const float*)d_in[15];
    const float* w_fc2   = (const float*)d_in[16];
    const float* w_am2   = (const float*)d_in[17];
    const float* s_am2   = (const float*)d_in[18];
    const float* b_am2   = (const float*)d_in[19];
    const float* w_mlp2  = (const float*)d_in[20];
    const float* s_mlp2  = (const float*)d_in[21];
    const float* b_mlp2  = (const float*)d_in[22];
    const float* w_sc    = (const float*)d_in[23];
    const float* s_sc    = (const float*)d_in[24];
    const float* b_sc    = (const float*)d_in[25];
    float* out = (float*)d_out;

    cudaFuncSetAttribute(kern_att1, cudaFuncAttributeMaxDynamicSharedMemorySize, K2_SMEM_BYTES);
    cudaFuncSetAttribute(kern_att2, cudaFuncAttributeMaxDynamicSharedMemorySize, K3_SMEM_BYTES);

    kern_mlp1<<<2048, 256>>>(feature, w_mlp1, s_mlp1, b_mlp1);

    kern_att1<<<1024, 512, K2_SMEM_BYTES>>>(
        xyz, neigh,
        w_lfa1, s_lfa1, b_lfa1,
        w_fc1,
        w_am1, s_am1, b_am1,
        w_lfa2, s_lfa2, b_lfa2);

    kern_att2<<<1024, 512, K3_SMEM_BYTES>>>(
        feature, neigh,
        w_fc2,
        w_am2, s_am2, b_am2,
        w_mlp2, s_mlp2, b_mlp2,
        w_sc, s_sc, b_sc,
        out);
}

// round 3
// speedup vs baseline: 1.5458x; 1.5458x over previous
#include <cuda_runtime.h>
#include <math.h>

#define BATCH 4
#define NPTS  40960
#define KNN   16
#define P_TOTAL (BATCH * NPTS)   // 163840

#define FS_PAD 68   // fs tile row stride (floats): conflict-free A-frag loads
#define LG_PAD 66   // logits tile row stride: conflict-free column reads
#define WF_PAD 72   // wfc row stride: conflict-free B-frag loads

// Scratch (device globals: no allocation allowed in kernel_launch)
__device__ float g_f_pc [P_TOTAL * 32];                 // 21 MB
__device__ float g_f_agg[P_TOTAL * 32];                 // 21 MB
__device__ float g_f_xyz2[(size_t)P_TOTAL * KNN * 32];  // 335 MB

__device__ __forceinline__ float to_tf32(float x) {
    float r;
    asm("cvt.rna.tf32.f32 %0, %1;" : "=f"(r) : "f"(x));
    return r;
}

__device__ __forceinline__ void mma_tf32(float* c,
                                         unsigned a0, unsigned a1, unsigned a2, unsigned a3,
                                         unsigned b0, unsigned b1) {
    asm("mma.sync.aligned.m16n8k8.row.col.f32.tf32.tf32.f32 "
        "{%0,%1,%2,%3}, {%4,%5,%6,%7}, {%8,%9}, {%0,%1,%2,%3};"
        : "+f"(c[0]), "+f"(c[1]), "+f"(c[2]), "+f"(c[3])
        : "r"(a0), "r"(a1), "r"(a2), "r"(a3), "r"(b0), "r"(b1));
}

// logits[16][64] = fs[16][64] @ wfc[64][64]  via 64x m16n8k8 tf32 mma.
// fs_s: pad FS_PAD, fp32. wfc: pad WF_PAD, pre-rounded tf32. lg_s: pad LG_PAD out.
__device__ __forceinline__ void logits_mma(const float* __restrict__ fs_s,
                                           float* __restrict__ lg_s,
                                           const float* __restrict__ wfc, int lane)
{
    const int gid = lane >> 2;    // 0..7
    const int tig = lane & 3;     // 0..3
    float acc[8][4];
    #pragma unroll
    for (int n = 0; n < 8; n++) {
        acc[n][0] = 0.f; acc[n][1] = 0.f; acc[n][2] = 0.f; acc[n][3] = 0.f;
    }
    #pragma unroll
    for (int q = 0; q < 8; q++) {
        const float* fr0 = fs_s + gid * FS_PAD + q * 8 + tig;
        const float* fr1 = fs_s + (gid + 8) * FS_PAD + q * 8 + tig;
        unsigned a0 = __float_as_uint(to_tf32(fr0[0]));
        unsigned a1 = __float_as_uint(to_tf32(fr1[0]));
        unsigned a2 = __float_as_uint(to_tf32(fr0[4]));
        unsigned a3 = __float_as_uint(to_tf32(fr1[4]));
        const float* w0 = wfc + (q * 8 + tig) * WF_PAD + gid;
        const float* w1 = wfc + (q * 8 + tig + 4) * WF_PAD + gid;
        #pragma unroll
        for (int n = 0; n < 8; n++) {
            unsigned b0 = __float_as_uint(w0[n * 8]);
            unsigned b1 = __float_as_uint(w1[n * 8]);
            mma_tf32(acc[n], a0, a1, a2, a3, b0, b1);
        }
    }
    #pragma unroll
    for (int n = 0; n < 8; n++) {
        *(float2*)(lg_s + gid * LG_PAD + n * 8 + 2 * tig)       = make_float2(acc[n][0], acc[n][1]);
        *(float2*)(lg_s + (gid + 8) * LG_PAD + n * 8 + 2 * tig) = make_float2(acc[n][2], acc[n][3]);
    }
}

// per-lane softmax over K=16 + attention pooling for channel ch
__device__ __forceinline__ float att_pool(const float* __restrict__ lg_s,
                                          const float* __restrict__ fs_s, int ch)
{
    float l[KNN];
    float m = -1e30f;
    #pragma unroll
    for (int k = 0; k < KNN; k++) { l[k] = lg_s[k * LG_PAD + ch]; m = fmaxf(m, l[k]); }
    float s = 0.f, a = 0.f;
    #pragma unroll
    for (int k = 0; k < KNN; k++) {
        float e = __expf(l[k] - m);
        s += e;
        a += e * fs_s[k * FS_PAD + ch];
    }
    return __fdividef(a, s);
}

// ---------------------------------------------------------------------------
// Kernel 1: f_pc = ReLU((feature @ w_mlp1) * s + b)
// ---------------------------------------------------------------------------
__global__ __launch_bounds__(256) void kern_mlp1(
    const float* __restrict__ feature,
    const float* __restrict__ w, const float* __restrict__ s, const float* __restrict__ b)
{
    __shared__ float ws[1024];
    __shared__ float sv[32], bv[32];
    __shared__ float xs[8][32];

    for (int i = threadIdx.x; i < 1024; i += blockDim.x) ws[i] = w[i];
    if (threadIdx.x < 32) { sv[threadIdx.x] = s[threadIdx.x]; bv[threadIdx.x] = b[threadIdx.x]; }
    __syncthreads();

    const int lane = threadIdx.x & 31;
    const int warp = threadIdx.x >> 5;
    const int nwarps = (gridDim.x * blockDim.x) >> 5;
    int gw = (blockIdx.x * blockDim.x + threadIdx.x) >> 5;

    for (int p = gw; p < P_TOTAL; p += nwarps) {
        xs[warp][lane] = feature[(size_t)p * 32 + lane];
        __syncwarp();
        float acc = 0.f;
        #pragma unroll
        for (int j4 = 0; j4 < 32; j4 += 4) {
            float4 f = *(const float4*)(&xs[warp][j4]);
            acc += f.x * ws[(j4 + 0) * 32 + lane];
            acc += f.y * ws[(j4 + 1) * 32 + lane];
            acc += f.z * ws[(j4 + 2) * 32 + lane];
            acc += f.w * ws[(j4 + 3) * 32 + lane];
        }
        g_f_pc[(size_t)p * 32 + lane] = fmaxf(acc * sv[lane] + bv[lane], 0.f);
        __syncwarp();
    }
}

// ---------------------------------------------------------------------------
// Kernel 2: rel_pos + lfa1 + gather(f_pc) + att1 -> g_f_agg ; lfa2 -> g_f_xyz2
// per-warp smem: fs 16*68 + lg 16*66 + rp 160 + agg 64 = 2368 floats
// ---------------------------------------------------------------------------
#define K2_WARP_FLOATS 2368
#define K2_BASE_FLOATS 8192   // wfc 4608 + wam 2048 + wl2 1024 + wl1 320 + vec 192
#define K2_WARPS 16
#define K2_SMEM_BYTES ((K2_BASE_FLOATS + K2_WARPS * K2_WARP_FLOATS) * 4)

__global__ __launch_bounds__(512) void kern_att1(
    const float* __restrict__ xyz, const int* __restrict__ neigh,
    const float* __restrict__ wlfa1, const float* __restrict__ slfa1, const float* __restrict__ blfa1,
    const float* __restrict__ wfc1,
    const float* __restrict__ wam1, const float* __restrict__ sam1, const float* __restrict__ bam1,
    const float* __restrict__ wlfa2, const float* __restrict__ slfa2, const float* __restrict__ blfa2)
{
    extern __shared__ float sm[];
    float* s_wfc = sm;            // 4608  wfc1 [64][WF_PAD] tf32-rounded
    float* s_wam = sm + 4608;     // 2048  wam1 [64][32]
    float* s_wl2 = sm + 6656;     // 1024  wlfa2 [32][32]
    float* s_wl1 = sm + 7680;     // 320   wlfa1 [10][32]
    float* s_vec = sm + 8000;     // 192
    float* s_wrp = sm + K2_BASE_FLOATS;

    for (int i = threadIdx.x; i < 4096; i += blockDim.x) {
        int j = i >> 6, c = i & 63;
        s_wfc[j * WF_PAD + c] = to_tf32(wfc1[i]);
    }
    for (int i = threadIdx.x; i < 2048; i += blockDim.x) s_wam[i] = wam1[i];
    for (int i = threadIdx.x; i < 1024; i += blockDim.x) s_wl2[i] = wlfa2[i];
    for (int i = threadIdx.x; i < 320;  i += blockDim.x) s_wl1[i] = wlfa1[i];
    if (threadIdx.x < 32) {
        int l = threadIdx.x;
        s_vec[l]       = slfa1[l];  s_vec[32 + l]  = blfa1[l];
        s_vec[64 + l]  = sam1[l];   s_vec[96 + l]  = bam1[l];
        s_vec[128 + l] = slfa2[l];  s_vec[160 + l] = blfa2[l];
    }
    __syncthreads();

    const int lane = threadIdx.x & 31;
    const int warp = threadIdx.x >> 5;
    float* fs_s  = s_wrp + warp * K2_WARP_FLOATS;   // [16][FS_PAD]
    float* lg_s  = fs_s + 16 * FS_PAD;              // [16][LG_PAD]
    float* rp_s  = lg_s + 16 * LG_PAD;              // [16][10]
    float* agg_s = rp_s + 160;                      // [64]

    const int nwarps = (gridDim.x * blockDim.x) >> 5;
    int gw = (blockIdx.x * blockDim.x + threadIdx.x) >> 5;

    for (int p = gw; p < P_TOTAL; p += nwarps) {
        const int b = p / NPTS;
        const size_t bbase = (size_t)b * NPTS;

        int myidx = 0;
        if (lane < KNN) myidx = neigh[(size_t)p * KNN + lane];

        const float cx = xyz[(size_t)p * 3 + 0];
        const float cy = xyz[(size_t)p * 3 + 1];
        const float cz = xyz[(size_t)p * 3 + 2];

        if (lane < KNN) {
            size_t nb = bbase + (size_t)myidx;
            float nx = xyz[nb * 3 + 0], ny = xyz[nb * 3 + 1], nz = xyz[nb * 3 + 2];
            float rx = cx - nx, ry = cy - ny, rz = cz - nz;
            float d = sqrtf(rx * rx + ry * ry + rz * rz);
            float* rp = rp_s + lane * 10;
            rp[0] = d;  rp[1] = rx; rp[2] = ry; rp[3] = rz;
            rp[4] = cx; rp[5] = cy; rp[6] = cz;
            rp[7] = nx; rp[8] = ny; rp[9] = nz;
        }
        __syncwarp();

        // f_xyz = ReLU(relpos @ wlfa1) -> fs[:,32+lane]
        {
            const float sl = s_vec[lane], bl = s_vec[32 + lane];
            #pragma unroll
            for (int k = 0; k < KNN; k++) {
                float acc = 0.f;
                #pragma unroll
                for (int j = 0; j < 10; j++) acc += rp_s[k * 10 + j] * s_wl1[j * 32 + lane];
                fs_s[k * FS_PAD + 32 + lane] = fmaxf(acc * sl + bl, 0.f);
            }
        }
        // f_nb = gather(f_pc) -> fs[:,lane]
        #pragma unroll
        for (int k = 0; k < KNN; k++) {
            int nb = __shfl_sync(0xffffffffu, myidx, k);
            fs_s[k * FS_PAD + lane] = g_f_pc[(bbase + (size_t)nb) * 32 + lane];
        }
        __syncwarp();

        // logits via tensor cores, then per-lane softmax + pool
        logits_mma(fs_s, lg_s, s_wfc, lane);
        __syncwarp();
        agg_s[lane]      = att_pool(lg_s, fs_s, lane);
        agg_s[32 + lane] = att_pool(lg_s, fs_s, 32 + lane);
        __syncwarp();

        // f_agg = ReLU((agg @ wam1)*s + b), channel = lane
        {
            float acc = 0.f;
            #pragma unroll
            for (int d4 = 0; d4 < 64; d4 += 4) {
                float4 a = *(const float4*)(agg_s + d4);
                acc += a.x * s_wam[(d4 + 0) * 32 + lane];
                acc += a.y * s_wam[(d4 + 1) * 32 + lane];
                acc += a.z * s_wam[(d4 + 2) * 32 + lane];
                acc += a.w * s_wam[(d4 + 3) * 32 + lane];
            }
            g_f_agg[(size_t)p * 32 + lane] = fmaxf(acc * s_vec[64 + lane] + s_vec[96 + lane], 0.f);
        }

        // f_xyz2 = ReLU((f_xyz @ wlfa2)*s + b) -> scratch
        {
            float wcol[32];
            #pragma unroll
            for (int j = 0; j < 32; j++) wcol[j] = s_wl2[j * 32 + lane];
            const float sl = s_vec[128 + lane], bl = s_vec[160 + lane];
            #pragma unroll
            for (int k = 0; k < KNN; k++) {
                float acc = 0.f;
                #pragma unroll
                for (int j4 = 0; j4 < 32; j4 += 4) {
                    float4 f = *(const float4*)(fs_s + k * FS_PAD + 32 + j4);
                    acc += f.x * wcol[j4 + 0] + f.y * wcol[j4 + 1]
                         + f.z * wcol[j4 + 2] + f.w * wcol[j4 + 3];
                }
                g_f_xyz2[((size_t)p * KNN + k) * 32 + lane] = fmaxf(acc * sl + bl, 0.f);
            }
        }
        __syncwarp();
    }
}

// ---------------------------------------------------------------------------
// Kernel 3: gather(f_agg) + f_xyz2 + att2 + att2_mlp + mlp2 + shortcut + leaky
// per-warp smem: fs 1088 + lg 1056 + agg 64 + pc2 64 + feat 32 = 2304 floats
// ---------------------------------------------------------------------------
#define K3_WARP_FLOATS 2304
#define K3_BASE_FLOATS 21632  // wfc 4608 + wam 4096 + wm2 8192 + wsc 4096 + vec 640
#define K3_WARPS 12
#define K3_SMEM_BYTES ((K3_BASE_FLOATS + K3_WARPS * K3_WARP_FLOATS) * 4)

__global__ __launch_bounds__(384) void kern_att2(
    const float* __restrict__ feature, const int* __restrict__ neigh,
    const float* __restrict__ wfc2,
    const float* __restrict__ wam2, const float* __restrict__ sam2, const float* __restrict__ bam2,
    const float* __restrict__ wmlp2, const float* __restrict__ smlp2, const float* __restrict__ bmlp2,
    const float* __restrict__ wsc, const float* __restrict__ ssc, const float* __restrict__ bsc,
    float* __restrict__ out)
{
    extern __shared__ float sm[];
    float* s_wfc = sm;             // 4608  wfc2 [64][WF_PAD] tf32-rounded
    float* s_wam = sm + 4608;      // 4096  wam2 [64][64]
    float* s_wm2 = sm + 8704;      // 8192  wmlp2 [64][128]
    float* s_wsc = sm + 16896;     // 4096  wsc  [32][128]
    float* s_vec = sm + 20992;     // 640
    float* s_wrp = sm + K3_BASE_FLOATS;

    for (int i = threadIdx.x; i < 4096; i += blockDim.x) {
        int j = i >> 6, c = i & 63;
        s_wfc[j * WF_PAD + c] = to_tf32(wfc2[i]);
    }
    for (int i = threadIdx.x; i < 4096; i += blockDim.x) s_wam[i] = wam2[i];
    for (int i = threadIdx.x; i < 8192; i += blockDim.x) s_wm2[i] = wmlp2[i];
    for (int i = threadIdx.x; i < 4096; i += blockDim.x) s_wsc[i] = wsc[i];
    if (threadIdx.x < 64) {
        int l = threadIdx.x;
        s_vec[l] = sam2[l]; s_vec[64 + l] = bam2[l];
    }
    if (threadIdx.x < 128) {
        int l = threadIdx.x;
        s_vec[128 + l] = smlp2[l]; s_vec[256 + l] = bmlp2[l];
        s_vec[384 + l] = ssc[l];   s_vec[512 + l] = bsc[l];
    }
    __syncthreads();

    const int lane = threadIdx.x & 31;
    const int warp = threadIdx.x >> 5;
    float* fs_s   = s_wrp + warp * K3_WARP_FLOATS;  // [16][FS_PAD]
    float* lg_s   = fs_s + 16 * FS_PAD;             // [16][LG_PAD]
    float* agg_s  = lg_s + 16 * LG_PAD;             // [64]
    float* pc2_s  = agg_s + 64;                     // [64]
    float* feat_s = pc2_s + 64;                     // [32]

    const int nwarps = (gridDim.x * blockDim.x) >> 5;
    int gw = (blockIdx.x * blockDim.x + threadIdx.x) >> 5;

    for (int p = gw; p < P_TOTAL; p += nwarps) {
        const int b = p / NPTS;
        const size_t bbase = (size_t)b * NPTS;

        int myidx = 0;
        if (lane < KNN) myidx = neigh[(size_t)p * KNN + lane];

        #pragma unroll
        for (int k = 0; k < KNN; k++) {
            int nb = __shfl_sync(0xffffffffu, myidx, k);
            fs_s[k * FS_PAD + lane] = g_f_agg[(bbase + (size_t)nb) * 32 + lane];
        }
        #pragma unroll
        for (int k = 0; k < KNN; k++) {
            fs_s[k * FS_PAD + 32 + lane] = g_f_xyz2[((size_t)p * KNN + k) * 32 + lane];
        }
        feat_s[lane] = feature[(size_t)p * 32 + lane];
        __syncwarp();

        logits_mma(fs_s, lg_s, s_wfc, lane);
        __syncwarp();
        agg_s[lane]      = att_pool(lg_s, fs_s, lane);
        agg_s[32 + lane] = att_pool(lg_s, fs_s, 32 + lane);
        __syncwarp();

        // f_pc2 = ReLU((agg @ wam2)*s + b), channels lane and lane+32
        {
            float accl = 0.f, acch = 0.f;
            #pragma unroll
            for (int d4 = 0; d4 < 64; d4 += 4) {
                float4 a = *(const float4*)(agg_s + d4);
                accl += a.x * s_wam[(d4 + 0) * 64 + lane];
                accl += a.y * s_wam[(d4 + 1) * 64 + lane];
                accl += a.z * s_wam[(d4 + 2) * 64 + lane];
                accl += a.w * s_wam[(d4 + 3) * 64 + lane];
                acch += a.x * s_wam[(d4 + 0) * 64 + 32 + lane];
                acch += a.y * s_wam[(d4 + 1) * 64 + 32 + lane];
                acch += a.z * s_wam[(d4 + 2) * 64 + 32 + lane];
                acch += a.w * s_wam[(d4 + 3) * 64 + 32 + lane];
            }
            pc2_s[lane]      = fmaxf(accl * s_vec[lane]      + s_vec[64 + lane], 0.f);
            pc2_s[32 + lane] = fmaxf(acch * s_vec[32 + lane] + s_vec[96 + lane], 0.f);
        }
        __syncwarp();

        // out = leaky( (f_pc2 @ wmlp2)*s+b + (feature @ wsc)*s+b )
        #pragma unroll
        for (int ci = 0; ci < 4; ci++) {
            int c = lane + ci * 32;
            float o = 0.f;
            #pragma unroll
            for (int d4 = 0; d4 < 64; d4 += 4) {
                float4 a = *(const float4*)(pc2_s + d4);
                o += a.x * s_wm2[(d4 + 0) * 128 + c];
                o += a.y * s_wm2[(d4 + 1) * 128 + c];
                o += a.z * s_wm2[(d4 + 2) * 128 + c];
                o += a.w * s_wm2[(d4 + 3) * 128 + c];
            }
            float scv = 0.f;
            #pragma unroll
            for (int j4 = 0; j4 < 32; j4 += 4) {
                float4 f = *(const float4*)(feat_s + j4);
                scv += f.x * s_wsc[(j4 + 0) * 128 + c];
                scv += f.y * s_wsc[(j4 + 1) * 128 + c];
                scv += f.z * s_wsc[(j4 + 2) * 128 + c];
                scv += f.w * s_wsc[(j4 + 3) * 128 + c];
            }
            float v = o * s_vec[128 + c] + s_vec[256 + c]
                    + scv * s_vec[384 + c] + s_vec[512 + c];
            out[(size_t)p * 128 + c] = (v < 0.f) ? 0.2f * v : v;
        }
        __syncwarp();
    }
}

// ---------------------------------------------------------------------------
extern "C" void kernel_launch(void* const* d_in, const int* in_sizes, int n_in,
                              void* d_out, int out_size)
{
    const float* feature = (const float*)d_in[0];
    const float* xyz     = (const float*)d_in[1];
    const int*   neigh   = (const int*)  d_in[2];
    const float* w_mlp1  = (const float*)d_in[3];
    const float* s_mlp1  = (const float*)d_in[4];
    const float* b_mlp1  = (const float*)d_in[5];
    const float* w_lfa1  = (const float*)d_in[6];
    const float* s_lfa1  = (const float*)d_in[7];
    const float* b_lfa1  = (const float*)d_in[8];
    const float* w_fc1   = (const float*)d_in[9];
    const float* w_am1   = (const float*)d_in[10];
    const float* s_am1   = (const float*)d_in[11];
    const float* b_am1   = (const float*)d_in[12];
    const float* w_lfa2  = (const float*)d_in[13];
    const float* s_lfa2  = (const float*)d_in[14];
    const float* b_lfa2  = (const float*)d_in[15];
    const float* w_fc2   = (const float*)d_in[16];
    const float* w_am2   = (const float*)d_in[17];
    const float* s_am2   = (const float*)d_in[18];
    const float* b_am2   = (const float*)d_in[19];
    const float* w_mlp2  = (const float*)d_in[20];
    const float* s_mlp2  = (const float*)d_in[21];
    const float* b_mlp2  = (const float*)d_in[22];
    const float* w_sc    = (const float*)d_in[23];
    const float* s_sc    = (const float*)d_in[24];
    const float* b_sc    = (const float*)d_in[25];
    float* out = (float*)d_out;

    cudaFuncSetAttribute(kern_att1, cudaFuncAttributeMaxDynamicSharedMemorySize, K2_SMEM_BYTES);
    cudaFuncSetAttribute(kern_att2, cudaFuncAttributeMaxDynamicSharedMemorySize, K3_SMEM_BYTES);

    kern_mlp1<<<2048, 256>>>(feature, w_mlp1, s_mlp1, b_mlp1);

    kern_att1<<<1024, 512, K2_SMEM_BYTES>>>(
        xyz, neigh,
        w_lfa1, s_lfa1, b_lfa1,
        w_fc1,
        w_am1, s_am1, b_am1,
        w_lfa2, s_lfa2, b_lfa2);

    kern_att2<<<1024, 384, K3_SMEM_BYTES>>>(
        feature, neigh,
        w_fc2,
        w_am2, s_am2, b_am2,
        w_mlp2, s_mlp2, b_mlp2,
        w_sc, s_sc, b_sc,
        out);
}

// round 5
// speedup vs baseline: 2.3515x; 1.5212x over previous
#include <cuda_runtime.h>
#include <math.h>

#define BATCH 4
#define NPTS  40960
#define KNN   16
#define P_TOTAL (BATCH * NPTS)   // 163840

#define FS_PAD 68   // fs tile row stride: conflict-free A-frag loads (4*gid+tig)
#define LG_PAD 66   // logits tile row stride: conflict-free column reads
#define WF_PAD 72   // B-tile stride for n<=64  (8 mod 32)
#define WB_PAD 40   // B-tile stride for n<=32  (8 mod 32)
#define WO_PAD 136  // B-tile stride for n<=128 (8 mod 32)
#define RP_PAD 20   // relpos tile stride (20*gid+tig distinct mod 32)
#define FT_PAD 36   // feat tile stride (4 mod 32)

// Scratch (device globals: no allocation allowed in kernel_launch)
__device__ float g_f_pc [P_TOTAL * 32];                 // 21 MB
__device__ float g_f_agg[P_TOTAL * 32];                 // 21 MB
__device__ float g_agg2 [(size_t)P_TOTAL * 64];         // 42 MB
__device__ float g_f_xyz2[(size_t)P_TOTAL * KNN * 32];  // 335 MB

__device__ __forceinline__ float to_tf32(float x) {
    float r;
    asm("cvt.rna.tf32.f32 %0, %1;" : "=f"(r) : "f"(x));
    return r;
}
__device__ __forceinline__ void tf32_split(float x, unsigned& h, unsigned& l) {
    float hf = to_tf32(x);
    h = __float_as_uint(hf);
    l = __float_as_uint(to_tf32(x - hf));
}

__device__ __forceinline__ void mma_tf32(float* c,
                                         unsigned a0, unsigned a1, unsigned a2, unsigned a3,
                                         unsigned b0, unsigned b1) {
    asm("mma.sync.aligned.m16n8k8.row.col.f32.tf32.tf32.f32 "
        "{%0,%1,%2,%3}, {%4,%5,%6,%7}, {%8,%9}, {%0,%1,%2,%3};"
        : "+f"(c[0]), "+f"(c[1]), "+f"(c[2]), "+f"(c[3])
        : "r"(a0), "r"(a1), "r"(a2), "r"(a3), "r"(b0), "r"(b1));
}

// logits[16][64] = fs[16][64] @ wfc[64][64]  (single tf32 -- softmax-damped)
__device__ __forceinline__ void logits_mma(const float* __restrict__ fs_s,
                                           float* __restrict__ lg_s,
                                           const float* __restrict__ wfc, int lane)
{
    const int gid = lane >> 2;
    const int tig = lane & 3;
    float acc[8][4];
    #pragma unroll
    for (int n = 0; n < 8; n++) { acc[n][0]=0.f; acc[n][1]=0.f; acc[n][2]=0.f; acc[n][3]=0.f; }
    #pragma unroll
    for (int q = 0; q < 8; q++) {
        const float* fr0 = fs_s + gid * FS_PAD + q * 8 + tig;
        const float* fr1 = fs_s + (gid + 8) * FS_PAD + q * 8 + tig;
        unsigned a0 = __float_as_uint(to_tf32(fr0[0]));
        unsigned a1 = __float_as_uint(to_tf32(fr1[0]));
        unsigned a2 = __float_as_uint(to_tf32(fr0[4]));
        unsigned a3 = __float_as_uint(to_tf32(fr1[4]));
        const float* w0 = wfc + (q * 8 + tig) * WF_PAD + gid;
        const float* w1 = wfc + (q * 8 + tig + 4) * WF_PAD + gid;
        #pragma unroll
        for (int n = 0; n < 8; n++) {
            unsigned b0 = __float_as_uint(w0[n * 8]);
            unsigned b1 = __float_as_uint(w1[n * 8]);
            mma_tf32(acc[n], a0, a1, a2, a3, b0, b1);
        }
    }
    #pragma unroll
    for (int n = 0; n < 8; n++) {
        *(float2*)(lg_s + gid * LG_PAD + n * 8 + 2 * tig)       = make_float2(acc[n][0], acc[n][1]);
        *(float2*)(lg_s + (gid + 8) * LG_PAD + n * 8 + 2 * tig) = make_float2(acc[n][2], acc[n][3]);
    }
}

// per-lane softmax over K=16 + attention pooling for channel ch
__device__ __forceinline__ float att_pool(const float* __restrict__ lg_s,
                                          const float* __restrict__ fs_s, int ch)
{
    float l[KNN];
    float m = -1e30f;
    #pragma unroll
    for (int k = 0; k < KNN; k++) { l[k] = lg_s[k * LG_PAD + ch]; m = fmaxf(m, l[k]); }
    float s = 0.f, a = 0.f;
    #pragma unroll
    for (int k = 0; k < KNN; k++) {
        float e = __expf(l[k] - m);
        s += e;
        a += e * fs_s[k * FS_PAD + ch];
    }
    return __fdividef(a, s);
}

// ---------------------------------------------------------------------------
// Kernel 1: f_pc = ReLU((feature @ w_mlp1) * s + b)
// ---------------------------------------------------------------------------
__global__ __launch_bounds__(256) void kern_mlp1(
    const float* __restrict__ feature,
    const float* __restrict__ w, const float* __restrict__ s, const float* __restrict__ b)
{
    __shared__ float ws[1024];
    __shared__ float sv[32], bv[32];
    __shared__ float xs[8][32];

    for (int i = threadIdx.x; i < 1024; i += blockDim.x) ws[i] = w[i];
    if (threadIdx.x < 32) { sv[threadIdx.x] = s[threadIdx.x]; bv[threadIdx.x] = b[threadIdx.x]; }
    __syncthreads();

    const int lane = threadIdx.x & 31;
    const int warp = threadIdx.x >> 5;
    const int nwarps = (gridDim.x * blockDim.x) >> 5;
    int gw = (blockIdx.x * blockDim.x + threadIdx.x) >> 5;

    for (int p = gw; p < P_TOTAL; p += nwarps) {
        xs[warp][lane] = feature[(size_t)p * 32 + lane];
        __syncwarp();
        float acc = 0.f;
        #pragma unroll
        for (int j4 = 0; j4 < 32; j4 += 4) {
            float4 f = *(const float4*)(&xs[warp][j4]);
            acc += f.x * ws[(j4 + 0) * 32 + lane];
            acc += f.y * ws[(j4 + 1) * 32 + lane];
            acc += f.z * ws[(j4 + 2) * 32 + lane];
            acc += f.w * ws[(j4 + 3) * 32 + lane];
        }
        g_f_pc[(size_t)p * 32 + lane] = fmaxf(acc * sv[lane] + bv[lane], 0.f);
        __syncwarp();
    }
}

// ---------------------------------------------------------------------------
// Kernel 2: rel_pos + lfa1(mma) + gather + logits(mma) + pool + f_agg ;
//           lfa2(mma) -> g_f_xyz2
// ---------------------------------------------------------------------------
#define K2_WARP_FLOATS 2528   // fs 1088 + lg 1056 + rp 320 + agg 64
#define K2_BASE_FLOATS 10624
#define K2_WARPS 16
#define K2_SMEM_BYTES ((K2_BASE_FLOATS + K2_WARPS * K2_WARP_FLOATS) * 4)

__global__ __launch_bounds__(512) void kern_att1(
    const float* __restrict__ xyz, const int* __restrict__ neigh,
    const float* __restrict__ wlfa1, const float* __restrict__ slfa1, const float* __restrict__ blfa1,
    const float* __restrict__ wfc1,
    const float* __restrict__ wam1, const float* __restrict__ sam1, const float* __restrict__ bam1,
    const float* __restrict__ wlfa2, const float* __restrict__ slfa2, const float* __restrict__ blfa2)
{
    extern __shared__ float sm[];
    float* s_wfc  = sm;            // 4608  wfc1 [64][72] tf32
    float* s_wam  = sm + 4608;     // 2048  wam1*sam1 [64][32] fp32
    float* s_wl1h = sm + 6656;     // 640   (wlfa1*slfa1) hi [16][40], rows 10-15 zero
    float* s_wl1l = sm + 7296;     // 640   lo
    float* s_wl2h = sm + 7936;     // 1280  (wlfa2*slfa2) hi [32][40]
    float* s_wl2l = sm + 9216;     // 1280  lo
    float* s_vec  = sm + 10496;    // 128: blfa1[32], blfa2[32], bam1[32]
    float* s_wrp  = sm + K2_BASE_FLOATS;

    for (int i = threadIdx.x; i < 4096; i += blockDim.x) {
        int j = i >> 6, c = i & 63;
        s_wfc[j * WF_PAD + c] = to_tf32(wfc1[i]);
    }
    for (int i = threadIdx.x; i < 2048; i += blockDim.x)
        s_wam[i] = wam1[i] * sam1[i & 31];
    for (int i = threadIdx.x; i < 640; i += blockDim.x) {
        int j = i / WB_PAD, c = i % WB_PAD;
        float v = (j < 10 && c < 32) ? wlfa1[j * 32 + c] * slfa1[c] : 0.f;
        float h = to_tf32(v);
        s_wl1h[i] = h;
        s_wl1l[i] = to_tf32(v - h);
    }
    for (int i = threadIdx.x; i < 1280; i += blockDim.x) {
        int j = i / WB_PAD, c = i % WB_PAD;
        float v = (c < 32) ? wlfa2[j * 32 + c] * slfa2[c] : 0.f;
        float h = to_tf32(v);
        s_wl2h[i] = h;
        s_wl2l[i] = to_tf32(v - h);
    }
    if (threadIdx.x < 32) {
        int l = threadIdx.x;
        s_vec[l]      = blfa1[l];
        s_vec[32 + l] = blfa2[l];
        s_vec[64 + l] = bam1[l];
    }
    __syncthreads();

    const int lane = threadIdx.x & 31;
    const int warp = threadIdx.x >> 5;
    const int gid = lane >> 2, tig = lane & 3;
    float* fs_s  = s_wrp + warp * K2_WARP_FLOATS;   // [16][68]
    float* lg_s  = fs_s + 1088;                     // [16][66]
    float* rp_s  = fs_s + 2144;                     // [16][20]
    float* agg_s = fs_s + 2464;                     // [64]

    // zero relpos pad columns (cols 10..15 of every row) once
    if (lane < KNN) {
        #pragma unroll
        for (int c = 10; c < 16; c++) rp_s[lane * RP_PAD + c] = 0.f;
    }
    __syncwarp();

    const int nwarps = (gridDim.x * blockDim.x) >> 5;
    int gw = (blockIdx.x * blockDim.x + threadIdx.x) >> 5;

    for (int p = gw; p < P_TOTAL; p += nwarps) {
        const int b = p / NPTS;
        const size_t bbase = (size_t)b * NPTS;

        int myidx = 0;
        if (lane < KNN) myidx = neigh[(size_t)p * KNN + lane];

        // issue gather loads early (hide latency under rel_pos + lfa1)
        float gv[KNN];
        #pragma unroll
        for (int k = 0; k < KNN; k++) {
            int nb = __shfl_sync(0xffffffffu, myidx, k);
            gv[k] = g_f_pc[(bbase + (size_t)nb) * 32 + lane];
        }

        const float cx = xyz[(size_t)p * 3 + 0];
        const float cy = xyz[(size_t)p * 3 + 1];
        const float cz = xyz[(size_t)p * 3 + 2];

        if (lane < KNN) {
            size_t nb = bbase + (size_t)myidx;
            float nx = xyz[nb * 3 + 0], ny = xyz[nb * 3 + 1], nz = xyz[nb * 3 + 2];
            float rx = cx - nx, ry = cy - ny, rz = cz - nz;
            float d = sqrtf(rx * rx + ry * ry + rz * rz);
            float* rp = rp_s + lane * RP_PAD;
            rp[0] = d;  rp[1] = rx; rp[2] = ry; rp[3] = rz;
            rp[4] = cx; rp[5] = cy; rp[6] = cz;
            rp[7] = nx; rp[8] = ny; rp[9] = nz;
        }
        __syncwarp();

        // ---- lfa1 via 3xTF32 mma: f_xyz[16][32] -> fs cols 32..63
        {
            float acc[4][4];
            #pragma unroll
            for (int n = 0; n < 4; n++) { acc[n][0]=0.f; acc[n][1]=0.f; acc[n][2]=0.f; acc[n][3]=0.f; }
            #pragma unroll
            for (int q = 0; q < 2; q++) {
                unsigned ah0, al0, ah1, al1, ah2, al2, ah3, al3;
                tf32_split(rp_s[gid * RP_PAD + q * 8 + tig],           ah0, al0);
                tf32_split(rp_s[(gid + 8) * RP_PAD + q * 8 + tig],     ah1, al1);
                tf32_split(rp_s[gid * RP_PAD + q * 8 + tig + 4],       ah2, al2);
                tf32_split(rp_s[(gid + 8) * RP_PAD + q * 8 + tig + 4], ah3, al3);
                const float* ph0 = s_wl1h + (q * 8 + tig) * WB_PAD + gid;
                const float* ph1 = s_wl1h + (q * 8 + tig + 4) * WB_PAD + gid;
                const float* pl0 = s_wl1l + (q * 8 + tig) * WB_PAD + gid;
                const float* pl1 = s_wl1l + (q * 8 + tig + 4) * WB_PAD + gid;
                #pragma unroll
                for (int n = 0; n < 4; n++) {
                    unsigned bh0 = __float_as_uint(ph0[n * 8]);
                    unsigned bh1 = __float_as_uint(ph1[n * 8]);
                    unsigned bl0 = __float_as_uint(pl0[n * 8]);
                    unsigned bl1 = __float_as_uint(pl1[n * 8]);
                    mma_tf32(acc[n], ah0, ah1, ah2, ah3, bh0, bh1);
                    mma_tf32(acc[n], al0, al1, al2, al3, bh0, bh1);
                    mma_tf32(acc[n], ah0, ah1, ah2, ah3, bl0, bl1);
                }
            }
            #pragma unroll
            for (int n = 0; n < 4; n++) {
                int c0 = n * 8 + 2 * tig;
                float b0 = s_vec[c0], b1 = s_vec[c0 + 1];
                *(float2*)(fs_s + gid * FS_PAD + 32 + c0) =
                    make_float2(fmaxf(acc[n][0] + b0, 0.f), fmaxf(acc[n][1] + b1, 0.f));
                *(float2*)(fs_s + (gid + 8) * FS_PAD + 32 + c0) =
                    make_float2(fmaxf(acc[n][2] + b0, 0.f), fmaxf(acc[n][3] + b1, 0.f));
            }
        }

        // gathered f_pc -> fs cols 0..31
        #pragma unroll
        for (int k = 0; k < KNN; k++) fs_s[k * FS_PAD + lane] = gv[k];
        __syncwarp();

        // ---- logits + softmax pool
        logits_mma(fs_s, lg_s, s_wfc, lane);
        __syncwarp();
        agg_s[lane]      = att_pool(lg_s, fs_s, lane);
        agg_s[32 + lane] = att_pool(lg_s, fs_s, 32 + lane);
        __syncwarp();

        // ---- f_agg = ReLU(agg @ (wam1*s) + b)   (scalar, 64 FFMA)
        {
            float acc = 0.f;
            #pragma unroll
            for (int d4 = 0; d4 < 64; d4 += 4) {
                float4 a = *(const float4*)(agg_s + d4);
                acc += a.x * s_wam[(d4 + 0) * 32 + lane];
                acc += a.y * s_wam[(d4 + 1) * 32 + lane];
                acc += a.z * s_wam[(d4 + 2) * 32 + lane];
                acc += a.w * s_wam[(d4 + 3) * 32 + lane];
            }
            g_f_agg[(size_t)p * 32 + lane] = fmaxf(acc + s_vec[64 + lane], 0.f);
        }

        // ---- lfa2 via 3xTF32 mma: f_xyz2[16][32] -> gmem
        {
            float acc[4][4];
            #pragma unroll
            for (int n = 0; n < 4; n++) { acc[n][0]=0.f; acc[n][1]=0.f; acc[n][2]=0.f; acc[n][3]=0.f; }
            #pragma unroll
            for (int q = 0; q < 4; q++) {
                unsigned ah0, al0, ah1, al1, ah2, al2, ah3, al3;
                tf32_split(fs_s[gid * FS_PAD + 32 + q * 8 + tig],           ah0, al0);
                tf32_split(fs_s[(gid + 8) * FS_PAD + 32 + q * 8 + tig],     ah1, al1);
                tf32_split(fs_s[gid * FS_PAD + 32 + q * 8 + tig + 4],       ah2, al2);
                tf32_split(fs_s[(gid + 8) * FS_PAD + 32 + q * 8 + tig + 4], ah3, al3);
                const float* ph0 = s_wl2h + (q * 8 + tig) * WB_PAD + gid;
                const float* ph1 = s_wl2h + (q * 8 + tig + 4) * WB_PAD + gid;
                const float* pl0 = s_wl2l + (q * 8 + tig) * WB_PAD + gid;
                const float* pl1 = s_wl2l + (q * 8 + tig + 4) * WB_PAD + gid;
                #pragma unroll
                for (int n = 0; n < 4; n++) {
                    unsigned bh0 = __float_as_uint(ph0[n * 8]);
                    unsigned bh1 = __float_as_uint(ph1[n * 8]);
                    unsigned bl0 = __float_as_uint(pl0[n * 8]);
                    unsigned bl1 = __float_as_uint(pl1[n * 8]);
                    mma_tf32(acc[n], ah0, ah1, ah2, ah3, bh0, bh1);
                    mma_tf32(acc[n], al0, al1, al2, al3, bh0, bh1);
                    mma_tf32(acc[n], ah0, ah1, ah2, ah3, bl0, bl1);
                }
            }
            #pragma unroll
            for (int n = 0; n < 4; n++) {
                int c0 = n * 8 + 2 * tig;
                float b0 = s_vec[32 + c0], b1 = s_vec[32 + c0 + 1];
                *(float2*)(&g_f_xyz2[((size_t)p * KNN + gid) * 32 + c0]) =
                    make_float2(fmaxf(acc[n][0] + b0, 0.f), fmaxf(acc[n][1] + b1, 0.f));
                *(float2*)(&g_f_xyz2[((size_t)p * KNN + gid + 8) * 32 + c0]) =
                    make_float2(fmaxf(acc[n][2] + b0, 0.f), fmaxf(acc[n][3] + b1, 0.f));
            }
        }
        __syncwarp();
    }
}

// ---------------------------------------------------------------------------
// Kernel 3: gather(f_agg) + f_xyz2 + logits(mma) + pool -> g_agg2
// ---------------------------------------------------------------------------
#define K3_WARP_FLOATS 2144   // fs 1088 + lg 1056
#define K3_BASE_FLOATS 4608
#define K3_WARPS 16
#define K3_SMEM_BYTES ((K3_BASE_FLOATS + K3_WARPS * K3_WARP_FLOATS) * 4)

__global__ __launch_bounds__(512) void kern_att2(
    const int* __restrict__ neigh,
    const float* __restrict__ wfc2)
{
    extern __shared__ float sm[];
    float* s_wfc = sm;             // 4608 wfc2 [64][72] tf32
    float* s_wrp = sm + K3_BASE_FLOATS;

    for (int i = threadIdx.x; i < 4096; i += blockDim.x) {
        int j = i >> 6, c = i & 63;
        s_wfc[j * WF_PAD + c] = to_tf32(wfc2[i]);
    }
    __syncthreads();

    const int lane = threadIdx.x & 31;
    const int warp = threadIdx.x >> 5;
    float* fs_s = s_wrp + warp * K3_WARP_FLOATS;   // [16][68]
    float* lg_s = fs_s + 1088;                     // [16][66]

    const int nwarps = (gridDim.x * blockDim.x) >> 5;
    int gw = (blockIdx.x * blockDim.x + threadIdx.x) >> 5;

    for (int p = gw; p < P_TOTAL; p += nwarps) {
        const int b = p / NPTS;
        const size_t bbase = (size_t)b * NPTS;

        int myidx = 0;
        if (lane < KNN) myidx = neigh[(size_t)p * KNN + lane];

        #pragma unroll
        for (int k = 0; k < KNN; k++) {
            int nb = __shfl_sync(0xffffffffu, myidx, k);
            fs_s[k * FS_PAD + lane] = g_f_agg[(bbase + (size_t)nb) * 32 + lane];
        }
        #pragma unroll
        for (int k = 0; k < KNN; k++) {
            fs_s[k * FS_PAD + 32 + lane] = g_f_xyz2[((size_t)p * KNN + k) * 32 + lane];
        }
        __syncwarp();

        logits_mma(fs_s, lg_s, s_wfc, lane);
        __syncwarp();

        g_agg2[(size_t)p * 64 + lane]      = att_pool(lg_s, fs_s, lane);
        g_agg2[(size_t)p * 64 + 32 + lane] = att_pool(lg_s, fs_s, 32 + lane);
        __syncwarp();
    }
}

// ---------------------------------------------------------------------------
// Kernel 4: 16-point tiles: pc2 = relu(agg2@wam2'+b); out = leaky(pc2@wm2' +
//           feat@wsc' + b2).  All GEMMs 3xTF32, scales folded into weights.
// ---------------------------------------------------------------------------
#define OUT_WARPS 8
#define OUT_BASE_FLOATS 35520
#define OUT_WARP_FLOATS 2176  // A1 1088 (reused for feat) + P2 1088
#define OUT_SMEM_BYTES ((OUT_BASE_FLOATS + OUT_WARPS * OUT_WARP_FLOATS) * 4)

__global__ __launch_bounds__(256) void kern_out(
    const float* __restrict__ feature,
    const float* __restrict__ wam2, const float* __restrict__ sam2, const float* __restrict__ bam2,
    const float* __restrict__ wmlp2, const float* __restrict__ smlp2, const float* __restrict__ bmlp2,
    const float* __restrict__ wsc, const float* __restrict__ ssc, const float* __restrict__ bsc,
    float* __restrict__ out)
{
    extern __shared__ float sm[];
    float* w1h = sm;            // [64][WF_PAD=72]  (4608)
    float* w1l = sm + 4608;     // [64][72]
    float* w2h = sm + 9216;     // [64][WO_PAD=136] (8704)
    float* w2l = sm + 17920;
    float* w3h = sm + 26624;    // [32][136] (4352)
    float* w3l = sm + 30976;
    float* b1  = sm + 35328;    // [64]
    float* b2  = sm + 35392;    // [128]
    float* wrp = sm + OUT_BASE_FLOATS;

    for (int i = threadIdx.x; i < 4096; i += blockDim.x) {
        int j = i >> 6, c = i & 63;
        float v = wam2[i] * sam2[c];
        float h = to_tf32(v);
        w1h[j * WF_PAD + c] = h;                 // FIX: WF_PAD stride (was WO_PAD overflow)
        w1l[j * WF_PAD + c] = to_tf32(v - h);
    }
    for (int i = threadIdx.x; i < 8192; i += blockDim.x) {
        int j = i >> 7, c = i & 127;
        float v = wmlp2[i] * smlp2[c];
        float h = to_tf32(v);
        w2h[j * WO_PAD + c] = h;
        w2l[j * WO_PAD + c] = to_tf32(v - h);
    }
    for (int i = threadIdx.x; i < 4096; i += blockDim.x) {
        int j = i >> 7, c = i & 127;
        float v = wsc[i] * ssc[c];
        float h = to_tf32(v);
        w3h[j * WO_PAD + c] = h;
        w3l[j * WO_PAD + c] = to_tf32(v - h);
    }
    if (threadIdx.x < 64)  b1[threadIdx.x] = bam2[threadIdx.x];
    if (threadIdx.x < 128) b2[threadIdx.x] = bmlp2[threadIdx.x] + bsc[threadIdx.x];
    __syncthreads();

    const int lane = threadIdx.x & 31;
    const int warp = threadIdx.x >> 5;
    const int gid = lane >> 2, tig = lane & 3;
    float* A1 = wrp + warp * OUT_WARP_FLOATS;  // [16][68] agg2, later [16][36] feat
    float* P2 = A1 + 1088;                     // [16][68] pc2

    const int nwarps = (gridDim.x * blockDim.x) >> 5;
    int gw = (blockIdx.x * blockDim.x + threadIdx.x) >> 5;
    const int ntiles = P_TOTAL / 16;

    for (int t = gw; t < ntiles; t += nwarps) {
        const int p0 = t * 16;

        float fpre[16];
        #pragma unroll
        for (int r = 0; r < 16; r++) {
            A1[r * FS_PAD + lane]      = g_agg2[(size_t)(p0 + r) * 64 + lane];
            A1[r * FS_PAD + 32 + lane] = g_agg2[(size_t)(p0 + r) * 64 + 32 + lane];
            fpre[r] = feature[(size_t)(p0 + r) * 32 + lane];
        }
        __syncwarp();

        // GEMM1: pc2 = relu(agg @ w1 + b1)
        {
            float acc[8][4];
            #pragma unroll
            for (int n = 0; n < 8; n++) { acc[n][0]=0.f; acc[n][1]=0.f; acc[n][2]=0.f; acc[n][3]=0.f; }
            #pragma unroll
            for (int q = 0; q < 8; q++) {
                unsigned ah0, al0, ah1, al1, ah2, al2, ah3, al3;
                tf32_split(A1[gid * FS_PAD + q * 8 + tig],           ah0, al0);
                tf32_split(A1[(gid + 8) * FS_PAD + q * 8 + tig],     ah1, al1);
                tf32_split(A1[gid * FS_PAD + q * 8 + tig + 4],       ah2, al2);
                tf32_split(A1[(gid + 8) * FS_PAD + q * 8 + tig + 4], ah3, al3);
                const float* ph0 = w1h + (q * 8 + tig) * WF_PAD + gid;      // FIX: WF_PAD
                const float* ph1 = w1h + (q * 8 + tig + 4) * WF_PAD + gid;
                const float* pl0 = w1l + (q * 8 + tig) * WF_PAD + gid;
                const float* pl1 = w1l + (q * 8 + tig + 4) * WF_PAD + gid;
                #pragma unroll
                for (int n = 0; n < 8; n++) {
                    unsigned bh0 = __float_as_uint(ph0[n * 8]);
                    unsigned bh1 = __float_as_uint(ph1[n * 8]);
                    unsigned bl0 = __float_as_uint(pl0[n * 8]);
                    unsigned bl1 = __float_as_uint(pl1[n * 8]);
                    mma_tf32(acc[n], ah0, ah1, ah2, ah3, bh0, bh1);
                    mma_tf32(acc[n], al0, al1, al2, al3, bh0, bh1);
                    mma_tf32(acc[n], ah0, ah1, ah2, ah3, bl0, bl1);
                }
            }
            #pragma unroll
            for (int n = 0; n < 8; n++) {
                int c0 = n * 8 + 2 * tig;
                float bb0 = b1[c0], bb1 = b1[c0 + 1];
                *(float2*)(P2 + gid * FS_PAD + c0) =
                    make_float2(fmaxf(acc[n][0] + bb0, 0.f), fmaxf(acc[n][1] + bb1, 0.f));
                *(float2*)(P2 + (gid + 8) * FS_PAD + c0) =
                    make_float2(fmaxf(acc[n][2] + bb0, 0.f), fmaxf(acc[n][3] + bb1, 0.f));
            }
        }
        __syncwarp();

        // overwrite A1 with feat tile [16][36]
        #pragma unroll
        for (int r = 0; r < 16; r++) A1[r * FT_PAD + lane] = fpre[r];
        __syncwarp();

        // GEMM2 (pc2 @ w2) + GEMM3 (feat @ w3), n in two halves of 8
        #pragma unroll
        for (int h = 0; h < 2; h++) {
            float acc[8][4];
            #pragma unroll
            for (int n = 0; n < 8; n++) { acc[n][0]=0.f; acc[n][1]=0.f; acc[n][2]=0.f; acc[n][3]=0.f; }
            #pragma unroll
            for (int q = 0; q < 8; q++) {
                unsigned ah0, al0, ah1, al1, ah2, al2, ah3, al3;
                tf32_split(P2[gid * FS_PAD + q * 8 + tig],           ah0, al0);
                tf32_split(P2[(gid + 8) * FS_PAD + q * 8 + tig],     ah1, al1);
                tf32_split(P2[gid * FS_PAD + q * 8 + tig + 4],       ah2, al2);
                tf32_split(P2[(gid + 8) * FS_PAD + q * 8 + tig + 4], ah3, al3);
                const float* ph0 = w2h + (q * 8 + tig) * WO_PAD + h * 64 + gid;
                const float* ph1 = w2h + (q * 8 + tig + 4) * WO_PAD + h * 64 + gid;
                const float* pl0 = w2l + (q * 8 + tig) * WO_PAD + h * 64 + gid;
                const float* pl1 = w2l + (q * 8 + tig + 4) * WO_PAD + h * 64 + gid;
                #pragma unroll
                for (int n = 0; n < 8; n++) {
                    unsigned bh0 = __float_as_uint(ph0[n * 8]);
                    unsigned bh1 = __float_as_uint(ph1[n * 8]);
                    unsigned bl0 = __float_as_uint(pl0[n * 8]);
                    unsigned bl1 = __float_as_uint(pl1[n * 8]);
                    mma_tf32(acc[n], ah0, ah1, ah2, ah3, bh0, bh1);
                    mma_tf32(acc[n], al0, al1, al2, al3, bh0, bh1);
                    mma_tf32(acc[n], ah0, ah1, ah2, ah3, bl0, bl1);
                }
            }
            #pragma unroll
            for (int q = 0; q < 4; q++) {
                unsigned ah0, al0, ah1, al1, ah2, al2, ah3, al3;
                tf32_split(A1[gid * FT_PAD + q * 8 + tig],           ah0, al0);
                tf32_split(A1[(gid + 8) * FT_PAD + q * 8 + tig],     ah1, al1);
                tf32_split(A1[gid * FT_PAD + q * 8 + tig + 4],       ah2, al2);
                tf32_split(A1[(gid + 8) * FT_PAD + q * 8 + tig + 4], ah3, al3);
                const float* ph0 = w3h + (q * 8 + tig) * WO_PAD + h * 64 + gid;
                const float* ph1 = w3h + (q * 8 + tig + 4) * WO_PAD + h * 64 + gid;
                const float* pl0 = w3l + (q * 8 + tig) * WO_PAD + h * 64 + gid;
                const float* pl1 = w3l + (q * 8 + tig + 4) * WO_PAD + h * 64 + gid;
                #pragma unroll
                for (int n = 0; n < 8; n++) {
                    unsigned bh0 = __float_as_uint(ph0[n * 8]);
                    unsigned bh1 = __float_as_uint(ph1[n * 8]);
                    unsigned bl0 = __float_as_uint(pl0[n * 8]);
                    unsigned bl1 = __float_as_uint(pl1[n * 8]);
                    mma_tf32(acc[n], ah0, ah1, ah2, ah3, bh0, bh1);
                    mma_tf32(acc[n], al0, al1, al2, al3, bh0, bh1);
                    mma_tf32(acc[n], ah0, ah1, ah2, ah3, bl0, bl1);
                }
            }
            #pragma unroll
            for (int n = 0; n < 8; n++) {
                int c0 = h * 64 + n * 8 + 2 * tig;
                float bb0 = b2[c0], bb1 = b2[c0 + 1];
                float v0 = acc[n][0] + bb0; v0 = (v0 < 0.f) ? 0.2f * v0 : v0;
                float v1 = acc[n][1] + bb1; v1 = (v1 < 0.f) ? 0.2f * v1 : v1;
                float v2 = acc[n][2] + bb0; v2 = (v2 < 0.f) ? 0.2f * v2 : v2;
                float v3 = acc[n][3] + bb1; v3 = (v3 < 0.f) ? 0.2f * v3 : v3;
                *(float2*)(&out[(size_t)(p0 + gid) * 128 + c0])     = make_float2(v0, v1);
                *(float2*)(&out[(size_t)(p0 + gid + 8) * 128 + c0]) = make_float2(v2, v3);
            }
        }
        __syncwarp();
    }
}

// ---------------------------------------------------------------------------
extern "C" void kernel_launch(void* const* d_in, const int* in_sizes, int n_in,
                              void* d_out, int out_size)
{
    const float* feature = (const float*)d_in[0];
    const float* xyz     = (const float*)d_in[1];
    const int*   neigh   = (const int*)  d_in[2];
    const float* w_mlp1  = (const float*)d_in[3];
    const float* s_mlp1  = (const float*)d_in[4];
    const float* b_mlp1  = (const float*)d_in[5];
    const float* w_lfa1  = (const float*)d_in[6];
    const float* s_lfa1  = (const float*)d_in[7];
    const float* b_lfa1  = (const float*)d_in[8];
    const float* w_fc1   = (const float*)d_in[9];
    const float* w_am1   = (const float*)d_in[10];
    const float* s_am1   = (const float*)d_in[11];
    const float* b_am1   = (const float*)d_in[12];
    const float* w_lfa2  = (const float*)d_in[13];
    const float* s_lfa2  = (const float*)d_in[14];
    const float* b_lfa2  = (const float*)d_in[15];
    const float* w_fc2   = (const float*)d_in[16];
    const float* w_am2   = (const float*)d_in[17];
    const float* s_am2   = (const float*)d_in[18];
    const float* b_am2   = (const float*)d_in[19];
    const float* w_mlp2  = (const float*)d_in[20];
    const float* s_mlp2  = (const float*)d_in[21];
    const float* b_mlp2  = (const float*)d_in[22];
    const float* w_sc    = (const float*)d_in[23];
    const float* s_sc    = (const float*)d_in[24];
    const float* b_sc    = (const float*)d_in[25];
    float* out = (float*)d_out;

    cudaFuncSetAttribute(kern_att1, cudaFuncAttributeMaxDynamicSharedMemorySize, K2_SMEM_BYTES);
    cudaFuncSetAttribute(kern_att2, cudaFuncAttributeMaxDynamicSharedMemorySize, K3_SMEM_BYTES);
    cudaFuncSetAttribute(kern_out,  cudaFuncAttributeMaxDynamicSharedMemorySize, OUT_SMEM_BYTES);

    kern_mlp1<<<2048, 256>>>(feature, w_mlp1, s_mlp1, b_mlp1);

    kern_att1<<<148, 512, K2_SMEM_BYTES>>>(
        xyz, neigh,
        w_lfa1, s_lfa1, b_lfa1,
        w_fc1,
        w_am1, s_am1, b_am1,
        w_lfa2, s_lfa2, b_lfa2);

    kern_att2<<<148, 512, K3_SMEM_BYTES>>>(neigh, w_fc2);

    kern_out<<<148, 256, OUT_SMEM_BYTES>>>(
        feature,
        w_am2, s_am2, b_am2,
        w_mlp2, s_mlp2, b_mlp2,
        w_sc, s_sc, b_sc,
        out);
}

// round 6
// speedup vs baseline: 2.3979x; 1.0197x over previous
#include <cuda_runtime.h>
#include <cuda_fp16.h>
#include <math.h>

#define BATCH 4
#define NPTS  40960
#define KNN   16
#define P_TOTAL (BATCH * NPTS)   // 163840

#define FS_PAD 68   // fs tile row stride: conflict-free A-frag loads (4*gid+tig)
#define LG_PAD 66   // logits tile row stride: conflict-free column reads
#define WF_PAD 72   // B-tile stride for n<=64  (8 mod 32)
#define WB_PAD 40   // B-tile stride for n<=32  (8 mod 32)
#define WO_PAD 136  // B-tile stride for n<=128 (8 mod 32)
#define RP_PAD 20   // relpos tile stride (20*gid+tig distinct mod 32)
#define OA_PAD 100  // kern_out A tile stride (4 mod 32)

// Scratch (device globals: no allocation allowed in kernel_launch)
__device__ float   g_f_pc [P_TOTAL * 32];                    // 21 MB
__device__ float   g_f_agg[P_TOTAL * 32];                    // 21 MB
__device__ float   g_agg2 [(size_t)P_TOTAL * 64];            // 42 MB
__device__ __half2 g_fx2  [(size_t)P_TOTAL * KNN * 16];      // 168 MB

__device__ __forceinline__ float to_tf32(float x) {
    float r;
    asm("cvt.rna.tf32.f32 %0, %1;" : "=f"(r) : "f"(x));
    return r;
}
__device__ __forceinline__ void tf32_split(float x, unsigned& h, unsigned& l) {
    float hf = to_tf32(x);
    h = __float_as_uint(hf);
    l = __float_as_uint(to_tf32(x - hf));
}

__device__ __forceinline__ void mma_tf32(float* c,
                                         unsigned a0, unsigned a1, unsigned a2, unsigned a3,
                                         unsigned b0, unsigned b1) {
    asm("mma.sync.aligned.m16n8k8.row.col.f32.tf32.tf32.f32 "
        "{%0,%1,%2,%3}, {%4,%5,%6,%7}, {%8,%9}, {%0,%1,%2,%3};"
        : "+f"(c[0]), "+f"(c[1]), "+f"(c[2]), "+f"(c[3])
        : "r"(a0), "r"(a1), "r"(a2), "r"(a3), "r"(b0), "r"(b1));
}

// logits[16][64] = fs[16][64] @ wfc[64][64]  (single tf32 -- softmax-damped)
__device__ __forceinline__ void logits_mma(const float* __restrict__ fs_s,
                                           float* __restrict__ lg_s,
                                           const float* __restrict__ wfc, int lane)
{
    const int gid = lane >> 2;
    const int tig = lane & 3;
    float acc[8][4];
    #pragma unroll
    for (int n = 0; n < 8; n++) { acc[n][0]=0.f; acc[n][1]=0.f; acc[n][2]=0.f; acc[n][3]=0.f; }
    #pragma unroll
    for (int q = 0; q < 8; q++) {
        const float* fr0 = fs_s + gid * FS_PAD + q * 8 + tig;
        const float* fr1 = fs_s + (gid + 8) * FS_PAD + q * 8 + tig;
        unsigned a0 = __float_as_uint(to_tf32(fr0[0]));
        unsigned a1 = __float_as_uint(to_tf32(fr1[0]));
        unsigned a2 = __float_as_uint(to_tf32(fr0[4]));
        unsigned a3 = __float_as_uint(to_tf32(fr1[4]));
        const float* w0 = wfc + (q * 8 + tig) * WF_PAD + gid;
        const float* w1 = wfc + (q * 8 + tig + 4) * WF_PAD + gid;
        #pragma unroll
        for (int n = 0; n < 8; n++) {
            unsigned b0 = __float_as_uint(w0[n * 8]);
            unsigned b1 = __float_as_uint(w1[n * 8]);
            mma_tf32(acc[n], a0, a1, a2, a3, b0, b1);
        }
    }
    #pragma unroll
    for (int n = 0; n < 8; n++) {
        *(float2*)(lg_s + gid * LG_PAD + n * 8 + 2 * tig)       = make_float2(acc[n][0], acc[n][1]);
        *(float2*)(lg_s + (gid + 8) * LG_PAD + n * 8 + 2 * tig) = make_float2(acc[n][2], acc[n][3]);
    }
}

// per-lane softmax over K=16 + attention pooling for channel ch
__device__ __forceinline__ float att_pool(const float* __restrict__ lg_s,
                                          const float* __restrict__ fs_s, int ch)
{
    float l[KNN];
    float m = -1e30f;
    #pragma unroll
    for (int k = 0; k < KNN; k++) { l[k] = lg_s[k * LG_PAD + ch]; m = fmaxf(m, l[k]); }
    float s = 0.f, a = 0.f;
    #pragma unroll
    for (int k = 0; k < KNN; k++) {
        float e = __expf(l[k] - m);
        s += e;
        a += e * fs_s[k * FS_PAD + ch];
    }
    return __fdividef(a, s);
}

// ---------------------------------------------------------------------------
// Kernel 1: f_pc = ReLU((feature @ w_mlp1) * s + b)
// ---------------------------------------------------------------------------
__global__ __launch_bounds__(256) void kern_mlp1(
    const float* __restrict__ feature,
    const float* __restrict__ w, const float* __restrict__ s, const float* __restrict__ b)
{
    __shared__ float ws[1024];
    __shared__ float sv[32], bv[32];
    __shared__ float xs[8][32];

    for (int i = threadIdx.x; i < 1024; i += blockDim.x) ws[i] = w[i];
    if (threadIdx.x < 32) { sv[threadIdx.x] = s[threadIdx.x]; bv[threadIdx.x] = b[threadIdx.x]; }
    __syncthreads();

    const int lane = threadIdx.x & 31;
    const int warp = threadIdx.x >> 5;
    const int nwarps = (gridDim.x * blockDim.x) >> 5;
    int gw = (blockIdx.x * blockDim.x + threadIdx.x) >> 5;

    for (int p = gw; p < P_TOTAL; p += nwarps) {
        xs[warp][lane] = feature[(size_t)p * 32 + lane];
        __syncwarp();
        float acc = 0.f;
        #pragma unroll
        for (int j4 = 0; j4 < 32; j4 += 4) {
            float4 f = *(const float4*)(&xs[warp][j4]);
            acc += f.x * ws[(j4 + 0) * 32 + lane];
            acc += f.y * ws[(j4 + 1) * 32 + lane];
            acc += f.z * ws[(j4 + 2) * 32 + lane];
            acc += f.w * ws[(j4 + 3) * 32 + lane];
        }
        g_f_pc[(size_t)p * 32 + lane] = fmaxf(acc * sv[lane] + bv[lane], 0.f);
        __syncwarp();
    }
}

// ---------------------------------------------------------------------------
// Kernel 2: rel_pos + lfa1(mma) + gather + logits(mma) + pool + f_agg ;
//           lfa2(mma) -> g_fx2 (fp16)
// per-warp: fs 1088 + lg 1056 (rp [16][20] aliases lg) + agg 64 = 2208
// ---------------------------------------------------------------------------
#define K2_WARP_FLOATS 2208
#define K2_BASE_FLOATS 10624
#define K2_WARPS 18
#define K2_SMEM_BYTES ((K2_BASE_FLOATS + K2_WARPS * K2_WARP_FLOATS) * 4)

__global__ __launch_bounds__(576) void kern_att1(
    const float* __restrict__ xyz, const int* __restrict__ neigh,
    const float* __restrict__ wlfa1, const float* __restrict__ slfa1, const float* __restrict__ blfa1,
    const float* __restrict__ wfc1,
    const float* __restrict__ wam1, const float* __restrict__ sam1, const float* __restrict__ bam1,
    const float* __restrict__ wlfa2, const float* __restrict__ slfa2, const float* __restrict__ blfa2)
{
    extern __shared__ float sm[];
    float* s_wfc  = sm;            // 4608  wfc1 [64][72] tf32
    float* s_wam  = sm + 4608;     // 2048  wam1*sam1 [64][32] fp32
    float* s_wl1h = sm + 6656;     // 640   (wlfa1*slfa1) hi [16][40], rows 10-15 zero
    float* s_wl1l = sm + 7296;     // 640   lo
    float* s_wl2h = sm + 7936;     // 1280  (wlfa2*slfa2) hi [32][40]
    float* s_wl2l = sm + 9216;     // 1280  lo
    float* s_vec  = sm + 10496;    // 128: blfa1[32], blfa2[32], bam1[32]
    float* s_wrp  = sm + K2_BASE_FLOATS;

    for (int i = threadIdx.x; i < 4096; i += blockDim.x) {
        int j = i >> 6, c = i & 63;
        s_wfc[j * WF_PAD + c] = to_tf32(wfc1[i]);
    }
    for (int i = threadIdx.x; i < 2048; i += blockDim.x)
        s_wam[i] = wam1[i] * sam1[i & 31];
    for (int i = threadIdx.x; i < 640; i += blockDim.x) {
        int j = i / WB_PAD, c = i % WB_PAD;
        float v = (j < 10 && c < 32) ? wlfa1[j * 32 + c] * slfa1[c] : 0.f;
        float h = to_tf32(v);
        s_wl1h[i] = h;
        s_wl1l[i] = to_tf32(v - h);
    }
    for (int i = threadIdx.x; i < 1280; i += blockDim.x) {
        int j = i / WB_PAD, c = i % WB_PAD;
        float v = (c < 32) ? wlfa2[j * 32 + c] * slfa2[c] : 0.f;
        float h = to_tf32(v);
        s_wl2h[i] = h;
        s_wl2l[i] = to_tf32(v - h);
    }
    if (threadIdx.x < 32) {
        int l = threadIdx.x;
        s_vec[l]      = blfa1[l];
        s_vec[32 + l] = blfa2[l];
        s_vec[64 + l] = bam1[l];
    }
    __syncthreads();

    const int lane = threadIdx.x & 31;
    const int warp = threadIdx.x >> 5;
    const int gid = lane >> 2, tig = lane & 3;
    float* fs_s  = s_wrp + warp * K2_WARP_FLOATS;   // [16][68]
    float* lg_s  = fs_s + 1088;                     // [16][66]
    float* rp_s  = lg_s;                            // [16][20] aliases lg (dead before logits)
    float* agg_s = fs_s + 2144;                     // [64]

    const int nwarps = (gridDim.x * blockDim.x) >> 5;
    int gw = (blockIdx.x * blockDim.x + threadIdx.x) >> 5;

    for (int p = gw; p < P_TOTAL; p += nwarps) {
        const int b = p / NPTS;
        const size_t bbase = (size_t)b * NPTS;

        int myidx = 0;
        if (lane < KNN) myidx = neigh[(size_t)p * KNN + lane];

        // issue gather loads early (hide latency under rel_pos + lfa1)
        float gv[KNN];
        #pragma unroll
        for (int k = 0; k < KNN; k++) {
            int nb = __shfl_sync(0xffffffffu, myidx, k);
            gv[k] = g_f_pc[(bbase + (size_t)nb) * 32 + lane];
        }

        const float cx = xyz[(size_t)p * 3 + 0];
        const float cy = xyz[(size_t)p * 3 + 1];
        const float cz = xyz[(size_t)p * 3 + 2];

        if (lane < KNN) {
            size_t nb = bbase + (size_t)myidx;
            float nx = xyz[nb * 3 + 0], ny = xyz[nb * 3 + 1], nz = xyz[nb * 3 + 2];
            float rx = cx - nx, ry = cy - ny, rz = cz - nz;
            float d = sqrtf(rx * rx + ry * ry + rz * rz);
            float* rp = rp_s + lane * RP_PAD;
            rp[0] = d;  rp[1] = rx; rp[2] = ry; rp[3] = rz;
            rp[4] = cx; rp[5] = cy; rp[6] = cz;
            rp[7] = nx; rp[8] = ny; rp[9] = nz;
            // zero K-pad cols (rp aliases lg, so re-zero every iteration)
            rp[10] = 0.f; rp[11] = 0.f; rp[12] = 0.f;
            rp[13] = 0.f; rp[14] = 0.f; rp[15] = 0.f;
        }
        __syncwarp();

        // ---- lfa1 via 3xTF32 mma: f_xyz[16][32] -> fs cols 32..63
        {
            float acc[4][4];
            #pragma unroll
            for (int n = 0; n < 4; n++) { acc[n][0]=0.f; acc[n][1]=0.f; acc[n][2]=0.f; acc[n][3]=0.f; }
            #pragma unroll
            for (int q = 0; q < 2; q++) {
                unsigned ah0, al0, ah1, al1, ah2, al2, ah3, al3;
                tf32_split(rp_s[gid * RP_PAD + q * 8 + tig],           ah0, al0);
                tf32_split(rp_s[(gid + 8) * RP_PAD + q * 8 + tig],     ah1, al1);
                tf32_split(rp_s[gid * RP_PAD + q * 8 + tig + 4],       ah2, al2);
                tf32_split(rp_s[(gid + 8) * RP_PAD + q * 8 + tig + 4], ah3, al3);
                const float* ph0 = s_wl1h + (q * 8 + tig) * WB_PAD + gid;
                const float* ph1 = s_wl1h + (q * 8 + tig + 4) * WB_PAD + gid;
                const float* pl0 = s_wl1l + (q * 8 + tig) * WB_PAD + gid;
                const float* pl1 = s_wl1l + (q * 8 + tig + 4) * WB_PAD + gid;
                #pragma unroll
                for (int n = 0; n < 4; n++) {
                    unsigned bh0 = __float_as_uint(ph0[n * 8]);
                    unsigned bh1 = __float_as_uint(ph1[n * 8]);
                    unsigned bl0 = __float_as_uint(pl0[n * 8]);
                    unsigned bl1 = __float_as_uint(pl1[n * 8]);
                    mma_tf32(acc[n], ah0, ah1, ah2, ah3, bh0, bh1);
                    mma_tf32(acc[n], al0, al1, al2, al3, bh0, bh1);
                    mma_tf32(acc[n], ah0, ah1, ah2, ah3, bl0, bl1);
                }
            }
            #pragma unroll
            for (int n = 0; n < 4; n++) {
                int c0 = n * 8 + 2 * tig;
                float b0 = s_vec[c0], b1 = s_vec[c0 + 1];
                *(float2*)(fs_s + gid * FS_PAD + 32 + c0) =
                    make_float2(fmaxf(acc[n][0] + b0, 0.f), fmaxf(acc[n][1] + b1, 0.f));
                *(float2*)(fs_s + (gid + 8) * FS_PAD + 32 + c0) =
                    make_float2(fmaxf(acc[n][2] + b0, 0.f), fmaxf(acc[n][3] + b1, 0.f));
            }
        }

        // gathered f_pc -> fs cols 0..31
        #pragma unroll
        for (int k = 0; k < KNN; k++) fs_s[k * FS_PAD + lane] = gv[k];
        __syncwarp();

        // ---- logits + softmax pool (lg overwrites rp -- rp is dead here)
        logits_mma(fs_s, lg_s, s_wfc, lane);
        __syncwarp();
        agg_s[lane]      = att_pool(lg_s, fs_s, lane);
        agg_s[32 + lane] = att_pool(lg_s, fs_s, 32 + lane);
        __syncwarp();

        // ---- f_agg = ReLU(agg @ (wam1*s) + b)   (scalar, 64 FFMA)
        {
            float acc = 0.f;
            #pragma unroll
            for (int d4 = 0; d4 < 64; d4 += 4) {
                float4 a = *(const float4*)(agg_s + d4);
                acc += a.x * s_wam[(d4 + 0) * 32 + lane];
                acc += a.y * s_wam[(d4 + 1) * 32 + lane];
                acc += a.z * s_wam[(d4 + 2) * 32 + lane];
                acc += a.w * s_wam[(d4 + 3) * 32 + lane];
            }
            g_f_agg[(size_t)p * 32 + lane] = fmaxf(acc + s_vec[64 + lane], 0.f);
        }

        // ---- lfa2 via 3xTF32 mma: f_xyz2[16][32] -> gmem fp16
        {
            float acc[4][4];
            #pragma unroll
            for (int n = 0; n < 4; n++) { acc[n][0]=0.f; acc[n][1]=0.f; acc[n][2]=0.f; acc[n][3]=0.f; }
            #pragma unroll
            for (int q = 0; q < 4; q++) {
                unsigned ah0, al0, ah1, al1, ah2, al2, ah3, al3;
                tf32_split(fs_s[gid * FS_PAD + 32 + q * 8 + tig],           ah0, al0);
                tf32_split(fs_s[(gid + 8) * FS_PAD + 32 + q * 8 + tig],     ah1, al1);
                tf32_split(fs_s[gid * FS_PAD + 32 + q * 8 + tig + 4],       ah2, al2);
                tf32_split(fs_s[(gid + 8) * FS_PAD + 32 + q * 8 + tig + 4], ah3, al3);
                const float* ph0 = s_wl2h + (q * 8 + tig) * WB_PAD + gid;
                const float* ph1 = s_wl2h + (q * 8 + tig + 4) * WB_PAD + gid;
                const float* pl0 = s_wl2l + (q * 8 + tig) * WB_PAD + gid;
                const float* pl1 = s_wl2l + (q * 8 + tig + 4) * WB_PAD + gid;
                #pragma unroll
                for (int n = 0; n < 4; n++) {
                    unsigned bh0 = __float_as_uint(ph0[n * 8]);
                    unsigned bh1 = __float_as_uint(ph1[n * 8]);
                    unsigned bl0 = __float_as_uint(pl0[n * 8]);
                    unsigned bl1 = __float_as_uint(pl1[n * 8]);
                    mma_tf32(acc[n], ah0, ah1, ah2, ah3, bh0, bh1);
                    mma_tf32(acc[n], al0, al1, al2, al3, bh0, bh1);
                    mma_tf32(acc[n], ah0, ah1, ah2, ah3, bl0, bl1);
                }
            }
            #pragma unroll
            for (int n = 0; n < 4; n++) {
                int c0 = n * 8 + 2 * tig;
                float b0 = s_vec[32 + c0], b1 = s_vec[32 + c0 + 1];
                g_fx2[((size_t)p * KNN + gid) * 16 + (c0 >> 1)] =
                    __floats2half2_rn(fmaxf(acc[n][0] + b0, 0.f), fmaxf(acc[n][1] + b1, 0.f));
                g_fx2[((size_t)p * KNN + gid + 8) * 16 + (c0 >> 1)] =
                    __floats2half2_rn(fmaxf(acc[n][2] + b0, 0.f), fmaxf(acc[n][3] + b1, 0.f));
            }
        }
        __syncwarp();
    }
}

// ---------------------------------------------------------------------------
// Kernel 3: gather(f_agg) + f_xyz2(fp16) + logits(mma) + pool -> g_agg2
// ---------------------------------------------------------------------------
#define K3_WARP_FLOATS 2144   // fs 1088 + lg 1056
#define K3_BASE_FLOATS 4608
#define K3_WARPS 20
#define K3_SMEM_BYTES ((K3_BASE_FLOATS + K3_WARPS * K3_WARP_FLOATS) * 4)

__global__ __launch_bounds__(640) void kern_att2(
    const int* __restrict__ neigh,
    const float* __restrict__ wfc2)
{
    extern __shared__ float sm[];
    float* s_wfc = sm;             // 4608 wfc2 [64][72] tf32
    float* s_wrp = sm + K3_BASE_FLOATS;

    for (int i = threadIdx.x; i < 4096; i += blockDim.x) {
        int j = i >> 6, c = i & 63;
        s_wfc[j * WF_PAD + c] = to_tf32(wfc2[i]);
    }
    __syncthreads();

    const int lane = threadIdx.x & 31;
    const int warp = threadIdx.x >> 5;
    float* fs_s = s_wrp + warp * K3_WARP_FLOATS;   // [16][68]
    float* lg_s = fs_s + 1088;                     // [16][66]

    const int kk = lane >> 4;      // 0/1: which of two k-rows this lane handles
    const int jj = lane & 15;      // half2 index within row

    const int nwarps = (gridDim.x * blockDim.x) >> 5;
    int gw = (blockIdx.x * blockDim.x + threadIdx.x) >> 5;

    for (int p = gw; p < P_TOTAL; p += nwarps) {
        const int b = p / NPTS;
        const size_t bbase = (size_t)b * NPTS;

        int myidx = 0;
        if (lane < KNN) myidx = neigh[(size_t)p * KNN + lane];

        #pragma unroll
        for (int k = 0; k < KNN; k++) {
            int nb = __shfl_sync(0xffffffffu, myidx, k);
            fs_s[k * FS_PAD + lane] = g_f_agg[(bbase + (size_t)nb) * 32 + lane];
        }
        // fp16 f_xyz2: 2 rows per pass, coalesced half2 loads
        const __half2* src = g_fx2 + (size_t)p * KNN * 16;
        #pragma unroll
        for (int k = 0; k < KNN; k += 2) {
            float2 f = __half22float2(src[(k + kk) * 16 + jj]);
            *(float2*)(fs_s + (k + kk) * FS_PAD + 32 + 2 * jj) = f;
        }
        __syncwarp();

        logits_mma(fs_s, lg_s, s_wfc, lane);
        __syncwarp();

        g_agg2[(size_t)p * 64 + lane]      = att_pool(lg_s, fs_s, lane);
        g_agg2[(size_t)p * 64 + 32 + lane] = att_pool(lg_s, fs_s, 32 + lane);
        __syncwarp();
    }
}

// ---------------------------------------------------------------------------
// Kernel 4: 16-point tiles: pc2 = relu(agg2@w1+b1) written into a combined
//           [pc2;feat] K=96 A-tile; out = leaky(A @ w23 + b2). 3xTF32.
// ---------------------------------------------------------------------------
#define OUT_WARPS 12
#define OUT_BASE_FLOATS 35520  // w1 2*4608 + w23 2*13056 + b1 64 + b2 128
#define OUT_WARP_FLOATS 1600   // A [16][100]
#define OUT_SMEM_BYTES ((OUT_BASE_FLOATS + OUT_WARPS * OUT_WARP_FLOATS) * 4)

__global__ __launch_bounds__(384) void kern_out(
    const float* __restrict__ feature,
    const float* __restrict__ wam2, const float* __restrict__ sam2, const float* __restrict__ bam2,
    const float* __restrict__ wmlp2, const float* __restrict__ smlp2, const float* __restrict__ bmlp2,
    const float* __restrict__ wsc, const float* __restrict__ ssc, const float* __restrict__ bsc,
    float* __restrict__ out)
{
    extern __shared__ float sm[];
    float* w1h = sm;            // [64][72]
    float* w1l = sm + 4608;
    float* w2h = sm + 9216;     // [96][136]: rows 0..63 = wmlp2', rows 64..95 = wsc'
    float* w2l = sm + 22272;    // 9216 + 13056
    float* b1  = sm + 35328;    // [64]
    float* b2  = sm + 35392;    // [128]
    float* wrp = sm + OUT_BASE_FLOATS;

    for (int i = threadIdx.x; i < 4096; i += blockDim.x) {
        int j = i >> 6, c = i & 63;
        float v = wam2[i] * sam2[c];
        float h = to_tf32(v);
        w1h[j * WF_PAD + c] = h;
        w1l[j * WF_PAD + c] = to_tf32(v - h);
    }
    for (int i = threadIdx.x; i < 8192; i += blockDim.x) {
        int j = i >> 7, c = i & 127;
        float v = wmlp2[i] * smlp2[c];
        float h = to_tf32(v);
        w2h[j * WO_PAD + c] = h;
        w2l[j * WO_PAD + c] = to_tf32(v - h);
    }
    for (int i = threadIdx.x; i < 4096; i += blockDim.x) {
        int j = i >> 7, c = i & 127;
        float v = wsc[i] * ssc[c];
        float h = to_tf32(v);
        w2h[(64 + j) * WO_PAD + c] = h;
        w2l[(64 + j) * WO_PAD + c] = to_tf32(v - h);
    }
    if (threadIdx.x < 64)  b1[threadIdx.x] = bam2[threadIdx.x];
    if (threadIdx.x < 128) b2[threadIdx.x] = bmlp2[threadIdx.x] + bsc[threadIdx.x];
    __syncthreads();

    const int lane = threadIdx.x & 31;
    const int warp = threadIdx.x >> 5;
    const int gid = lane >> 2, tig = lane & 3;
    float* A1 = wrp + warp * OUT_WARP_FLOATS;  // [16][100]: cols 0-63 agg2->pc2, 64-95 feat

    const int nwarps = (gridDim.x * blockDim.x) >> 5;
    int gw = (blockIdx.x * blockDim.x + threadIdx.x) >> 5;
    const int ntiles = P_TOTAL / 16;

    for (int t = gw; t < ntiles; t += nwarps) {
        const int p0 = t * 16;

        #pragma unroll
        for (int r = 0; r < 16; r++) {
            A1[r * OA_PAD + lane]      = g_agg2[(size_t)(p0 + r) * 64 + lane];
            A1[r * OA_PAD + 32 + lane] = g_agg2[(size_t)(p0 + r) * 64 + 32 + lane];
            A1[r * OA_PAD + 64 + lane] = feature[(size_t)(p0 + r) * 32 + lane];
        }
        __syncwarp();

        // GEMM1: pc2 = relu(agg @ w1 + b1), written back into A cols 0..63
        {
            float acc[8][4];
            #pragma unroll
            for (int n = 0; n < 8; n++) { acc[n][0]=0.f; acc[n][1]=0.f; acc[n][2]=0.f; acc[n][3]=0.f; }
            #pragma unroll
            for (int q = 0; q < 8; q++) {
                unsigned ah0, al0, ah1, al1, ah2, al2, ah3, al3;
                tf32_split(A1[gid * OA_PAD + q * 8 + tig],           ah0, al0);
                tf32_split(A1[(gid + 8) * OA_PAD + q * 8 + tig],     ah1, al1);
                tf32_split(A1[gid * OA_PAD + q * 8 + tig + 4],       ah2, al2);
                tf32_split(A1[(gid + 8) * OA_PAD + q * 8 + tig + 4], ah3, al3);
                const float* ph0 = w1h + (q * 8 + tig) * WF_PAD + gid;
                const float* ph1 = w1h + (q * 8 + tig + 4) * WF_PAD + gid;
                const float* pl0 = w1l + (q * 8 + tig) * WF_PAD + gid;
                const float* pl1 = w1l + (q * 8 + tig + 4) * WF_PAD + gid;
                #pragma unroll
                for (int n = 0; n < 8; n++) {
                    unsigned bh0 = __float_as_uint(ph0[n * 8]);
                    unsigned bh1 = __float_as_uint(ph1[n * 8]);
                    unsigned bl0 = __float_as_uint(pl0[n * 8]);
                    unsigned bl1 = __float_as_uint(pl1[n * 8]);
                    mma_tf32(acc[n], ah0, ah1, ah2, ah3, bh0, bh1);
                    mma_tf32(acc[n], al0, al1, al2, al3, bh0, bh1);
                    mma_tf32(acc[n], ah0, ah1, ah2, ah3, bl0, bl1);
                }
            }
            __syncwarp();
            #pragma unroll
            for (int n = 0; n < 8; n++) {
                int c0 = n * 8 + 2 * tig;
                float bb0 = b1[c0], bb1 = b1[c0 + 1];
                *(float2*)(A1 + gid * OA_PAD + c0) =
                    make_float2(fmaxf(acc[n][0] + bb0, 0.f), fmaxf(acc[n][1] + bb1, 0.f));
                *(float2*)(A1 + (gid + 8) * OA_PAD + c0) =
                    make_float2(fmaxf(acc[n][2] + bb0, 0.f), fmaxf(acc[n][3] + bb1, 0.f));
            }
        }
        __syncwarp();

        // GEMM2: out = leaky(A[16][96] @ w23 + b2), n in two halves of 64
        #pragma unroll
        for (int h = 0; h < 2; h++) {
            float acc[8][4];
            #pragma unroll
            for (int n = 0; n < 8; n++) { acc[n][0]=0.f; acc[n][1]=0.f; acc[n][2]=0.f; acc[n][3]=0.f; }
            #pragma unroll
            for (int q = 0; q < 12; q++) {
                unsigned ah0, al0, ah1, al1, ah2, al2, ah3, al3;
                tf32_split(A1[gid * OA_PAD + q * 8 + tig],           ah0, al0);
                tf32_split(A1[(gid + 8) * OA_PAD + q * 8 + tig],     ah1, al1);
                tf32_split(A1[gid * OA_PAD + q * 8 + tig + 4],       ah2, al2);
                tf32_split(A1[(gid + 8) * OA_PAD + q * 8 + tig + 4], ah3, al3);
                const float* ph0 = w2h + (q * 8 + tig) * WO_PAD + h * 64 + gid;
                const float* ph1 = w2h + (q * 8 + tig + 4) * WO_PAD + h * 64 + gid;
                const float* pl0 = w2l + (q * 8 + tig) * WO_PAD + h * 64 + gid;
                const float* pl1 = w2l + (q * 8 + tig + 4) * WO_PAD + h * 64 + gid;
                #pragma unroll
                for (int n = 0; n < 8; n++) {
                    unsigned bh0 = __float_as_uint(ph0[n * 8]);
                    unsigned bh1 = __float_as_uint(ph1[n * 8]);
                    unsigned bl0 = __float_as_uint(pl0[n * 8]);
                    unsigned bl1 = __float_as_uint(pl1[n * 8]);
                    mma_tf32(acc[n], ah0, ah1, ah2, ah3, bh0, bh1);
                    mma_tf32(acc[n], al0, al1, al2, al3, bh0, bh1);
                    mma_tf32(acc[n], ah0, ah1, ah2, ah3, bl0, bl1);
                }
            }
            #pragma unroll
            for (int n = 0; n < 8; n++) {
                int c0 = h * 64 + n * 8 + 2 * tig;
                float bb0 = b2[c0], bb1 = b2[c0 + 1];
                float v0 = acc[n][0] + bb0; v0 = (v0 < 0.f) ? 0.2f * v0 : v0;
                float v1 = acc[n][1] + bb1; v1 = (v1 < 0.f) ? 0.2f * v1 : v1;
                float v2 = acc[n][2] + bb0; v2 = (v2 < 0.f) ? 0.2f * v2 : v2;
                float v3 = acc[n][3] + bb1; v3 = (v3 < 0.f) ? 0.2f * v3 : v3;
                *(float2*)(&out[(size_t)(p0 + gid) * 128 + c0])     = make_float2(v0, v1);
                *(float2*)(&out[(size_t)(p0 + gid + 8) * 128 + c0]) = make_float2(v2, v3);
            }
        }
        __syncwarp();
    }
}

// ---------------------------------------------------------------------------
extern "C" void kernel_launch(void* const* d_in, const int* in_sizes, int n_in,
                              void* d_out, int out_size)
{
    const float* feature = (const float*)d_in[0];
    const float* xyz     = (const float*)d_in[1];
    const int*   neigh   = (const int*)  d_in[2];
    const float* w_mlp1  = (const float*)d_in[3];
    const float* s_mlp1  = (const float*)d_in[4];
    const float* b_mlp1  = (const float*)d_in[5];
    const float* w_lfa1  = (const float*)d_in[6];
    const float* s_lfa1  = (const float*)d_in[7];
    const float* b_lfa1  = (const float*)d_in[8];
    const float* w_fc1   = (const float*)d_in[9];
    const float* w_am1   = (const float*)d_in[10];
    const float* s_am1   = (const float*)d_in[11];
    const float* b_am1   = (const float*)d_in[12];
    const float* w_lfa2  = (const float*)d_in[13];
    const float* s_lfa2  = (const float*)d_in[14];
    const float* b_lfa2  = (const float*)d_in[15];
    const float* w_fc2   = (const float*)d_in[16];
    const float* w_am2   = (const float*)d_in[17];
    const float* s_am2   = (const float*)d_in[18];
    const float* b_am2   = (const float*)d_in[19];
    const float* w_mlp2  = (const float*)d_in[20];
    const float* s_mlp2  = (const float*)d_in[21];
    const float* b_mlp2  = (const float*)d_in[22];
    const float* w_sc    = (const float*)d_in[23];
    const float* s_sc    = (const float*)d_in[24];
    const float* b_sc    = (const float*)d_in[25];
    float* out = (float*)d_out;

    cudaFuncSetAttribute(kern_att1, cudaFuncAttributeMaxDynamicSharedMemorySize, K2_SMEM_BYTES);
    cudaFuncSetAttribute(kern_att2, cudaFuncAttributeMaxDynamicSharedMemorySize, K3_SMEM_BYTES);
    cudaFuncSetAttribute(kern_out,  cudaFuncAttributeMaxDynamicSharedMemorySize, OUT_SMEM_BYTES);

    kern_mlp1<<<2048, 256>>>(feature, w_mlp1, s_mlp1, b_mlp1);

    kern_att1<<<148, 576, K2_SMEM_BYTES>>>(
        xyz, neigh,
        w_lfa1, s_lfa1, b_lfa1,
        w_fc1,
        w_am1, s_am1, b_am1,
        w_lfa2, s_lfa2, b_lfa2);

    kern_att2<<<148, 640, K3_SMEM_BYTES>>>(neigh, w_fc2);

    kern_out<<<148, 384, OUT_SMEM_BYTES>>>(
        feature,
        w_am2, s_am2, b_am2,
        w_mlp2, s_mlp2, b_mlp2,
        w_sc, s_sc, b_sc,
        out);
}

// round 7
// speedup vs baseline: 2.5272x; 1.0539x over previous
#include <cuda_runtime.h>
#include <cuda_fp16.h>
#include <math.h>

#define BATCH 4
#define NPTS  40960
#define KNN   16
#define P_TOTAL (BATCH * NPTS)   // 163840

#define FS_PAD 68    // fs tile row stride (floats): conflict-free A-frag loads
#define LG_PAD 66    // logits tile row stride: conflict-free column reads
#define P2F    68    // float2 B-tile stride (units of float2): 4 mod 16
#define P4_32  34    // float4 B-tile stride, 32 cols: 2 mod 8
#define P4_64  66    // float4 B-tile stride, 64 cols: 2 mod 8
#define P4_128 130   // float4 B-tile stride, 128 cols: 2 mod 8
#define RP_PAD 20    // relpos tile stride
#define OA_PAD 100   // kern_out A tile stride (4 mod 32)

// Scratch (device globals: no allocation allowed in kernel_launch)
__device__ float   g_f_pc [P_TOTAL * 32];                    // 21 MB
__device__ float   g_f_agg[P_TOTAL * 32];                    // 21 MB
__device__ float   g_agg2 [(size_t)P_TOTAL * 64];            // 42 MB
__device__ __half2 g_fx2  [(size_t)P_TOTAL * KNN * 16];      // 168 MB

__device__ __forceinline__ float to_tf32(float x) {
    float r;
    asm("cvt.rna.tf32.f32 %0, %1;" : "=f"(r) : "f"(x));
    return r;
}
__device__ __forceinline__ void tf32_split(float x, unsigned& h, unsigned& l) {
    float hf = to_tf32(x);
    h = __float_as_uint(hf);
    l = __float_as_uint(to_tf32(x - hf));
}

__device__ __forceinline__ void mma_tf32(float* c,
                                         unsigned a0, unsigned a1, unsigned a2, unsigned a3,
                                         unsigned b0, unsigned b1) {
    asm("mma.sync.aligned.m16n8k8.row.col.f32.tf32.tf32.f32 "
        "{%0,%1,%2,%3}, {%4,%5,%6,%7}, {%8,%9}, {%0,%1,%2,%3};"
        : "+f"(c[0]), "+f"(c[1]), "+f"(c[2]), "+f"(c[3])
        : "r"(a0), "r"(a1), "r"(a2), "r"(a3), "r"(b0), "r"(b1));
}

// 3xTF32 mma step with packed float4 B = (bh0,bh1,bl0,bl1)
__device__ __forceinline__ void mma3_pk(float* acc, float4 b,
                                        unsigned ah0, unsigned ah1, unsigned ah2, unsigned ah3,
                                        unsigned al0, unsigned al1, unsigned al2, unsigned al3) {
    unsigned bh0 = __float_as_uint(b.x), bh1 = __float_as_uint(b.y);
    unsigned bl0 = __float_as_uint(b.z), bl1 = __float_as_uint(b.w);
    mma_tf32(acc, ah0, ah1, ah2, ah3, bh0, bh1);
    mma_tf32(acc, al0, al1, al2, al3, bh0, bh1);
    mma_tf32(acc, ah0, ah1, ah2, ah3, bl0, bl1);
}

// logits[16][64] = fs[16][64] @ wfc[64][64], wfc packed float2 rows (q*4+tig)
__device__ __forceinline__ void logits_mma(const float* __restrict__ fs_s,
                                           float* __restrict__ lg_s,
                                           const float2* __restrict__ wfcp, int lane)
{
    const int gid = lane >> 2;
    const int tig = lane & 3;
    float acc[8][4];
    #pragma unroll
    for (int n = 0; n < 8; n++) { acc[n][0]=0.f; acc[n][1]=0.f; acc[n][2]=0.f; acc[n][3]=0.f; }
    #pragma unroll
    for (int q = 0; q < 8; q++) {
        const float* fr0 = fs_s + gid * FS_PAD + q * 8 + tig;
        const float* fr1 = fs_s + (gid + 8) * FS_PAD + q * 8 + tig;
        unsigned a0 = __float_as_uint(to_tf32(fr0[0]));
        unsigned a1 = __float_as_uint(to_tf32(fr1[0]));
        unsigned a2 = __float_as_uint(to_tf32(fr0[4]));
        unsigned a3 = __float_as_uint(to_tf32(fr1[4]));
        const float2* br = wfcp + (q * 4 + tig) * P2F + gid;
        #pragma unroll
        for (int n = 0; n < 8; n++) {
            float2 b = br[8 * n];
            mma_tf32(acc[n], a0, a1, a2, a3,
                     __float_as_uint(b.x), __float_as_uint(b.y));
        }
    }
    #pragma unroll
    for (int n = 0; n < 8; n++) {
        *(float2*)(lg_s + gid * LG_PAD + n * 8 + 2 * tig)       = make_float2(acc[n][0], acc[n][1]);
        *(float2*)(lg_s + (gid + 8) * LG_PAD + n * 8 + 2 * tig) = make_float2(acc[n][2], acc[n][3]);
    }
}

// softmax over K + pool, fs values from smem (channel ch)
__device__ __forceinline__ float att_pool(const float* __restrict__ lg_s,
                                          const float* __restrict__ fs_s, int ch)
{
    float l[KNN];
    float m = -1e30f;
    #pragma unroll
    for (int k = 0; k < KNN; k++) { l[k] = lg_s[k * LG_PAD + ch]; m = fmaxf(m, l[k]); }
    float s = 0.f, a = 0.f;
    #pragma unroll
    for (int k = 0; k < KNN; k++) {
        float e = __expf(l[k] - m);
        s += e;
        a += e * fs_s[k * FS_PAD + ch];
    }
    return __fdividef(a, s);
}

// softmax over K + pool, fs values from registers
__device__ __forceinline__ float att_pool_reg(const float* __restrict__ lg_s,
                                              const float* __restrict__ vals, int ch)
{
    float l[KNN];
    float m = -1e30f;
    #pragma unroll
    for (int k = 0; k < KNN; k++) { l[k] = lg_s[k * LG_PAD + ch]; m = fmaxf(m, l[k]); }
    float s = 0.f, a = 0.f;
    #pragma unroll
    for (int k = 0; k < KNN; k++) {
        float e = __expf(l[k] - m);
        s += e;
        a += e * vals[k];
    }
    return __fdividef(a, s);
}

// ---------------------------------------------------------------------------
// Kernel 1: f_pc = ReLU((feature @ w_mlp1) * s + b)
// ---------------------------------------------------------------------------
__global__ __launch_bounds__(256) void kern_mlp1(
    const float* __restrict__ feature,
    const float* __restrict__ w, const float* __restrict__ s, const float* __restrict__ b)
{
    __shared__ float ws[1024];
    __shared__ float sv[32], bv[32];
    __shared__ float xs[8][32];

    for (int i = threadIdx.x; i < 1024; i += blockDim.x) ws[i] = w[i];
    if (threadIdx.x < 32) { sv[threadIdx.x] = s[threadIdx.x]; bv[threadIdx.x] = b[threadIdx.x]; }
    __syncthreads();

    const int lane = threadIdx.x & 31;
    const int warp = threadIdx.x >> 5;
    const int nwarps = (gridDim.x * blockDim.x) >> 5;
    int gw = (blockIdx.x * blockDim.x + threadIdx.x) >> 5;

    for (int p = gw; p < P_TOTAL; p += nwarps) {
        xs[warp][lane] = feature[(size_t)p * 32 + lane];
        __syncwarp();
        float acc = 0.f;
        #pragma unroll
        for (int j4 = 0; j4 < 32; j4 += 4) {
            float4 f = *(const float4*)(&xs[warp][j4]);
            acc += f.x * ws[(j4 + 0) * 32 + lane];
            acc += f.y * ws[(j4 + 1) * 32 + lane];
            acc += f.z * ws[(j4 + 2) * 32 + lane];
            acc += f.w * ws[(j4 + 3) * 32 + lane];
        }
        g_f_pc[(size_t)p * 32 + lane] = fmaxf(acc * sv[lane] + bv[lane], 0.f);
        __syncwarp();
    }
}

// ---------------------------------------------------------------------------
// Kernel 2: rel_pos + lfa1(mma) + gather + logits(mma) + pool + f_agg ;
//           lfa2(mma) -> g_fx2 (fp16).  All B tiles vector-packed.
// ---------------------------------------------------------------------------
#define K2_WARP_FLOATS 2208   // fs 1088 + lg 1056 (rp aliases lg) + agg 64
#define K2_BASE_FLOATS 9792
#define K2_WARPS 18
#define K2_SMEM_BYTES ((K2_BASE_FLOATS + K2_WARPS * K2_WARP_FLOATS) * 4)

__global__ __launch_bounds__(576) void kern_att1(
    const float* __restrict__ xyz, const int* __restrict__ neigh,
    const float* __restrict__ wlfa1, const float* __restrict__ slfa1, const float* __restrict__ blfa1,
    const float* __restrict__ wfc1,
    const float* __restrict__ wam1, const float* __restrict__ sam1, const float* __restrict__ bam1,
    const float* __restrict__ wlfa2, const float* __restrict__ slfa2, const float* __restrict__ blfa2)
{
    extern __shared__ float sm[];
    float2* s_wfcp = (float2*)sm;             // [32][68] float2 = 4352 floats @0
    float2* s_wamp = (float2*)(sm + 4352);    // [32][32] float2 = 2048 floats
    float4* s_wl1p = (float4*)(sm + 6400);    // [8][34] float4 = 1088 floats
    float4* s_wl2p = (float4*)(sm + 7488);    // [16][34] float4 = 2176 floats
    float*  s_vec  = sm + 9664;               // 128: blfa1, blfa2, bam1
    float*  s_wrp  = sm + K2_BASE_FLOATS;

    for (int i = threadIdx.x; i < 2048; i += blockDim.x) {
        int r = i >> 6, c = i & 63;
        int k0 = (r >> 2) * 8 + (r & 3), k1 = k0 + 4;
        s_wfcp[r * P2F + c] = make_float2(to_tf32(wfc1[k0 * 64 + c]), to_tf32(wfc1[k1 * 64 + c]));
    }
    for (int i = threadIdx.x; i < 1024; i += blockDim.x) {
        int r = i >> 5, c = i & 31;
        s_wamp[r * 32 + c] = make_float2(wam1[(2 * r) * 32 + c] * sam1[c],
                                         wam1[(2 * r + 1) * 32 + c] * sam1[c]);
    }
    for (int i = threadIdx.x; i < 256; i += blockDim.x) {
        int r = i >> 5, c = i & 31;
        int k0 = (r >> 2) * 8 + (r & 3), k1 = k0 + 4;
        float v0 = (k0 < 10) ? wlfa1[k0 * 32 + c] * slfa1[c] : 0.f;
        float v1 = (k1 < 10) ? wlfa1[k1 * 32 + c] * slfa1[c] : 0.f;
        float h0 = to_tf32(v0), h1 = to_tf32(v1);
        s_wl1p[r * P4_32 + c] = make_float4(h0, h1, to_tf32(v0 - h0), to_tf32(v1 - h1));
    }
    for (int i = threadIdx.x; i < 512; i += blockDim.x) {
        int r = i >> 5, c = i & 31;
        int k0 = (r >> 2) * 8 + (r & 3), k1 = k0 + 4;
        float v0 = wlfa2[k0 * 32 + c] * slfa2[c];
        float v1 = wlfa2[k1 * 32 + c] * slfa2[c];
        float h0 = to_tf32(v0), h1 = to_tf32(v1);
        s_wl2p[r * P4_32 + c] = make_float4(h0, h1, to_tf32(v0 - h0), to_tf32(v1 - h1));
    }
    if (threadIdx.x < 32) {
        int l = threadIdx.x;
        s_vec[l]      = blfa1[l];
        s_vec[32 + l] = blfa2[l];
        s_vec[64 + l] = bam1[l];
    }
    __syncthreads();

    const int lane = threadIdx.x & 31;
    const int warp = threadIdx.x >> 5;
    const int gid = lane >> 2, tig = lane & 3;
    float* fs_s  = s_wrp + warp * K2_WARP_FLOATS;   // [16][68]
    float* lg_s  = fs_s + 1088;                     // [16][66]
    float* rp_s  = lg_s;                            // [16][20] aliases lg
    float* agg_s = fs_s + 2144;                     // [64]

    const int nwarps = (gridDim.x * blockDim.x) >> 5;
    int gw = (blockIdx.x * blockDim.x + threadIdx.x) >> 5;

    for (int p = gw; p < P_TOTAL; p += nwarps) {
        const int b = p / NPTS;
        const size_t bbase = (size_t)b * NPTS;

        int myidx = 0;
        if (lane < KNN) myidx = neigh[(size_t)p * KNN + lane];

        // gather loads early
        float gv[KNN];
        #pragma unroll
        for (int k = 0; k < KNN; k++) {
            int nb = __shfl_sync(0xffffffffu, myidx, k);
            gv[k] = g_f_pc[(bbase + (size_t)nb) * 32 + lane];
        }

        const float cx = xyz[(size_t)p * 3 + 0];
        const float cy = xyz[(size_t)p * 3 + 1];
        const float cz = xyz[(size_t)p * 3 + 2];

        if (lane < KNN) {
            size_t nb = bbase + (size_t)myidx;
            float nx = xyz[nb * 3 + 0], ny = xyz[nb * 3 + 1], nz = xyz[nb * 3 + 2];
            float rx = cx - nx, ry = cy - ny, rz = cz - nz;
            float d = sqrtf(rx * rx + ry * ry + rz * rz);
            float* rp = rp_s + lane * RP_PAD;
            rp[0] = d;  rp[1] = rx; rp[2] = ry; rp[3] = rz;
            rp[4] = cx; rp[5] = cy; rp[6] = cz;
            rp[7] = nx; rp[8] = ny; rp[9] = nz;
            rp[10] = 0.f; rp[11] = 0.f; rp[12] = 0.f;
            rp[13] = 0.f; rp[14] = 0.f; rp[15] = 0.f;
        }
        __syncwarp();

        // ---- lfa1 via 3xTF32 mma (packed B): f_xyz -> fs cols 32..63
        {
            float acc[4][4];
            #pragma unroll
            for (int n = 0; n < 4; n++) { acc[n][0]=0.f; acc[n][1]=0.f; acc[n][2]=0.f; acc[n][3]=0.f; }
            #pragma unroll
            for (int q = 0; q < 2; q++) {
                unsigned ah0, al0, ah1, al1, ah2, al2, ah3, al3;
                tf32_split(rp_s[gid * RP_PAD + q * 8 + tig],           ah0, al0);
                tf32_split(rp_s[(gid + 8) * RP_PAD + q * 8 + tig],     ah1, al1);
                tf32_split(rp_s[gid * RP_PAD + q * 8 + tig + 4],       ah2, al2);
                tf32_split(rp_s[(gid + 8) * RP_PAD + q * 8 + tig + 4], ah3, al3);
                const float4* br = s_wl1p + (q * 4 + tig) * P4_32 + gid;
                #pragma unroll
                for (int n = 0; n < 4; n++)
                    mma3_pk(acc[n], br[8 * n], ah0, ah1, ah2, ah3, al0, al1, al2, al3);
            }
            #pragma unroll
            for (int n = 0; n < 4; n++) {
                int c0 = n * 8 + 2 * tig;
                float b0 = s_vec[c0], b1 = s_vec[c0 + 1];
                *(float2*)(fs_s + gid * FS_PAD + 32 + c0) =
                    make_float2(fmaxf(acc[n][0] + b0, 0.f), fmaxf(acc[n][1] + b1, 0.f));
                *(float2*)(fs_s + (gid + 8) * FS_PAD + 32 + c0) =
                    make_float2(fmaxf(acc[n][2] + b0, 0.f), fmaxf(acc[n][3] + b1, 0.f));
            }
        }

        // gathered f_pc -> fs cols 0..31
        #pragma unroll
        for (int k = 0; k < KNN; k++) fs_s[k * FS_PAD + lane] = gv[k];
        __syncwarp();

        // ---- logits + softmax pool
        logits_mma(fs_s, lg_s, s_wfcp, lane);
        __syncwarp();
        agg_s[lane]      = att_pool_reg(lg_s, gv, lane);        // fs[:,lane] == gv
        agg_s[32 + lane] = att_pool(lg_s, fs_s, 32 + lane);
        __syncwarp();

        // ---- f_agg = ReLU(agg @ (wam1*s) + b)  (packed float2 weights)
        {
            float acc = 0.f;
            #pragma unroll
            for (int d2 = 0; d2 < 32; d2 += 2) {
                float4 a = *(const float4*)(agg_s + 2 * d2);
                float2 w0 = s_wamp[d2 * 32 + lane];
                float2 w1 = s_wamp[(d2 + 1) * 32 + lane];
                acc += a.x * w0.x + a.y * w0.y + a.z * w1.x + a.w * w1.y;
            }
            g_f_agg[(size_t)p * 32 + lane] = fmaxf(acc + s_vec[64 + lane], 0.f);
        }

        // ---- lfa2 via 3xTF32 mma (packed B): f_xyz2 -> gmem fp16
        {
            float acc[4][4];
            #pragma unroll
            for (int n = 0; n < 4; n++) { acc[n][0]=0.f; acc[n][1]=0.f; acc[n][2]=0.f; acc[n][3]=0.f; }
            #pragma unroll
            for (int q = 0; q < 4; q++) {
                unsigned ah0, al0, ah1, al1, ah2, al2, ah3, al3;
                tf32_split(fs_s[gid * FS_PAD + 32 + q * 8 + tig],           ah0, al0);
                tf32_split(fs_s[(gid + 8) * FS_PAD + 32 + q * 8 + tig],     ah1, al1);
                tf32_split(fs_s[gid * FS_PAD + 32 + q * 8 + tig + 4],       ah2, al2);
                tf32_split(fs_s[(gid + 8) * FS_PAD + 32 + q * 8 + tig + 4], ah3, al3);
                const float4* br = s_wl2p + (q * 4 + tig) * P4_32 + gid;
                #pragma unroll
                for (int n = 0; n < 4; n++)
                    mma3_pk(acc[n], br[8 * n], ah0, ah1, ah2, ah3, al0, al1, al2, al3);
            }
            #pragma unroll
            for (int n = 0; n < 4; n++) {
                int c0 = n * 8 + 2 * tig;
                float b0 = s_vec[32 + c0], b1 = s_vec[32 + c0 + 1];
                g_fx2[((size_t)p * KNN + gid) * 16 + (c0 >> 1)] =
                    __floats2half2_rn(fmaxf(acc[n][0] + b0, 0.f), fmaxf(acc[n][1] + b1, 0.f));
                g_fx2[((size_t)p * KNN + gid + 8) * 16 + (c0 >> 1)] =
                    __floats2half2_rn(fmaxf(acc[n][2] + b0, 0.f), fmaxf(acc[n][3] + b1, 0.f));
            }
        }
        __syncwarp();
    }
}

// ---------------------------------------------------------------------------
// Kernel 3: gather(f_agg) + f_xyz2(fp16) + logits(mma) + pool -> g_agg2
// ---------------------------------------------------------------------------
#define K3_WARP_FLOATS 2144   // fs 1088 + lg 1056
#define K3_BASE_FLOATS 4352
#define K3_WARPS 20
#define K3_SMEM_BYTES ((K3_BASE_FLOATS + K3_WARPS * K3_WARP_FLOATS) * 4)

__global__ __launch_bounds__(640) void kern_att2(
    const int* __restrict__ neigh,
    const float* __restrict__ wfc2)
{
    extern __shared__ float sm[];
    float2* s_wfcp = (float2*)sm;             // [32][68] float2
    float*  s_wrp  = sm + K3_BASE_FLOATS;

    for (int i = threadIdx.x; i < 2048; i += blockDim.x) {
        int r = i >> 6, c = i & 63;
        int k0 = (r >> 2) * 8 + (r & 3), k1 = k0 + 4;
        s_wfcp[r * P2F + c] = make_float2(to_tf32(wfc2[k0 * 64 + c]), to_tf32(wfc2[k1 * 64 + c]));
    }
    __syncthreads();

    const int lane = threadIdx.x & 31;
    const int warp = threadIdx.x >> 5;
    float* fs_s = s_wrp + warp * K3_WARP_FLOATS;   // [16][68]
    float* lg_s = fs_s + 1088;                     // [16][66]

    const int kk = lane >> 4;
    const int jj = lane & 15;

    const int nwarps = (gridDim.x * blockDim.x) >> 5;
    int gw = (blockIdx.x * blockDim.x + threadIdx.x) >> 5;

    for (int p = gw; p < P_TOTAL; p += nwarps) {
        const int b = p / NPTS;
        const size_t bbase = (size_t)b * NPTS;

        int myidx = 0;
        if (lane < KNN) myidx = neigh[(size_t)p * KNN + lane];

        float gv[KNN];
        #pragma unroll
        for (int k = 0; k < KNN; k++) {
            int nb = __shfl_sync(0xffffffffu, myidx, k);
            gv[k] = g_f_agg[(bbase + (size_t)nb) * 32 + lane];
            fs_s[k * FS_PAD + lane] = gv[k];
        }
        const __half2* src = g_fx2 + (size_t)p * KNN * 16;
        #pragma unroll
        for (int k = 0; k < KNN; k += 2) {
            float2 f = __half22float2(src[(k + kk) * 16 + jj]);
            *(float2*)(fs_s + (k + kk) * FS_PAD + 32 + 2 * jj) = f;
        }
        __syncwarp();

        logits_mma(fs_s, lg_s, s_wfcp, lane);
        __syncwarp();

        g_agg2[(size_t)p * 64 + lane]      = att_pool_reg(lg_s, gv, lane);
        g_agg2[(size_t)p * 64 + 32 + lane] = att_pool(lg_s, fs_s, 32 + lane);
        __syncwarp();
    }
}

// ---------------------------------------------------------------------------
// Kernel 4: 16-point tiles: pc2 = relu(agg2@w1+b1) into combined [pc2;feat]
//           K=96 A tile; out = leaky(A @ w23 + b2).  Packed float4 B.
// ---------------------------------------------------------------------------
#define OUT_WARPS 12
#define OUT_BASE_FLOATS 33600  // w1p 8448 + w23p 24960 + b1 64 + b2 128
#define OUT_WARP_FLOATS 1600   // A [16][100]
#define OUT_SMEM_BYTES ((OUT_BASE_FLOATS + OUT_WARPS * OUT_WARP_FLOATS) * 4)

__global__ __launch_bounds__(384) void kern_out(
    const float* __restrict__ feature,
    const float* __restrict__ wam2, const float* __restrict__ sam2, const float* __restrict__ bam2,
    const float* __restrict__ wmlp2, const float* __restrict__ smlp2, const float* __restrict__ bmlp2,
    const float* __restrict__ wsc, const float* __restrict__ ssc, const float* __restrict__ bsc,
    float* __restrict__ out)
{
    extern __shared__ float sm[];
    float4* w1p  = (float4*)sm;              // [32][66] float4 = 8448 floats
    float4* w23p = (float4*)(sm + 8448);     // [48][130] float4 = 24960 floats
    float*  b1   = sm + 33408;               // [64]
    float*  b2   = sm + 33472;               // [128]
    float*  wrp  = sm + OUT_BASE_FLOATS;

    for (int i = threadIdx.x; i < 2048; i += blockDim.x) {
        int r = i >> 6, c = i & 63;
        int k0 = (r >> 2) * 8 + (r & 3), k1 = k0 + 4;
        float v0 = wam2[k0 * 64 + c] * sam2[c];
        float v1 = wam2[k1 * 64 + c] * sam2[c];
        float h0 = to_tf32(v0), h1 = to_tf32(v1);
        w1p[r * P4_64 + c] = make_float4(h0, h1, to_tf32(v0 - h0), to_tf32(v1 - h1));
    }
    for (int i = threadIdx.x; i < 6144; i += blockDim.x) {
        int r = i >> 7, c = i & 127;
        int k0 = (r >> 2) * 8 + (r & 3), k1 = k0 + 4;
        float v0 = (k0 < 64) ? wmlp2[k0 * 128 + c] * smlp2[c] : wsc[(k0 - 64) * 128 + c] * ssc[c];
        float v1 = (k1 < 64) ? wmlp2[k1 * 128 + c] * smlp2[c] : wsc[(k1 - 64) * 128 + c] * ssc[c];
        float h0 = to_tf32(v0), h1 = to_tf32(v1);
        w23p[r * P4_128 + c] = make_float4(h0, h1, to_tf32(v0 - h0), to_tf32(v1 - h1));
    }
    if (threadIdx.x < 64)  b1[threadIdx.x] = bam2[threadIdx.x];
    if (threadIdx.x < 128) b2[threadIdx.x] = bmlp2[threadIdx.x] + bsc[threadIdx.x];
    __syncthreads();

    const int lane = threadIdx.x & 31;
    const int warp = threadIdx.x >> 5;
    const int gid = lane >> 2, tig = lane & 3;
    float* A1 = wrp + warp * OUT_WARP_FLOATS;  // [16][100]: cols 0-63 agg2->pc2, 64-95 feat

    const int nwarps = (gridDim.x * blockDim.x) >> 5;
    int gw = (blockIdx.x * blockDim.x + threadIdx.x) >> 5;
    const int ntiles = P_TOTAL / 16;

    for (int t = gw; t < ntiles; t += nwarps) {
        const int p0 = t * 16;

        #pragma unroll
        for (int r = 0; r < 16; r++) {
            A1[r * OA_PAD + lane]      = g_agg2[(size_t)(p0 + r) * 64 + lane];
            A1[r * OA_PAD + 32 + lane] = g_agg2[(size_t)(p0 + r) * 64 + 32 + lane];
            A1[r * OA_PAD + 64 + lane] = feature[(size_t)(p0 + r) * 32 + lane];
        }
        __syncwarp();

        // GEMM1: pc2 = relu(agg @ w1 + b1), written back into A cols 0..63
        {
            float acc[8][4];
            #pragma unroll
            for (int n = 0; n < 8; n++) { acc[n][0]=0.f; acc[n][1]=0.f; acc[n][2]=0.f; acc[n][3]=0.f; }
            #pragma unroll
            for (int q = 0; q < 8; q++) {
                unsigned ah0, al0, ah1, al1, ah2, al2, ah3, al3;
                tf32_split(A1[gid * OA_PAD + q * 8 + tig],           ah0, al0);
                tf32_split(A1[(gid + 8) * OA_PAD + q * 8 + tig],     ah1, al1);
                tf32_split(A1[gid * OA_PAD + q * 8 + tig + 4],       ah2, al2);
                tf32_split(A1[(gid + 8) * OA_PAD + q * 8 + tig + 4], ah3, al3);
                const float4* br = w1p + (q * 4 + tig) * P4_64 + gid;
                #pragma unroll
                for (int n = 0; n < 8; n++)
                    mma3_pk(acc[n], br[8 * n], ah0, ah1, ah2, ah3, al0, al1, al2, al3);
            }
            __syncwarp();
            #pragma unroll
            for (int n = 0; n < 8; n++) {
                int c0 = n * 8 + 2 * tig;
                float bb0 = b1[c0], bb1 = b1[c0 + 1];
                *(float2*)(A1 + gid * OA_PAD + c0) =
                    make_float2(fmaxf(acc[n][0] + bb0, 0.f), fmaxf(acc[n][1] + bb1, 0.f));
                *(float2*)(A1 + (gid + 8) * OA_PAD + c0) =
                    make_float2(fmaxf(acc[n][2] + bb0, 0.f), fmaxf(acc[n][3] + bb1, 0.f));
            }
        }
        __syncwarp();

        // GEMM2: out = leaky(A[16][96] @ w23 + b2), n in two halves of 64
        #pragma unroll
        for (int h = 0; h < 2; h++) {
            float acc[8][4];
            #pragma unroll
            for (int n = 0; n < 8; n++) { acc[n][0]=0.f; acc[n][1]=0.f; acc[n][2]=0.f; acc[n][3]=0.f; }
            #pragma unroll
            for (int q = 0; q < 12; q++) {
                unsigned ah0, al0, ah1, al1, ah2, al2, ah3, al3;
                tf32_split(A1[gid * OA_PAD + q * 8 + tig],           ah0, al0);
                tf32_split(A1[(gid + 8) * OA_PAD + q * 8 + tig],     ah1, al1);
                tf32_split(A1[gid * OA_PAD + q * 8 + tig + 4],       ah2, al2);
                tf32_split(A1[(gid + 8) * OA_PAD + q * 8 + tig + 4], ah3, al3);
                const float4* br = w23p + (q * 4 + tig) * P4_128 + h * 64 + gid;
                #pragma unroll
                for (int n = 0; n < 8; n++)
                    mma3_pk(acc[n], br[8 * n], ah0, ah1, ah2, ah3, al0, al1, al2, al3);
            }
            #pragma unroll
            for (int n = 0; n < 8; n++) {
                int c0 = h * 64 + n * 8 + 2 * tig;
                float bb0 = b2[c0], bb1 = b2[c0 + 1];
                float v0 = acc[n][0] + bb0; v0 = (v0 < 0.f) ? 0.2f * v0 : v0;
                float v1 = acc[n][1] + bb1; v1 = (v1 < 0.f) ? 0.2f * v1 : v1;
                float v2 = acc[n][2] + bb0; v2 = (v2 < 0.f) ? 0.2f * v2 : v2;
                float v3 = acc[n][3] + bb1; v3 = (v3 < 0.f) ? 0.2f * v3 : v3;
                *(float2*)(&out[(size_t)(p0 + gid) * 128 + c0])     = make_float2(v0, v1);
                *(float2*)(&out[(size_t)(p0 + gid + 8) * 128 + c0]) = make_float2(v2, v3);
            }
        }
        __syncwarp();
    }
}

// ---------------------------------------------------------------------------
extern "C" void kernel_launch(void* const* d_in, const int* in_sizes, int n_in,
                              void* d_out, int out_size)
{
    const float* feature = (const float*)d_in[0];
    const float* xyz     = (const float*)d_in[1];
    const int*   neigh   = (const int*)  d_in[2];
    const float* w_mlp1  = (const float*)d_in[3];
    const float* s_mlp1  = (const float*)d_in[4];
    const float* b_mlp1  = (const float*)d_in[5];
    const float* w_lfa1  = (const float*)d_in[6];
    const float* s_lfa1  = (const float*)d_in[7];
    const float* b_lfa1  = (const float*)d_in[8];
    const float* w_fc1   = (const float*)d_in[9];
    const float* w_am1   = (const float*)d_in[10];
    const float* s_am1   = (const float*)d_in[11];
    const float* b_am1   = (const float*)d_in[12];
    const float* w_lfa2  = (const float*)d_in[13];
    const float* s_lfa2  = (const float*)d_in[14];
    const float* b_lfa2  = (const float*)d_in[15];
    const float* w_fc2   = (const float*)d_in[16];
    const float* w_am2   = (const float*)d_in[17];
    const float* s_am2   = (const float*)d_in[18];
    const float* b_am2   = (const float*)d_in[19];
    const float* w_mlp2  = (const float*)d_in[20];
    const float* s_mlp2  = (const float*)d_in[21];
    const float* b_mlp2  = (const float*)d_in[22];
    const float* w_sc    = (const float*)d_in[23];
    const float* s_sc    = (const float*)d_in[24];
    const float* b_sc    = (const float*)d_in[25];
    float* out = (float*)d_out;

    cudaFuncSetAttribute(kern_att1, cudaFuncAttributeMaxDynamicSharedMemorySize, K2_SMEM_BYTES);
    cudaFuncSetAttribute(kern_att2, cudaFuncAttributeMaxDynamicSharedMemorySize, K3_SMEM_BYTES);
    cudaFuncSetAttribute(kern_out,  cudaFuncAttributeMaxDynamicSharedMemorySize, OUT_SMEM_BYTES);

    kern_mlp1<<<2048, 256>>>(feature, w_mlp1, s_mlp1, b_mlp1);

    kern_att1<<<148, 576, K2_SMEM_BYTES>>>(
        xyz, neigh,
        w_lfa1, s_lfa1, b_lfa1,
        w_fc1,
        w_am1, s_am1, b_am1,
        w_lfa2, s_lfa2, b_lfa2);

    kern_att2<<<148, 640, K3_SMEM_BYTES>>>(neigh, w_fc2);

    kern_out<<<148, 384, OUT_SMEM_BYTES>>>(
        feature,
        w_am2, s_am2, b_am2,
        w_mlp2, s_mlp2, b_mlp2,
        w_sc, s_sc, b_sc,
        out);
}

// round 8
// speedup vs baseline: 3.0697x; 1.2146x over previous
#include <cuda_runtime.h>
#include <cuda_fp16.h>
#include <math.h>

#define BATCH 4
#define NPTS  40960
#define KNN   16
#define P_TOTAL (BATCH * NPTS)   // 163840

#define FS_H2  36    // fs tile row stride in half2 units (4 mod 32)
#define LG_PAD 66    // logits tile row stride (floats)
#define WH64   68    // fp16 B-tile stride, 64 cols, uint2 units (4 mod 16)
#define WH32   36    // fp16 B-tile stride, 32 cols, uint2 units (4 mod 16)
#define P4_32  34    // float4 B-tile stride, 32 cols (2 mod 8)
#define P4_64  66    // float4 B-tile stride, 64 cols (2 mod 8)
#define P4_128 130   // float4 B-tile stride, 128 cols (2 mod 8)
#define RP_PAD 20    // relpos tile stride
#define OA_PAD 100   // kern_out A tile stride (4 mod 32)

// Scratch (device globals)
__device__ float   g_f_pc [P_TOTAL * 32];                    // 21 MB
__device__ float   g_f_agg[P_TOTAL * 32];                    // 21 MB
__device__ float   g_agg2 [(size_t)P_TOTAL * 64];            // 42 MB
__device__ __half2 g_fx2  [(size_t)P_TOTAL * KNN * 16];      // 168 MB

__device__ __forceinline__ float to_tf32(float x) {
    float r;
    asm("cvt.rna.tf32.f32 %0, %1;" : "=f"(r) : "f"(x));
    return r;
}
__device__ __forceinline__ void tf32_split(float x, unsigned& h, unsigned& l) {
    float hf = to_tf32(x);
    h = __float_as_uint(hf);
    l = __float_as_uint(to_tf32(x - hf));
}
__device__ __forceinline__ unsigned f2_to_u(float a, float b) {
    __half2 h = __floats2half2_rn(a, b);
    return *(unsigned*)&h;
}

__device__ __forceinline__ void mma_tf32(float* c,
                                         unsigned a0, unsigned a1, unsigned a2, unsigned a3,
                                         unsigned b0, unsigned b1) {
    asm("mma.sync.aligned.m16n8k8.row.col.f32.tf32.tf32.f32 "
        "{%0,%1,%2,%3}, {%4,%5,%6,%7}, {%8,%9}, {%0,%1,%2,%3};"
        : "+f"(c[0]), "+f"(c[1]), "+f"(c[2]), "+f"(c[3])
        : "r"(a0), "r"(a1), "r"(a2), "r"(a3), "r"(b0), "r"(b1));
}

__device__ __forceinline__ void mma_f16(float* c,
                                        unsigned a0, unsigned a1, unsigned a2, unsigned a3,
                                        unsigned b0, unsigned b1) {
    asm("mma.sync.aligned.m16n8k16.row.col.f32.f16.f16.f32 "
        "{%0,%1,%2,%3}, {%4,%5,%6,%7}, {%8,%9}, {%0,%1,%2,%3};"
        : "+f"(c[0]), "+f"(c[1]), "+f"(c[2]), "+f"(c[3])
        : "r"(a0), "r"(a1), "r"(a2), "r"(a3), "r"(b0), "r"(b1));
}

// 3xTF32 mma step with packed float4 B = (bh0,bh1,bl0,bl1)
__device__ __forceinline__ void mma3_pk(float* acc, float4 b,
                                        unsigned ah0, unsigned ah1, unsigned ah2, unsigned ah3,
                                        unsigned al0, unsigned al1, unsigned al2, unsigned al3) {
    unsigned bh0 = __float_as_uint(b.x), bh1 = __float_as_uint(b.y);
    unsigned bl0 = __float_as_uint(b.z), bl1 = __float_as_uint(b.w);
    mma_tf32(acc, ah0, ah1, ah2, ah3, bh0, bh1);
    mma_tf32(acc, al0, al1, al2, al3, bh0, bh1);
    mma_tf32(acc, ah0, ah1, ah2, ah3, bl0, bl1);
}

// logits[16][64] = fs(fp16)[16][64] @ wfc(fp16)[64][64] via m16n8k16
__device__ __forceinline__ void logits_f16(const unsigned* __restrict__ fsw,
                                           float* __restrict__ lg_s,
                                           const uint2* __restrict__ wfc, int lane)
{
    const int gid = lane >> 2;
    const int tig = lane & 3;
    float acc[8][4];
    #pragma unroll
    for (int n = 0; n < 8; n++) { acc[n][0]=0.f; acc[n][1]=0.f; acc[n][2]=0.f; acc[n][3]=0.f; }
    #pragma unroll
    for (int q = 0; q < 4; q++) {
        unsigned a0 = fsw[gid * FS_H2 + q * 8 + tig];
        unsigned a1 = fsw[(gid + 8) * FS_H2 + q * 8 + tig];
        unsigned a2 = fsw[gid * FS_H2 + q * 8 + tig + 4];
        unsigned a3 = fsw[(gid + 8) * FS_H2 + q * 8 + tig + 4];
        const uint2* br = wfc + (q * 4 + tig) * WH64 + gid;
        #pragma unroll
        for (int n = 0; n < 8; n++) {
            uint2 b = br[8 * n];
            mma_f16(acc[n], a0, a1, a2, a3, b.x, b.y);
        }
    }
    #pragma unroll
    for (int n = 0; n < 8; n++) {
        *(float2*)(lg_s + gid * LG_PAD + n * 8 + 2 * tig)       = make_float2(acc[n][0], acc[n][1]);
        *(float2*)(lg_s + (gid + 8) * LG_PAD + n * 8 + 2 * tig) = make_float2(acc[n][2], acc[n][3]);
    }
}

// softmax over K + pool, values from registers
__device__ __forceinline__ float att_pool_reg(const float* __restrict__ lg_s,
                                              const float* __restrict__ vals, int ch)
{
    float l[KNN];
    float m = -1e30f;
    #pragma unroll
    for (int k = 0; k < KNN; k++) { l[k] = lg_s[k * LG_PAD + ch]; m = fmaxf(m, l[k]); }
    float s = 0.f, a = 0.f;
    #pragma unroll
    for (int k = 0; k < KNN; k++) {
        float e = __expf(l[k] - m);
        s += e;
        a += e * vals[k];
    }
    return __fdividef(a, s);
}

// softmax over K + pool, fs values fp16 (channel 32+lane)
__device__ __forceinline__ float att_pool_h(const float* __restrict__ lg_s,
                                            const __half2* __restrict__ fs_h, int lane)
{
    const int ch = 32 + lane;
    float vals[KNN];
    #pragma unroll
    for (int k = 0; k < KNN; k++) {
        __half2 h = fs_h[k * FS_H2 + 16 + (lane >> 1)];
        vals[k] = (lane & 1) ? __high2float(h) : __low2float(h);
    }
    return att_pool_reg(lg_s, vals, ch);
}

// ---------------------------------------------------------------------------
// Kernel 1: f_pc = ReLU((feature @ w_mlp1) * s + b)
// ---------------------------------------------------------------------------
__global__ __launch_bounds__(256) void kern_mlp1(
    const float* __restrict__ feature,
    const float* __restrict__ w, const float* __restrict__ s, const float* __restrict__ b)
{
    __shared__ float ws[1024];
    __shared__ float sv[32], bv[32];
    __shared__ float xs[8][32];

    for (int i = threadIdx.x; i < 1024; i += blockDim.x) ws[i] = w[i];
    if (threadIdx.x < 32) { sv[threadIdx.x] = s[threadIdx.x]; bv[threadIdx.x] = b[threadIdx.x]; }
    __syncthreads();

    const int lane = threadIdx.x & 31;
    const int warp = threadIdx.x >> 5;
    const int nwarps = (gridDim.x * blockDim.x) >> 5;
    int gw = (blockIdx.x * blockDim.x + threadIdx.x) >> 5;

    for (int p = gw; p < P_TOTAL; p += nwarps) {
        xs[warp][lane] = feature[(size_t)p * 32 + lane];
        __syncwarp();
        float acc = 0.f;
        #pragma unroll
        for (int j4 = 0; j4 < 32; j4 += 4) {
            float4 f = *(const float4*)(&xs[warp][j4]);
            acc += f.x * ws[(j4 + 0) * 32 + lane];
            acc += f.y * ws[(j4 + 1) * 32 + lane];
            acc += f.z * ws[(j4 + 2) * 32 + lane];
            acc += f.w * ws[(j4 + 3) * 32 + lane];
        }
        g_f_pc[(size_t)p * 32 + lane] = fmaxf(acc * sv[lane] + bv[lane], 0.f);
        __syncwarp();
    }
}

// ---------------------------------------------------------------------------
// Kernel 2: rel_pos + lfa1(3xTF32) + gather + logits(f16) + pool + f_agg ;
//           lfa2(f16) -> g_fx2
// ---------------------------------------------------------------------------
#define K2_WARP_FLOATS 1696   // fs 576 (half2) + lg 1056 (rp aliases lg) + agg 64
#define K2_BASE_FLOATS 6016
#define K2_WARPS 20
#define K2_SMEM_BYTES ((K2_BASE_FLOATS + K2_WARPS * K2_WARP_FLOATS) * 4)

__global__ __launch_bounds__(640) void kern_att1(
    const float* __restrict__ xyz, const int* __restrict__ neigh,
    const float* __restrict__ wlfa1, const float* __restrict__ slfa1, const float* __restrict__ blfa1,
    const float* __restrict__ wfc1,
    const float* __restrict__ wam1, const float* __restrict__ sam1, const float* __restrict__ bam1,
    const float* __restrict__ wlfa2, const float* __restrict__ slfa2, const float* __restrict__ blfa2)
{
    extern __shared__ float sm[];
    uint2*  s_wfcp = (uint2*)sm;              // [16][68] uint2 = 2176 floats
    float2* s_wamp = (float2*)(sm + 2176);    // [32][32] float2 = 2048 floats
    float4* s_wl1p = (float4*)(sm + 4224);    // [8][34] float4 = 1088 floats
    uint2*  s_wl2p = (uint2*)(sm + 5312);     // [8][36] uint2 = 576 floats
    float*  s_vec  = sm + 5888;               // 128: blfa1, blfa2, bam1
    float*  s_wrp  = sm + K2_BASE_FLOATS;

    for (int i = threadIdx.x; i < 1024; i += blockDim.x) {
        int r = i >> 6, c = i & 63;
        int q = r >> 2, t = r & 3;
        int k0 = 16 * q + 2 * t;
        s_wfcp[r * WH64 + c] = make_uint2(
            f2_to_u(wfc1[k0 * 64 + c], wfc1[(k0 + 1) * 64 + c]),
            f2_to_u(wfc1[(k0 + 8) * 64 + c], wfc1[(k0 + 9) * 64 + c]));
    }
    for (int i = threadIdx.x; i < 1024; i += blockDim.x) {
        int r = i >> 5, c = i & 31;
        s_wamp[r * 32 + c] = make_float2(wam1[(2 * r) * 32 + c] * sam1[c],
                                         wam1[(2 * r + 1) * 32 + c] * sam1[c]);
    }
    for (int i = threadIdx.x; i < 256; i += blockDim.x) {
        int r = i >> 5, c = i & 31;
        int k0 = (r >> 2) * 8 + (r & 3), k1 = k0 + 4;
        float v0 = (k0 < 10) ? wlfa1[k0 * 32 + c] * slfa1[c] : 0.f;
        float v1 = (k1 < 10) ? wlfa1[k1 * 32 + c] * slfa1[c] : 0.f;
        float h0 = to_tf32(v0), h1 = to_tf32(v1);
        s_wl1p[r * P4_32 + c] = make_float4(h0, h1, to_tf32(v0 - h0), to_tf32(v1 - h1));
    }
    for (int i = threadIdx.x; i < 256; i += blockDim.x) {
        int r = i >> 5, c = i & 31;
        int q = r >> 2, t = r & 3;
        int k0 = 16 * q + 2 * t;
        s_wl2p[r * WH32 + c] = make_uint2(
            f2_to_u(wlfa2[k0 * 32 + c] * slfa2[c], wlfa2[(k0 + 1) * 32 + c] * slfa2[c]),
            f2_to_u(wlfa2[(k0 + 8) * 32 + c] * slfa2[c], wlfa2[(k0 + 9) * 32 + c] * slfa2[c]));
    }
    if (threadIdx.x < 32) {
        int l = threadIdx.x;
        s_vec[l]      = blfa1[l];
        s_vec[32 + l] = blfa2[l];
        s_vec[64 + l] = bam1[l];
    }
    __syncthreads();

    const int lane = threadIdx.x & 31;
    const int warp = threadIdx.x >> 5;
    const int gid = lane >> 2, tig = lane & 3;
    __half2*  fs_h = (__half2*)(s_wrp + warp * K2_WARP_FLOATS);  // [16][36] half2
    unsigned* fsw  = (unsigned*)fs_h;
    float* lg_s  = s_wrp + warp * K2_WARP_FLOATS + 576;          // [16][66]
    float* rp_s  = lg_s;                                         // [16][20] aliases lg
    float* agg_s = lg_s + 1056;                                  // [64]

    const int nwarps = (gridDim.x * blockDim.x) >> 5;
    int gw = (blockIdx.x * blockDim.x + threadIdx.x) >> 5;

    for (int p = gw; p < P_TOTAL; p += nwarps) {
        const int b = p / NPTS;
        const size_t bbase = (size_t)b * NPTS;

        int myidx = 0;
        if (lane < KNN) myidx = neigh[(size_t)p * KNN + lane];

        float gv[KNN];
        #pragma unroll
        for (int k = 0; k < KNN; k++) {
            int nb = __shfl_sync(0xffffffffu, myidx, k);
            gv[k] = g_f_pc[(bbase + (size_t)nb) * 32 + lane];
        }

        const float cx = xyz[(size_t)p * 3 + 0];
        const float cy = xyz[(size_t)p * 3 + 1];
        const float cz = xyz[(size_t)p * 3 + 2];

        if (lane < KNN) {
            size_t nb = bbase + (size_t)myidx;
            float nx = xyz[nb * 3 + 0], ny = xyz[nb * 3 + 1], nz = xyz[nb * 3 + 2];
            float rx = cx - nx, ry = cy - ny, rz = cz - nz;
            float d = sqrtf(rx * rx + ry * ry + rz * rz);
            float* rp = rp_s + lane * RP_PAD;
            rp[0] = d;  rp[1] = rx; rp[2] = ry; rp[3] = rz;
            rp[4] = cx; rp[5] = cy; rp[6] = cz;
            rp[7] = nx; rp[8] = ny; rp[9] = nz;
            rp[10] = 0.f; rp[11] = 0.f; rp[12] = 0.f;
            rp[13] = 0.f; rp[14] = 0.f; rp[15] = 0.f;
        }
        __syncwarp();

        // ---- lfa1 via 3xTF32 mma: f_xyz -> fs half2 cols 16..31 (ch 32..63)
        {
            float acc[4][4];
            #pragma unroll
            for (int n = 0; n < 4; n++) { acc[n][0]=0.f; acc[n][1]=0.f; acc[n][2]=0.f; acc[n][3]=0.f; }
            #pragma unroll
            for (int q = 0; q < 2; q++) {
                unsigned ah0, al0, ah1, al1, ah2, al2, ah3, al3;
                tf32_split(rp_s[gid * RP_PAD + q * 8 + tig],           ah0, al0);
                tf32_split(rp_s[(gid + 8) * RP_PAD + q * 8 + tig],     ah1, al1);
                tf32_split(rp_s[gid * RP_PAD + q * 8 + tig + 4],       ah2, al2);
                tf32_split(rp_s[(gid + 8) * RP_PAD + q * 8 + tig + 4], ah3, al3);
                const float4* br = s_wl1p + (q * 4 + tig) * P4_32 + gid;
                #pragma unroll
                for (int n = 0; n < 4; n++)
                    mma3_pk(acc[n], br[8 * n], ah0, ah1, ah2, ah3, al0, al1, al2, al3);
            }
            #pragma unroll
            for (int n = 0; n < 4; n++) {
                int c0 = n * 8 + 2 * tig;
                float b0 = s_vec[c0], b1 = s_vec[c0 + 1];
                fs_h[gid * FS_H2 + 16 + n * 4 + tig] =
                    __floats2half2_rn(fmaxf(acc[n][0] + b0, 0.f), fmaxf(acc[n][1] + b1, 0.f));
                fs_h[(gid + 8) * FS_H2 + 16 + n * 4 + tig] =
                    __floats2half2_rn(fmaxf(acc[n][2] + b0, 0.f), fmaxf(acc[n][3] + b1, 0.f));
            }
        }

        // gathered f_pc -> fs half2 cols 0..15 (pack pairs via shfl)
        #pragma unroll
        for (int k = 0; k < KNN; k++) {
            float v0 = gv[k];
            float v1 = __shfl_xor_sync(0xffffffffu, v0, 1);
            if (!(lane & 1))
                fs_h[k * FS_H2 + (lane >> 1)] = __floats2half2_rn(v0, v1);
        }
        __syncwarp();

        // ---- logits (f16 mma) + softmax pool
        logits_f16(fsw, lg_s, s_wfcp, lane);
        __syncwarp();
        agg_s[lane]      = att_pool_reg(lg_s, gv, lane);
        agg_s[32 + lane] = att_pool_h(lg_s, fs_h, lane);
        __syncwarp();

        // ---- f_agg = ReLU(agg @ (wam1*s) + b)
        {
            float acc = 0.f;
            #pragma unroll
            for (int d2 = 0; d2 < 32; d2 += 2) {
                float4 a = *(const float4*)(agg_s + 2 * d2);
                float2 w0 = s_wamp[d2 * 32 + lane];
                float2 w1 = s_wamp[(d2 + 1) * 32 + lane];
                acc += a.x * w0.x + a.y * w0.y + a.z * w1.x + a.w * w1.y;
            }
            g_f_agg[(size_t)p * 32 + lane] = fmaxf(acc + s_vec[64 + lane], 0.f);
        }

        // ---- lfa2 via f16 mma: f_xyz2 -> g_fx2 (half2)
        {
            float acc[4][4];
            #pragma unroll
            for (int n = 0; n < 4; n++) { acc[n][0]=0.f; acc[n][1]=0.f; acc[n][2]=0.f; acc[n][3]=0.f; }
            #pragma unroll
            for (int q = 0; q < 2; q++) {
                unsigned a0 = fsw[gid * FS_H2 + 16 + q * 8 + tig];
                unsigned a1 = fsw[(gid + 8) * FS_H2 + 16 + q * 8 + tig];
                unsigned a2 = fsw[gid * FS_H2 + 16 + q * 8 + tig + 4];
                unsigned a3 = fsw[(gid + 8) * FS_H2 + 16 + q * 8 + tig + 4];
                const uint2* br = s_wl2p + (q * 4 + tig) * WH32 + gid;
                #pragma unroll
                for (int n = 0; n < 4; n++) {
                    uint2 bb = br[8 * n];
                    mma_f16(acc[n], a0, a1, a2, a3, bb.x, bb.y);
                }
            }
            #pragma unroll
            for (int n = 0; n < 4; n++) {
                int c0 = n * 8 + 2 * tig;
                float b0 = s_vec[32 + c0], b1 = s_vec[32 + c0 + 1];
                g_fx2[((size_t)p * KNN + gid) * 16 + (c0 >> 1)] =
                    __floats2half2_rn(fmaxf(acc[n][0] + b0, 0.f), fmaxf(acc[n][1] + b1, 0.f));
                g_fx2[((size_t)p * KNN + gid + 8) * 16 + (c0 >> 1)] =
                    __floats2half2_rn(fmaxf(acc[n][2] + b0, 0.f), fmaxf(acc[n][3] + b1, 0.f));
            }
        }
        __syncwarp();
    }
}

// ---------------------------------------------------------------------------
// Kernel 3: gather(f_agg) + f_xyz2(fp16) + logits(f16) + pool -> g_agg2
// ---------------------------------------------------------------------------
#define K3_WARP_FLOATS 1632   // fs 576 (half2) + lg 1056
#define K3_BASE_FLOATS 2176
#define K3_WARPS 24
#define K3_SMEM_BYTES ((K3_BASE_FLOATS + K3_WARPS * K3_WARP_FLOATS) * 4)

__global__ __launch_bounds__(768) void kern_att2(
    const int* __restrict__ neigh,
    const float* __restrict__ wfc2)
{
    extern __shared__ float sm[];
    uint2* s_wfcp = (uint2*)sm;               // [16][68] uint2
    float* s_wrp  = sm + K3_BASE_FLOATS;

    for (int i = threadIdx.x; i < 1024; i += blockDim.x) {
        int r = i >> 6, c = i & 63;
        int q = r >> 2, t = r & 3;
        int k0 = 16 * q + 2 * t;
        s_wfcp[r * WH64 + c] = make_uint2(
            f2_to_u(wfc2[k0 * 64 + c], wfc2[(k0 + 1) * 64 + c]),
            f2_to_u(wfc2[(k0 + 8) * 64 + c], wfc2[(k0 + 9) * 64 + c]));
    }
    __syncthreads();

    const int lane = threadIdx.x & 31;
    const int warp = threadIdx.x >> 5;
    __half2*  fs_h = (__half2*)(s_wrp + warp * K3_WARP_FLOATS);  // [16][36] half2
    unsigned* fsw  = (unsigned*)fs_h;
    float* lg_s = s_wrp + warp * K3_WARP_FLOATS + 576;           // [16][66]

    const int kk = lane >> 4;
    const int jj = lane & 15;

    const int nwarps = (gridDim.x * blockDim.x) >> 5;
    int gw = (blockIdx.x * blockDim.x + threadIdx.x) >> 5;

    for (int p = gw; p < P_TOTAL; p += nwarps) {
        const int b = p / NPTS;
        const size_t bbase = (size_t)b * NPTS;

        int myidx = 0;
        if (lane < KNN) myidx = neigh[(size_t)p * KNN + lane];

        float gv[KNN];
        #pragma unroll
        for (int k = 0; k < KNN; k++) {
            int nb = __shfl_sync(0xffffffffu, myidx, k);
            gv[k] = g_f_agg[(bbase + (size_t)nb) * 32 + lane];
        }
        #pragma unroll
        for (int k = 0; k < KNN; k++) {
            float v0 = gv[k];
            float v1 = __shfl_xor_sync(0xffffffffu, v0, 1);
            if (!(lane & 1))
                fs_h[k * FS_H2 + (lane >> 1)] = __floats2half2_rn(v0, v1);
        }
        // f_xyz2 (already fp16): raw 4B copy, coalesced
        const unsigned* src = (const unsigned*)(g_fx2 + (size_t)p * KNN * 16);
        #pragma unroll
        for (int k = 0; k < KNN; k += 2) {
            fsw[(k + kk) * FS_H2 + 16 + jj] = src[(k + kk) * 16 + jj];
        }
        __syncwarp();

        logits_f16(fsw, lg_s, s_wfcp, lane);
        __syncwarp();

        g_agg2[(size_t)p * 64 + lane]      = att_pool_reg(lg_s, gv, lane);
        g_agg2[(size_t)p * 64 + 32 + lane] = att_pool_h(lg_s, fs_h, lane);
        __syncwarp();
    }
}

// ---------------------------------------------------------------------------
// Kernel 4: 16-point tiles: pc2 = relu(agg2@w1+b1) into combined [pc2;feat]
//           K=96 A tile; out = leaky(A @ w23 + b2).  3xTF32 packed float4 B.
// ---------------------------------------------------------------------------
#define OUT_WARPS 12
#define OUT_BASE_FLOATS 33600  // w1p 8448 + w23p 24960 + b1 64 + b2 128
#define OUT_WARP_FLOATS 1600   // A [16][100]
#define OUT_SMEM_BYTES ((OUT_BASE_FLOATS + OUT_WARPS * OUT_WARP_FLOATS) * 4)

__global__ __launch_bounds__(384) void kern_out(
    const float* __restrict__ feature,
    const float* __restrict__ wam2, const float* __restrict__ sam2, const float* __restrict__ bam2,
    const float* __restrict__ wmlp2, const float* __restrict__ smlp2, const float* __restrict__ bmlp2,
    const float* __restrict__ wsc, const float* __restrict__ ssc, const float* __restrict__ bsc,
    float* __restrict__ out)
{
    extern __shared__ float sm[];
    float4* w1p  = (float4*)sm;              // [32][66] float4 = 8448 floats
    float4* w23p = (float4*)(sm + 8448);     // [48][130] float4 = 24960 floats
    float*  b1   = sm + 33408;               // [64]
    float*  b2   = sm + 33472;               // [128]
    float*  wrp  = sm + OUT_BASE_FLOATS;

    for (int i = threadIdx.x; i < 2048; i += blockDim.x) {
        int r = i >> 6, c = i & 63;
        int k0 = (r >> 2) * 8 + (r & 3), k1 = k0 + 4;
        float v0 = wam2[k0 * 64 + c] * sam2[c];
        float v1 = wam2[k1 * 64 + c] * sam2[c];
        float h0 = to_tf32(v0), h1 = to_tf32(v1);
        w1p[r * P4_64 + c] = make_float4(h0, h1, to_tf32(v0 - h0), to_tf32(v1 - h1));
    }
    for (int i = threadIdx.x; i < 6144; i += blockDim.x) {
        int r = i >> 7, c = i & 127;
        int k0 = (r >> 2) * 8 + (r & 3), k1 = k0 + 4;
        float v0 = (k0 < 64) ? wmlp2[k0 * 128 + c] * smlp2[c] : wsc[(k0 - 64) * 128 + c] * ssc[c];
        float v1 = (k1 < 64) ? wmlp2[k1 * 128 + c] * smlp2[c] : wsc[(k1 - 64) * 128 + c] * ssc[c];
        float h0 = to_tf32(v0), h1 = to_tf32(v1);
        w23p[r * P4_128 + c] = make_float4(h0, h1, to_tf32(v0 - h0), to_tf32(v1 - h1));
    }
    if (threadIdx.x < 64)  b1[threadIdx.x] = bam2[threadIdx.x];
    if (threadIdx.x < 128) b2[threadIdx.x] = bmlp2[threadIdx.x] + bsc[threadIdx.x];
    __syncthreads();

    const int lane = threadIdx.x & 31;
    const int warp = threadIdx.x >> 5;
    const int gid = lane >> 2, tig = lane & 3;
    float* A1 = wrp + warp * OUT_WARP_FLOATS;  // [16][100]

    const int nwarps = (gridDim.x * blockDim.x) >> 5;
    int gw = (blockIdx.x * blockDim.x + threadIdx.x) >> 5;
    const int ntiles = P_TOTAL / 16;

    for (int t = gw; t < ntiles; t += nwarps) {
        const int p0 = t * 16;

        #pragma unroll
        for (int r = 0; r < 16; r++) {
            A1[r * OA_PAD + lane]      = g_agg2[(size_t)(p0 + r) * 64 + lane];
            A1[r * OA_PAD + 32 + lane] = g_agg2[(size_t)(p0 + r) * 64 + 32 + lane];
            A1[r * OA_PAD + 64 + lane] = feature[(size_t)(p0 + r) * 32 + lane];
        }
        __syncwarp();

        // GEMM1: pc2 = relu(agg @ w1 + b1), written back into A cols 0..63
        {
            float acc[8][4];
            #pragma unroll
            for (int n = 0; n < 8; n++) { acc[n][0]=0.f; acc[n][1]=0.f; acc[n][2]=0.f; acc[n][3]=0.f; }
            #pragma unroll
            for (int q = 0; q < 8; q++) {
                unsigned ah0, al0, ah1, al1, ah2, al2, ah3, al3;
                tf32_split(A1[gid * OA_PAD + q * 8 + tig],           ah0, al0);
                tf32_split(A1[(gid + 8) * OA_PAD + q * 8 + tig],     ah1, al1);
                tf32_split(A1[gid * OA_PAD + q * 8 + tig + 4],       ah2, al2);
                tf32_split(A1[(gid + 8) * OA_PAD + q * 8 + tig + 4], ah3, al3);
                const float4* br = w1p + (q * 4 + tig) * P4_64 + gid;
                #pragma unroll
                for (int n = 0; n < 8; n++)
                    mma3_pk(acc[n], br[8 * n], ah0, ah1, ah2, ah3, al0, al1, al2, al3);
            }
            __syncwarp();
            #pragma unroll
            for (int n = 0; n < 8; n++) {
                int c0 = n * 8 + 2 * tig;
                float bb0 = b1[c0], bb1 = b1[c0 + 1];
                *(float2*)(A1 + gid * OA_PAD + c0) =
                    make_float2(fmaxf(acc[n][0] + bb0, 0.f), fmaxf(acc[n][1] + bb1, 0.f));
                *(float2*)(A1 + (gid + 8) * OA_PAD + c0) =
                    make_float2(fmaxf(acc[n][2] + bb0, 0.f), fmaxf(acc[n][3] + bb1, 0.f));
            }
        }
        __syncwarp();

        // GEMM2: out = leaky(A[16][96] @ w23 + b2), n in two halves of 64
        #pragma unroll
        for (int h = 0; h < 2; h++) {
            float acc[8][4];
            #pragma unroll
            for (int n = 0; n < 8; n++) { acc[n][0]=0.f; acc[n][1]=0.f; acc[n][2]=0.f; acc[n][3]=0.f; }
            #pragma unroll
            for (int q = 0; q < 12; q++) {
                unsigned ah0, al0, ah1, al1, ah2, al2, ah3, al3;
                tf32_split(A1[gid * OA_PAD + q * 8 + tig],           ah0, al0);
                tf32_split(A1[(gid + 8) * OA_PAD + q * 8 + tig],     ah1, al1);
                tf32_split(A1[gid * OA_PAD + q * 8 + tig + 4],       ah2, al2);
                tf32_split(A1[(gid + 8) * OA_PAD + q * 8 + tig + 4], ah3, al3);
                const float4* br = w23p + (q * 4 + tig) * P4_128 + h * 64 + gid;
                #pragma unroll
                for (int n = 0; n < 8; n++)
                    mma3_pk(acc[n], br[8 * n], ah0, ah1, ah2, ah3, al0, al1, al2, al3);
            }
            #pragma unroll
            for (int n = 0; n < 8; n++) {
                int c0 = h * 64 + n * 8 + 2 * tig;
                float bb0 = b2[c0], bb1 = b2[c0 + 1];
                float v0 = acc[n][0] + bb0; v0 = (v0 < 0.f) ? 0.2f * v0 : v0;
                float v1 = acc[n][1] + bb1; v1 = (v1 < 0.f) ? 0.2f * v1 : v1;
                float v2 = acc[n][2] + bb0; v2 = (v2 < 0.f) ? 0.2f * v2 : v2;
                float v3 = acc[n][3] + bb1; v3 = (v3 < 0.f) ? 0.2f * v3 : v3;
                *(float2*)(&out[(size_t)(p0 + gid) * 128 + c0])     = make_float2(v0, v1);
                *(float2*)(&out[(size_t)(p0 + gid + 8) * 128 + c0]) = make_float2(v2, v3);
            }
        }
        __syncwarp();
    }
}

// ---------------------------------------------------------------------------
extern "C" void kernel_launch(void* const* d_in, const int* in_sizes, int n_in,
                              void* d_out, int out_size)
{
    const float* feature = (const float*)d_in[0];
    const float* xyz     = (const float*)d_in[1];
    const int*   neigh   = (const int*)  d_in[2];
    const float* w_mlp1  = (const float*)d_in[3];
    const float* s_mlp1  = (const float*)d_in[4];
    const float* b_mlp1  = (const float*)d_in[5];
    const float* w_lfa1  = (const float*)d_in[6];
    const float* s_lfa1  = (const float*)d_in[7];
    const float* b_lfa1  = (const float*)d_in[8];
    const float* w_fc1   = (const float*)d_in[9];
    const float* w_am1   = (const float*)d_in[10];
    const float* s_am1   = (const float*)d_in[11];
    const float* b_am1   = (const float*)d_in[12];
    const float* w_lfa2  = (const float*)d_in[13];
    const float* s_lfa2  = (const float*)d_in[14];
    const float* b_lfa2  = (const float*)d_in[15];
    const float* w_fc2   = (const float*)d_in[16];
    const float* w_am2   = (const float*)d_in[17];
    const float* s_am2   = (const float*)d_in[18];
    const float* b_am2   = (const float*)d_in[19];
    const float* w_mlp2  = (const float*)d_in[20];
    const float* s_mlp2  = (const float*)d_in[21];
    const float* b_mlp2  = (const float*)d_in[22];
    const float* w_sc    = (const float*)d_in[23];
    const float* s_sc    = (const float*)d_in[24];
    const float* b_sc    = (const float*)d_in[25];
    float* out = (float*)d_out;

    cudaFuncSetAttribute(kern_att1, cudaFuncAttributeMaxDynamicSharedMemorySize, K2_SMEM_BYTES);
    cudaFuncSetAttribute(kern_att2, cudaFuncAttributeMaxDynamicSharedMemorySize, K3_SMEM_BYTES);
    cudaFuncSetAttribute(kern_out,  cudaFuncAttributeMaxDynamicSharedMemorySize, OUT_SMEM_BYTES);

    kern_mlp1<<<2048, 256>>>(feature, w_mlp1, s_mlp1, b_mlp1);

    kern_att1<<<148, 640, K2_SMEM_BYTES>>>(
        xyz, neigh,
        w_lfa1, s_lfa1, b_lfa1,
        w_fc1,
        w_am1, s_am1, b_am1,
        w_lfa2, s_lfa2, b_lfa2);

    kern_att2<<<148, 768, K3_SMEM_BYTES>>>(neigh, w_fc2);

    kern_out<<<148, 384, OUT_SMEM_BYTES>>>(
        feature,
        w_am2, s_am2, b_am2,
        w_mlp2, s_mlp2, b_mlp2,
        w_sc, s_sc, b_sc,
        out);
}

// round 9
// speedup vs baseline: 3.1668x; 1.0316x over previous
#include <cuda_runtime.h>
#include <cuda_fp16.h>
#include <math.h>

#define BATCH 4
#define NPTS  40960
#define KNN   16
#define P_TOTAL (BATCH * NPTS)   // 163840

#define FS_H2  36    // fs tile row stride in half2 units (4 mod 32)
#define LG_PAD 66    // logits tile row stride (floats)
#define WH64   68    // fp16 B-tile stride, 64 cols, uint2 units
#define WH32   36    // fp16 B-tile stride, 32 cols, uint2 units
#define P4_64  66    // float4 B-tile stride, 64 cols (2 mod 8)
#define P4_128 130   // float4 B-tile stride, 128 cols (2 mod 8)
#define RP2    12    // relpos tile stride in half2 units (12g+t distinct mod 32)
#define OA_PAD 100   // kern_out A tile stride (4 mod 32)

// Scratch (device globals)
__device__ float   g_f_pc [P_TOTAL * 32];                    // 21 MB
__device__ float   g_f_agg[P_TOTAL * 32];                    // 21 MB
__device__ float   g_agg2 [(size_t)P_TOTAL * 64];            // 42 MB
__device__ __half2 g_fx2  [(size_t)P_TOTAL * KNN * 16];      // 168 MB

__device__ __forceinline__ float to_tf32(float x) {
    float r;
    asm("cvt.rna.tf32.f32 %0, %1;" : "=f"(r) : "f"(x));
    return r;
}
__device__ __forceinline__ void tf32_split(float x, unsigned& h, unsigned& l) {
    float hf = to_tf32(x);
    h = __float_as_uint(hf);
    l = __float_as_uint(to_tf32(x - hf));
}
__device__ __forceinline__ unsigned f2_to_u(float a, float b) {
    __half2 h = __floats2half2_rn(a, b);
    return *(unsigned*)&h;
}

__device__ __forceinline__ void mma_tf32(float* c,
                                         unsigned a0, unsigned a1, unsigned a2, unsigned a3,
                                         unsigned b0, unsigned b1) {
    asm("mma.sync.aligned.m16n8k8.row.col.f32.tf32.tf32.f32 "
        "{%0,%1,%2,%3}, {%4,%5,%6,%7}, {%8,%9}, {%0,%1,%2,%3};"
        : "+f"(c[0]), "+f"(c[1]), "+f"(c[2]), "+f"(c[3])
        : "r"(a0), "r"(a1), "r"(a2), "r"(a3), "r"(b0), "r"(b1));
}
__device__ __forceinline__ void mma_f16(float* c,
                                        unsigned a0, unsigned a1, unsigned a2, unsigned a3,
                                        unsigned b0, unsigned b1) {
    asm("mma.sync.aligned.m16n8k16.row.col.f32.f16.f16.f32 "
        "{%0,%1,%2,%3}, {%4,%5,%6,%7}, {%8,%9}, {%0,%1,%2,%3};"
        : "+f"(c[0]), "+f"(c[1]), "+f"(c[2]), "+f"(c[3])
        : "r"(a0), "r"(a1), "r"(a2), "r"(a3), "r"(b0), "r"(b1));
}
__device__ __forceinline__ void mma3_pk(float* acc, float4 b,
                                        unsigned ah0, unsigned ah1, unsigned ah2, unsigned ah3,
                                        unsigned al0, unsigned al1, unsigned al2, unsigned al3) {
    unsigned bh0 = __float_as_uint(b.x), bh1 = __float_as_uint(b.y);
    unsigned bl0 = __float_as_uint(b.z), bl1 = __float_as_uint(b.w);
    mma_tf32(acc, ah0, ah1, ah2, ah3, bh0, bh1);
    mma_tf32(acc, al0, al1, al2, al3, bh0, bh1);
    mma_tf32(acc, ah0, ah1, ah2, ah3, bl0, bl1);
}

// dual-point logits: fs0/fs1 fp16 tiles share the B reads
__device__ __forceinline__ void logits_f16_x2(const unsigned* __restrict__ fsw0,
                                              const unsigned* __restrict__ fsw1,
                                              float* __restrict__ lg0,
                                              float* __restrict__ lg1,
                                              const uint2* __restrict__ wfc, int lane)
{
    const int gid = lane >> 2;
    const int tig = lane & 3;
    float ac0[8][4], ac1[8][4];
    #pragma unroll
    for (int n = 0; n < 8; n++)
        #pragma unroll
        for (int j = 0; j < 4; j++) { ac0[n][j] = 0.f; ac1[n][j] = 0.f; }
    #pragma unroll
    for (int q = 0; q < 4; q++) {
        unsigned a00 = fsw0[gid * FS_H2 + q * 8 + tig];
        unsigned a01 = fsw0[(gid + 8) * FS_H2 + q * 8 + tig];
        unsigned a02 = fsw0[gid * FS_H2 + q * 8 + tig + 4];
        unsigned a03 = fsw0[(gid + 8) * FS_H2 + q * 8 + tig + 4];
        unsigned a10 = fsw1[gid * FS_H2 + q * 8 + tig];
        unsigned a11 = fsw1[(gid + 8) * FS_H2 + q * 8 + tig];
        unsigned a12 = fsw1[gid * FS_H2 + q * 8 + tig + 4];
        unsigned a13 = fsw1[(gid + 8) * FS_H2 + q * 8 + tig + 4];
        const uint2* br = wfc + (q * 4 + tig) * WH64 + gid;
        #pragma unroll
        for (int n = 0; n < 8; n++) {
            uint2 b = br[8 * n];
            mma_f16(ac0[n], a00, a01, a02, a03, b.x, b.y);
            mma_f16(ac1[n], a10, a11, a12, a13, b.x, b.y);
        }
    }
    #pragma unroll
    for (int n = 0; n < 8; n++) {
        *(float2*)(lg0 + gid * LG_PAD + n * 8 + 2 * tig)       = make_float2(ac0[n][0], ac0[n][1]);
        *(float2*)(lg0 + (gid + 8) * LG_PAD + n * 8 + 2 * tig) = make_float2(ac0[n][2], ac0[n][3]);
        *(float2*)(lg1 + gid * LG_PAD + n * 8 + 2 * tig)       = make_float2(ac1[n][0], ac1[n][1]);
        *(float2*)(lg1 + (gid + 8) * LG_PAD + n * 8 + 2 * tig) = make_float2(ac1[n][2], ac1[n][3]);
    }
}

__device__ __forceinline__ float att_pool_reg(const float* __restrict__ lg_s,
                                              const float* __restrict__ vals, int ch)
{
    float l[KNN];
    float m = -1e30f;
    #pragma unroll
    for (int k = 0; k < KNN; k++) { l[k] = lg_s[k * LG_PAD + ch]; m = fmaxf(m, l[k]); }
    float s = 0.f, a = 0.f;
    #pragma unroll
    for (int k = 0; k < KNN; k++) {
        float e = __expf(l[k] - m);
        s += e;
        a += e * vals[k];
    }
    return __fdividef(a, s);
}

__device__ __forceinline__ float att_pool_h(const float* __restrict__ lg_s,
                                            const __half2* __restrict__ fs_h, int lane)
{
    const int ch = 32 + lane;
    float vals[KNN];
    #pragma unroll
    for (int k = 0; k < KNN; k++) {
        __half2 h = fs_h[k * FS_H2 + 16 + (lane >> 1)];
        vals[k] = (lane & 1) ? __high2float(h) : __low2float(h);
    }
    return att_pool_reg(lg_s, vals, ch);
}

// ---------------------------------------------------------------------------
// Kernel 1: f_pc = ReLU((feature @ w_mlp1) * s + b)
// ---------------------------------------------------------------------------
__global__ __launch_bounds__(256) void kern_mlp1(
    const float* __restrict__ feature,
    const float* __restrict__ w, const float* __restrict__ s, const float* __restrict__ b)
{
    __shared__ float ws[1024];
    __shared__ float sv[32], bv[32];
    __shared__ float xs[8][32];

    for (int i = threadIdx.x; i < 1024; i += blockDim.x) ws[i] = w[i];
    if (threadIdx.x < 32) { sv[threadIdx.x] = s[threadIdx.x]; bv[threadIdx.x] = b[threadIdx.x]; }
    __syncthreads();

    const int lane = threadIdx.x & 31;
    const int warp = threadIdx.x >> 5;
    const int nwarps = (gridDim.x * blockDim.x) >> 5;
    int gw = (blockIdx.x * blockDim.x + threadIdx.x) >> 5;

    for (int p = gw; p < P_TOTAL; p += nwarps) {
        xs[warp][lane] = feature[(size_t)p * 32 + lane];
        __syncwarp();
        float acc = 0.f;
        #pragma unroll
        for (int j4 = 0; j4 < 32; j4 += 4) {
            float4 f = *(const float4*)(&xs[warp][j4]);
            acc += f.x * ws[(j4 + 0) * 32 + lane];
            acc += f.y * ws[(j4 + 1) * 32 + lane];
            acc += f.z * ws[(j4 + 2) * 32 + lane];
            acc += f.w * ws[(j4 + 3) * 32 + lane];
        }
        g_f_pc[(size_t)p * 32 + lane] = fmaxf(acc * sv[lane] + bv[lane], 0.f);
        __syncwarp();
    }
}

// ---------------------------------------------------------------------------
// Kernel 2: TWO points per warp. rel_pos(lane halves) + lfa1(f16, shared B) +
//           gather + logits(f16, shared B) + pool + f_agg(shared wam) +
//           lfa2(f16, shared B) -> g_fx2
// per warp floats: fs0 576 + fs1 576 + lg0 1056 + lg1 1056 + agg 128 = 3392
// ---------------------------------------------------------------------------
#define K2_WARP_FLOATS 3392
#define K2_BASE_FLOATS 5216
#define K2_WARPS 12
#define K2_SMEM_BYTES ((K2_BASE_FLOATS + K2_WARPS * K2_WARP_FLOATS) * 4)

__global__ __launch_bounds__(384) void kern_att1(
    const float* __restrict__ xyz, const int* __restrict__ neigh,
    const float* __restrict__ wlfa1, const float* __restrict__ slfa1, const float* __restrict__ blfa1,
    const float* __restrict__ wfc1,
    const float* __restrict__ wam1, const float* __restrict__ sam1, const float* __restrict__ bam1,
    const float* __restrict__ wlfa2, const float* __restrict__ slfa2, const float* __restrict__ blfa2)
{
    extern __shared__ float sm[];
    uint2*  s_wfcp = (uint2*)sm;              // [16][68] uint2 = 2176 floats
    float2* s_wamp = (float2*)(sm + 2176);    // [32][32] float2 = 2048 floats
    uint2*  s_wl1p = (uint2*)(sm + 4224);     // [4][36] uint2 = 288 floats (f16)
    uint2*  s_wl2p = (uint2*)(sm + 4512);     // [8][36] uint2 = 576 floats
    float*  s_vec  = sm + 5088;               // 128: blfa1, blfa2, bam1
    float*  s_wrp  = sm + K2_BASE_FLOATS;

    for (int i = threadIdx.x; i < 1024; i += blockDim.x) {
        int r = i >> 6, c = i & 63;
        int q = r >> 2, t = r & 3;
        int k0 = 16 * q + 2 * t;
        s_wfcp[r * WH64 + c] = make_uint2(
            f2_to_u(wfc1[k0 * 64 + c], wfc1[(k0 + 1) * 64 + c]),
            f2_to_u(wfc1[(k0 + 8) * 64 + c], wfc1[(k0 + 9) * 64 + c]));
    }
    for (int i = threadIdx.x; i < 1024; i += blockDim.x) {
        int r = i >> 5, c = i & 31;
        s_wamp[r * 32 + c] = make_float2(wam1[(2 * r) * 32 + c] * sam1[c],
                                         wam1[(2 * r + 1) * 32 + c] * sam1[c]);
    }
    for (int i = threadIdx.x; i < 128; i += blockDim.x) {
        int t = i >> 5, c = i & 31;
        int k0 = 2 * t, k1 = 2 * t + 8;
        float w00 = wlfa1[k0 * 32 + c] * slfa1[c];          // k0 in {0,2,4,6} < 10
        float w01 = wlfa1[(k0 + 1) * 32 + c] * slfa1[c];    // {1,3,5,7} < 10
        float w10 = (k1 < 10) ? wlfa1[k1 * 32 + c] * slfa1[c] : 0.f;
        float w11 = (k1 + 1 < 10) ? wlfa1[(k1 + 1) * 32 + c] * slfa1[c] : 0.f;
        s_wl1p[t * WH32 + c] = make_uint2(f2_to_u(w00, w01), f2_to_u(w10, w11));
    }
    for (int i = threadIdx.x; i < 256; i += blockDim.x) {
        int r = i >> 5, c = i & 31;
        int q = r >> 2, t = r & 3;
        int k0 = 16 * q + 2 * t;
        s_wl2p[r * WH32 + c] = make_uint2(
            f2_to_u(wlfa2[k0 * 32 + c] * slfa2[c], wlfa2[(k0 + 1) * 32 + c] * slfa2[c]),
            f2_to_u(wlfa2[(k0 + 8) * 32 + c] * slfa2[c], wlfa2[(k0 + 9) * 32 + c] * slfa2[c]));
    }
    if (threadIdx.x < 32) {
        int l = threadIdx.x;
        s_vec[l]      = blfa1[l];
        s_vec[32 + l] = blfa2[l];
        s_vec[64 + l] = bam1[l];
    }
    __syncthreads();

    const int lane = threadIdx.x & 31;
    const int warp = threadIdx.x >> 5;
    const int gid = lane >> 2, tig = lane & 3;
    float* wbase = s_wrp + warp * K2_WARP_FLOATS;
    __half2*  fs0_h = (__half2*)wbase;            // [16][36] half2
    __half2*  fs1_h = (__half2*)(wbase + 576);
    unsigned* fsw0  = (unsigned*)fs0_h;
    unsigned* fsw1  = (unsigned*)fs1_h;
    float* lg0  = wbase + 1152;                   // [16][66]
    float* lg1  = wbase + 2208;
    __half2* rp0 = (__half2*)lg0;                 // [16][12] half2, aliases lg
    __half2* rp1 = (__half2*)lg1;
    unsigned* rp0w = (unsigned*)rp0;
    unsigned* rp1w = (unsigned*)rp1;
    float* agg_s = wbase + 3264;                  // [128]

    const int nwarps = (gridDim.x * blockDim.x) >> 5;
    int gw = (blockIdx.x * blockDim.x + threadIdx.x) >> 5;

    for (int pp = gw; pp < P_TOTAL / 2; pp += nwarps) {
        const int p0 = 2 * pp, p1 = p0 + 1;
        const int b = p0 / NPTS;
        const size_t bbase = (size_t)b * NPTS;

        // one coalesced load covers both points' neighbor lists
        int idx = neigh[(size_t)p0 * KNN + lane];

        float gv0[KNN], gv1[KNN];
        #pragma unroll
        for (int k = 0; k < KNN; k++) {
            int nb = __shfl_sync(0xffffffffu, idx, k);
            gv0[k] = g_f_pc[(bbase + (size_t)nb) * 32 + lane];
        }
        #pragma unroll
        for (int k = 0; k < KNN; k++) {
            int nb = __shfl_sync(0xffffffffu, idx, 16 + k);
            gv1[k] = g_f_pc[(bbase + (size_t)nb) * 32 + lane];
        }

        // relpos: lanes 0-15 -> p0 rows, lanes 16-31 -> p1 rows (fp16 tile)
        {
            const int myp = (lane < 16) ? p0 : p1;
            const int krow = lane & 15;
            float cx = xyz[(size_t)myp * 3 + 0];
            float cy = xyz[(size_t)myp * 3 + 1];
            float cz = xyz[(size_t)myp * 3 + 2];
            size_t nb = bbase + (size_t)idx;
            float nx = xyz[nb * 3 + 0], ny = xyz[nb * 3 + 1], nz = xyz[nb * 3 + 2];
            float rx = cx - nx, ry = cy - ny, rz = cz - nz;
            float d = sqrtf(rx * rx + ry * ry + rz * rz);
            __half2* rp = (lane < 16) ? rp0 : rp1;
            __half2 z = __floats2half2_rn(0.f, 0.f);
            rp[krow * RP2 + 0] = __floats2half2_rn(d, rx);
            rp[krow * RP2 + 1] = __floats2half2_rn(ry, rz);
            rp[krow * RP2 + 2] = __floats2half2_rn(cx, cy);
            rp[krow * RP2 + 3] = __floats2half2_rn(cz, nx);
            rp[krow * RP2 + 4] = __floats2half2_rn(ny, nz);
            rp[krow * RP2 + 5] = z;
            rp[krow * RP2 + 6] = z;
            rp[krow * RP2 + 7] = z;
        }
        __syncwarp();

        // ---- lfa1 via f16 mma (K=16 covers all 10 rows), B shared
        {
            unsigned a00 = rp0w[gid * RP2 + tig];
            unsigned a01 = rp0w[(gid + 8) * RP2 + tig];
            unsigned a02 = rp0w[gid * RP2 + tig + 4];
            unsigned a03 = rp0w[(gid + 8) * RP2 + tig + 4];
            unsigned a10 = rp1w[gid * RP2 + tig];
            unsigned a11 = rp1w[(gid + 8) * RP2 + tig];
            unsigned a12 = rp1w[gid * RP2 + tig + 4];
            unsigned a13 = rp1w[(gid + 8) * RP2 + tig + 4];
            float ac0[4][4], ac1[4][4];
            #pragma unroll
            for (int n = 0; n < 4; n++)
                #pragma unroll
                for (int j = 0; j < 4; j++) { ac0[n][j] = 0.f; ac1[n][j] = 0.f; }
            const uint2* br = s_wl1p + tig * WH32 + gid;
            #pragma unroll
            for (int n = 0; n < 4; n++) {
                uint2 bb = br[8 * n];
                mma_f16(ac0[n], a00, a01, a02, a03, bb.x, bb.y);
                mma_f16(ac1[n], a10, a11, a12, a13, bb.x, bb.y);
            }
            #pragma unroll
            for (int n = 0; n < 4; n++) {
                int c0 = n * 8 + 2 * tig;
                float b0 = s_vec[c0], b1 = s_vec[c0 + 1];
                fs0_h[gid * FS_H2 + 16 + n * 4 + tig] =
                    __floats2half2_rn(fmaxf(ac0[n][0] + b0, 0.f), fmaxf(ac0[n][1] + b1, 0.f));
                fs0_h[(gid + 8) * FS_H2 + 16 + n * 4 + tig] =
                    __floats2half2_rn(fmaxf(ac0[n][2] + b0, 0.f), fmaxf(ac0[n][3] + b1, 0.f));
                fs1_h[gid * FS_H2 + 16 + n * 4 + tig] =
                    __floats2half2_rn(fmaxf(ac1[n][0] + b0, 0.f), fmaxf(ac1[n][1] + b1, 0.f));
                fs1_h[(gid + 8) * FS_H2 + 16 + n * 4 + tig] =
                    __floats2half2_rn(fmaxf(ac1[n][2] + b0, 0.f), fmaxf(ac1[n][3] + b1, 0.f));
            }
        }

        // gathered f_pc -> fs half2 cols 0..15 (pack pairs via shfl)
        #pragma unroll
        for (int k = 0; k < KNN; k++) {
            float v0 = gv0[k];
            float v1 = __shfl_xor_sync(0xffffffffu, v0, 1);
            if (!(lane & 1))
                fs0_h[k * FS_H2 + (lane >> 1)] = __floats2half2_rn(v0, v1);
        }
        #pragma unroll
        for (int k = 0; k < KNN; k++) {
            float v0 = gv1[k];
            float v1 = __shfl_xor_sync(0xffffffffu, v0, 1);
            if (!(lane & 1))
                fs1_h[k * FS_H2 + (lane >> 1)] = __floats2half2_rn(v0, v1);
        }
        __syncwarp();

        // ---- logits (shared B) + softmax pools (lg overwrites rp -- dead)
        logits_f16_x2(fsw0, fsw1, lg0, lg1, s_wfcp, lane);
        __syncwarp();
        agg_s[lane]       = att_pool_reg(lg0, gv0, lane);
        agg_s[32 + lane]  = att_pool_h(lg0, fs0_h, lane);
        agg_s[64 + lane]  = att_pool_reg(lg1, gv1, lane);
        agg_s[96 + lane]  = att_pool_h(lg1, fs1_h, lane);
        __syncwarp();

        // ---- f_agg for both points, wam read once
        {
            float acc0 = 0.f, acc1 = 0.f;
            #pragma unroll
            for (int d2 = 0; d2 < 32; d2 += 2) {
                float4 a0 = *(const float4*)(agg_s + 2 * d2);
                float4 a1 = *(const float4*)(agg_s + 64 + 2 * d2);
                float2 w0 = s_wamp[d2 * 32 + lane];
                float2 w1 = s_wamp[(d2 + 1) * 32 + lane];
                acc0 += a0.x * w0.x + a0.y * w0.y + a0.z * w1.x + a0.w * w1.y;
                acc1 += a1.x * w0.x + a1.y * w0.y + a1.z * w1.x + a1.w * w1.y;
            }
            float bb = s_vec[64 + lane];
            g_f_agg[(size_t)p0 * 32 + lane] = fmaxf(acc0 + bb, 0.f);
            g_f_agg[(size_t)p1 * 32 + lane] = fmaxf(acc1 + bb, 0.f);
        }

        // ---- lfa2 via f16 mma, B shared
        {
            float ac0[4][4], ac1[4][4];
            #pragma unroll
            for (int n = 0; n < 4; n++)
                #pragma unroll
                for (int j = 0; j < 4; j++) { ac0[n][j] = 0.f; ac1[n][j] = 0.f; }
            #pragma unroll
            for (int q = 0; q < 2; q++) {
                unsigned a00 = fsw0[gid * FS_H2 + 16 + q * 8 + tig];
                unsigned a01 = fsw0[(gid + 8) * FS_H2 + 16 + q * 8 + tig];
                unsigned a02 = fsw0[gid * FS_H2 + 16 + q * 8 + tig + 4];
                unsigned a03 = fsw0[(gid + 8) * FS_H2 + 16 + q * 8 + tig + 4];
                unsigned a10 = fsw1[gid * FS_H2 + 16 + q * 8 + tig];
                unsigned a11 = fsw1[(gid + 8) * FS_H2 + 16 + q * 8 + tig];
                unsigned a12 = fsw1[gid * FS_H2 + 16 + q * 8 + tig + 4];
                unsigned a13 = fsw1[(gid + 8) * FS_H2 + 16 + q * 8 + tig + 4];
                const uint2* br = s_wl2p + (q * 4 + tig) * WH32 + gid;
                #pragma unroll
                for (int n = 0; n < 4; n++) {
                    uint2 bb = br[8 * n];
                    mma_f16(ac0[n], a00, a01, a02, a03, bb.x, bb.y);
                    mma_f16(ac1[n], a10, a11, a12, a13, bb.x, bb.y);
                }
            }
            #pragma unroll
            for (int n = 0; n < 4; n++) {
                int c0 = n * 8 + 2 * tig;
                float b0 = s_vec[32 + c0], b1 = s_vec[32 + c0 + 1];
                g_fx2[((size_t)p0 * KNN + gid) * 16 + (c0 >> 1)] =
                    __floats2half2_rn(fmaxf(ac0[n][0] + b0, 0.f), fmaxf(ac0[n][1] + b1, 0.f));
                g_fx2[((size_t)p0 * KNN + gid + 8) * 16 + (c0 >> 1)] =
                    __floats2half2_rn(fmaxf(ac0[n][2] + b0, 0.f), fmaxf(ac0[n][3] + b1, 0.f));
                g_fx2[((size_t)p1 * KNN + gid) * 16 + (c0 >> 1)] =
                    __floats2half2_rn(fmaxf(ac1[n][0] + b0, 0.f), fmaxf(ac1[n][1] + b1, 0.f));
                g_fx2[((size_t)p1 * KNN + gid + 8) * 16 + (c0 >> 1)] =
                    __floats2half2_rn(fmaxf(ac1[n][2] + b0, 0.f), fmaxf(ac1[n][3] + b1, 0.f));
            }
        }
        __syncwarp();
    }
}

// ---------------------------------------------------------------------------
// Kernel 3: TWO points per warp: gather(f_agg) + fx2 + logits(shared B) +
//           pools -> g_agg2
// per warp floats: fs0 576 + fs1 576 + lg0 1056 + lg1 1056 = 3264
// ---------------------------------------------------------------------------
#define K3_WARP_FLOATS 3264
#define K3_BASE_FLOATS 2176
#define K3_WARPS 14
#define K3_SMEM_BYTES ((K3_BASE_FLOATS + K3_WARPS * K3_WARP_FLOATS) * 4)

__global__ __launch_bounds__(448) void kern_att2(
    const int* __restrict__ neigh,
    const float* __restrict__ wfc2)
{
    extern __shared__ float sm[];
    uint2* s_wfcp = (uint2*)sm;               // [16][68] uint2
    float* s_wrp  = sm + K3_BASE_FLOATS;

    for (int i = threadIdx.x; i < 1024; i += blockDim.x) {
        int r = i >> 6, c = i & 63;
        int q = r >> 2, t = r & 3;
        int k0 = 16 * q + 2 * t;
        s_wfcp[r * WH64 + c] = make_uint2(
            f2_to_u(wfc2[k0 * 64 + c], wfc2[(k0 + 1) * 64 + c]),
            f2_to_u(wfc2[(k0 + 8) * 64 + c], wfc2[(k0 + 9) * 64 + c]));
    }
    __syncthreads();

    const int lane = threadIdx.x & 31;
    const int warp = threadIdx.x >> 5;
    float* wbase = s_wrp + warp * K3_WARP_FLOATS;
    __half2*  fs0_h = (__half2*)wbase;
    __half2*  fs1_h = (__half2*)(wbase + 576);
    unsigned* fsw0  = (unsigned*)fs0_h;
    unsigned* fsw1  = (unsigned*)fs1_h;
    float* lg0 = wbase + 1152;
    float* lg1 = wbase + 2208;

    const int kk = lane >> 4;
    const int jj = lane & 15;

    const int nwarps = (gridDim.x * blockDim.x) >> 5;
    int gw = (blockIdx.x * blockDim.x + threadIdx.x) >> 5;

    for (int pp = gw; pp < P_TOTAL / 2; pp += nwarps) {
        const int p0 = 2 * pp, p1 = p0 + 1;
        const int b = p0 / NPTS;
        const size_t bbase = (size_t)b * NPTS;

        int idx = neigh[(size_t)p0 * KNN + lane];

        float gv0[KNN], gv1[KNN];
        #pragma unroll
        for (int k = 0; k < KNN; k++) {
            int nb = __shfl_sync(0xffffffffu, idx, k);
            gv0[k] = g_f_agg[(bbase + (size_t)nb) * 32 + lane];
        }
        #pragma unroll
        for (int k = 0; k < KNN; k++) {
            int nb = __shfl_sync(0xffffffffu, idx, 16 + k);
            gv1[k] = g_f_agg[(bbase + (size_t)nb) * 32 + lane];
        }
        #pragma unroll
        for (int k = 0; k < KNN; k++) {
            float v0 = gv0[k];
            float v1 = __shfl_xor_sync(0xffffffffu, v0, 1);
            if (!(lane & 1))
                fs0_h[k * FS_H2 + (lane >> 1)] = __floats2half2_rn(v0, v1);
        }
        #pragma unroll
        for (int k = 0; k < KNN; k++) {
            float v0 = gv1[k];
            float v1 = __shfl_xor_sync(0xffffffffu, v0, 1);
            if (!(lane & 1))
                fs1_h[k * FS_H2 + (lane >> 1)] = __floats2half2_rn(v0, v1);
        }
        const unsigned* src0 = (const unsigned*)(g_fx2 + (size_t)p0 * KNN * 16);
        const unsigned* src1 = (const unsigned*)(g_fx2 + (size_t)p1 * KNN * 16);
        #pragma unroll
        for (int k = 0; k < KNN; k += 2) {
            fsw0[(k + kk) * FS_H2 + 16 + jj] = src0[(k + kk) * 16 + jj];
            fsw1[(k + kk) * FS_H2 + 16 + jj] = src1[(k + kk) * 16 + jj];
        }
        __syncwarp();

        logits_f16_x2(fsw0, fsw1, lg0, lg1, s_wfcp, lane);
        __syncwarp();

        g_agg2[(size_t)p0 * 64 + lane]      = att_pool_reg(lg0, gv0, lane);
        g_agg2[(size_t)p0 * 64 + 32 + lane] = att_pool_h(lg0, fs0_h, lane);
        g_agg2[(size_t)p1 * 64 + lane]      = att_pool_reg(lg1, gv1, lane);
        g_agg2[(size_t)p1 * 64 + 32 + lane] = att_pool_h(lg1, fs1_h, lane);
        __syncwarp();
    }
}

// ---------------------------------------------------------------------------
// Kernel 4: 16-point tiles: pc2 = relu(agg2@w1+b1) into combined [pc2;feat]
//           K=96 A tile; out = leaky(A @ w23 + b2).  3xTF32 packed float4 B.
// ---------------------------------------------------------------------------
#define OUT_WARPS 12
#define OUT_BASE_FLOATS 33600  // w1p 8448 + w23p 24960 + b1 64 + b2 128
#define OUT_WARP_FLOATS 1600   // A [16][100]
#define OUT_SMEM_BYTES ((OUT_BASE_FLOATS + OUT_WARPS * OUT_WARP_FLOATS) * 4)

__global__ __launch_bounds__(384) void kern_out(
    const float* __restrict__ feature,
    const float* __restrict__ wam2, const float* __restrict__ sam2, const float* __restrict__ bam2,
    const float* __restrict__ wmlp2, const float* __restrict__ smlp2, const float* __restrict__ bmlp2,
    const float* __restrict__ wsc, const float* __restrict__ ssc, const float* __restrict__ bsc,
    float* __restrict__ out)
{
    extern __shared__ float sm[];
    float4* w1p  = (float4*)sm;              // [32][66] float4 = 8448 floats
    float4* w23p = (float4*)(sm + 8448);     // [48][130] float4 = 24960 floats
    float*  b1   = sm + 33408;               // [64]
    float*  b2   = sm + 33472;               // [128]
    float*  wrp  = sm + OUT_BASE_FLOATS;

    for (int i = threadIdx.x; i < 2048; i += blockDim.x) {
        int r = i >> 6, c = i & 63;
        int k0 = (r >> 2) * 8 + (r & 3), k1 = k0 + 4;
        float v0 = wam2[k0 * 64 + c] * sam2[c];
        float v1 = wam2[k1 * 64 + c] * sam2[c];
        float h0 = to_tf32(v0), h1 = to_tf32(v1);
        w1p[r * P4_64 + c] = make_float4(h0, h1, to_tf32(v0 - h0), to_tf32(v1 - h1));
    }
    for (int i = threadIdx.x; i < 6144; i += blockDim.x) {
        int r = i >> 7, c = i & 127;
        int k0 = (r >> 2) * 8 + (r & 3), k1 = k0 + 4;
        float v0 = (k0 < 64) ? wmlp2[k0 * 128 + c] * smlp2[c] : wsc[(k0 - 64) * 128 + c] * ssc[c];
        float v1 = (k1 < 64) ? wmlp2[k1 * 128 + c] * smlp2[c] : wsc[(k1 - 64) * 128 + c] * ssc[c];
        float h0 = to_tf32(v0), h1 = to_tf32(v1);
        w23p[r * P4_128 + c] = make_float4(h0, h1, to_tf32(v0 - h0), to_tf32(v1 - h1));
    }
    if (threadIdx.x < 64)  b1[threadIdx.x] = bam2[threadIdx.x];
    if (threadIdx.x < 128) b2[threadIdx.x] = bmlp2[threadIdx.x] + bsc[threadIdx.x];
    __syncthreads();

    const int lane = threadIdx.x & 31;
    const int warp = threadIdx.x >> 5;
    const int gid = lane >> 2, tig = lane & 3;
    float* A1 = wrp + warp * OUT_WARP_FLOATS;  // [16][100]

    const int nwarps = (gridDim.x * blockDim.x) >> 5;
    int gw = (blockIdx.x * blockDim.x + threadIdx.x) >> 5;
    const int ntiles = P_TOTAL / 16;

    for (int t = gw; t < ntiles; t += nwarps) {
        const int p0 = t * 16;

        #pragma unroll
        for (int r = 0; r < 16; r++) {
            A1[r * OA_PAD + lane]      = g_agg2[(size_t)(p0 + r) * 64 + lane];
            A1[r * OA_PAD + 32 + lane] = g_agg2[(size_t)(p0 + r) * 64 + 32 + lane];
            A1[r * OA_PAD + 64 + lane] = feature[(size_t)(p0 + r) * 32 + lane];
        }
        __syncwarp();

        // GEMM1: pc2 = relu(agg @ w1 + b1), written back into A cols 0..63
        {
            float acc[8][4];
            #pragma unroll
            for (int n = 0; n < 8; n++) { acc[n][0]=0.f; acc[n][1]=0.f; acc[n][2]=0.f; acc[n][3]=0.f; }
            #pragma unroll
            for (int q = 0; q < 8; q++) {
                unsigned ah0, al0, ah1, al1, ah2, al2, ah3, al3;
                tf32_split(A1[gid * OA_PAD + q * 8 + tig],           ah0, al0);
                tf32_split(A1[(gid + 8) * OA_PAD + q * 8 + tig],     ah1, al1);
                tf32_split(A1[gid * OA_PAD + q * 8 + tig + 4],       ah2, al2);
                tf32_split(A1[(gid + 8) * OA_PAD + q * 8 + tig + 4], ah3, al3);
                const float4* br = w1p + (q * 4 + tig) * P4_64 + gid;
                #pragma unroll
                for (int n = 0; n < 8; n++)
                    mma3_pk(acc[n], br[8 * n], ah0, ah1, ah2, ah3, al0, al1, al2, al3);
            }
            __syncwarp();
            #pragma unroll
            for (int n = 0; n < 8; n++) {
                int c0 = n * 8 + 2 * tig;
                float bb0 = b1[c0], bb1 = b1[c0 + 1];
                *(float2*)(A1 + gid * OA_PAD + c0) =
                    make_float2(fmaxf(acc[n][0] + bb0, 0.f), fmaxf(acc[n][1] + bb1, 0.f));
                *(float2*)(A1 + (gid + 8) * OA_PAD + c0) =
                    make_float2(fmaxf(acc[n][2] + bb0, 0.f), fmaxf(acc[n][3] + bb1, 0.f));
            }
        }
        __syncwarp();

        // GEMM2: out = leaky(A[16][96] @ w23 + b2), n in two halves of 64
        #pragma unroll
        for (int h = 0; h < 2; h++) {
            float acc[8][4];
            #pragma unroll
            for (int n = 0; n < 8; n++) { acc[n][0]=0.f; acc[n][1]=0.f; acc[n][2]=0.f; acc[n][3]=0.f; }
            #pragma unroll
            for (int q = 0; q < 12; q++) {
                unsigned ah0, al0, ah1, al1, ah2, al2, ah3, al3;
                tf32_split(A1[gid * OA_PAD + q * 8 + tig],           ah0, al0);
                tf32_split(A1[(gid + 8) * OA_PAD + q * 8 + tig],     ah1, al1);
                tf32_split(A1[gid * OA_PAD + q * 8 + tig + 4],       ah2, al2);
                tf32_split(A1[(gid + 8) * OA_PAD + q * 8 + tig + 4], ah3, al3);
                const float4* br = w23p + (q * 4 + tig) * P4_128 + h * 64 + gid;
                #pragma unroll
                for (int n = 0; n < 8; n++)
                    mma3_pk(acc[n], br[8 * n], ah0, ah1, ah2, ah3, al0, al1, al2, al3);
            }
            #pragma unroll
            for (int n = 0; n < 8; n++) {
                int c0 = h * 64 + n * 8 + 2 * tig;
                float bb0 = b2[c0], bb1 = b2[c0 + 1];
                float v0 = acc[n][0] + bb0; v0 = (v0 < 0.f) ? 0.2f * v0 : v0;
                float v1 = acc[n][1] + bb1; v1 = (v1 < 0.f) ? 0.2f * v1 : v1;
                float v2 = acc[n][2] + bb0; v2 = (v2 < 0.f) ? 0.2f * v2 : v2;
                float v3 = acc[n][3] + bb1; v3 = (v3 < 0.f) ? 0.2f * v3 : v3;
                *(float2*)(&out[(size_t)(p0 + gid) * 128 + c0])     = make_float2(v0, v1);
                *(float2*)(&out[(size_t)(p0 + gid + 8) * 128 + c0]) = make_float2(v2, v3);
            }
        }
        __syncwarp();
    }
}

// ---------------------------------------------------------------------------
extern "C" void kernel_launch(void* const* d_in, const int* in_sizes, int n_in,
                              void* d_out, int out_size)
{
    const float* feature = (const float*)d_in[0];
    const float* xyz     = (const float*)d_in[1];
    const int*   neigh   = (const int*)  d_in[2];
    const float* w_mlp1  = (const float*)d_in[3];
    const float* s_mlp1  = (const float*)d_in[4];
    const float* b_mlp1  = (const float*)d_in[5];
    const float* w_lfa1  = (const float*)d_in[6];
    const float* s_lfa1  = (const float*)d_in[7];
    const float* b_lfa1  = (const float*)d_in[8];
    const float* w_fc1   = (const float*)d_in[9];
    const float* w_am1   = (const float*)d_in[10];
    const float* s_am1   = (const float*)d_in[11];
    const float* b_am1   = (const float*)d_in[12];
    const float* w_lfa2  = (const float*)d_in[13];
    const float* s_lfa2  = (const float*)d_in[14];
    const float* b_lfa2  = (const float*)d_in[15];
    const float* w_fc2   = (const float*)d_in[16];
    const float* w_am2   = (const float*)d_in[17];
    const float* s_am2   = (const float*)d_in[18];
    const float* b_am2   = (const float*)d_in[19];
    const float* w_mlp2  = (const float*)d_in[20];
    const float* s_mlp2  = (const float*)d_in[21];
    const float* b_mlp2  = (const float*)d_in[22];
    const float* w_sc    = (const float*)d_in[23];
    const float* s_sc    = (const float*)d_in[24];
    const float* b_sc    = (const float*)d_in[25];
    float* out = (float*)d_out;

    cudaFuncSetAttribute(kern_att1, cudaFuncAttributeMaxDynamicSharedMemorySize, K2_SMEM_BYTES);
    cudaFuncSetAttribute(kern_att2, cudaFuncAttributeMaxDynamicSharedMemorySize, K3_SMEM_BYTES);
    cudaFuncSetAttribute(kern_out,  cudaFuncAttributeMaxDynamicSharedMemorySize, OUT_SMEM_BYTES);

    kern_mlp1<<<2048, 256>>>(feature, w_mlp1, s_mlp1, b_mlp1);

    kern_att1<<<148, 384, K2_SMEM_BYTES>>>(
        xyz, neigh,
        w_lfa1, s_lfa1, b_lfa1,
        w_fc1,
        w_am1, s_am1, b_am1,
        w_lfa2, s_lfa2, b_lfa2);

    kern_att2<<<148, 448, K3_SMEM_BYTES>>>(neigh, w_fc2);

    kern_out<<<148, 384, OUT_SMEM_BYTES>>>(
        feature,
        w_am2, s_am2, b_am2,
        w_mlp2, s_mlp2, b_mlp2,
        w_sc, s_sc, b_sc,
        out);
}